// round 10
// baseline (speedup 1.0000x reference)
#include <cuda_runtime.h>
#include <cuda_bf16.h>
#include <cstdint>

// Problem constants
#define NB 4
#define TT 1500
#define TP 1536            // padded seq len (24 tiles of 64)
#define EE 1280
#define NH 20
#define DH 64
#define MR (NB*TT)         // 6000
#define QKSCALE 0.125f

// GEMM tiling (R5/R8-proven): block 128x128, k-chunk 16, 8 warps (2x4), warp tile 64x32
#define BK 16
#define NCH (EE/BK)         // 80
#define RS 48
#define TILE_SZ (128*RS)    // 6144
#define STAGE_SZ (4*TILE_SZ)// 24576
#define GSM (2*STAGE_SZ)    // 49152

// Attention smem: 2 stages x 4 tiles (KH,KL,VH,VL) of 64x64 bf16, 144B stride
#define ATS 144
#define ATILE (64*ATS)      // 9216
#define AST   (4*ATILE)     // 36864 per stage
#define AKH 0
#define AKL ATILE
#define AVH (2*ATILE)
#define AVL (3*ATILE)
#define ASMEM (2*AST)       // 73728

// Scratch: q/k/v pre-split bf16 (padded T); ctx fp32
static __device__ __align__(16) __nv_bfloat16 g_qh[(size_t)NB*NH*TP*DH], g_ql[(size_t)NB*NH*TP*DH];
static __device__ __align__(16) __nv_bfloat16 g_kh[(size_t)NB*NH*TP*DH], g_kl[(size_t)NB*NH*TP*DH];
static __device__ __align__(16) __nv_bfloat16 g_vh[(size_t)NB*NH*TP*DH], g_vl[(size_t)NB*NH*TP*DH];
static __device__ float g_ctx[(size_t)MR*EE];

// ---------------- helpers ----------------
__device__ __forceinline__ uint32_t smem_u32(const void* p){
    uint32_t a;
    asm("{ .reg .u64 t; cvta.to.shared.u64 t, %1; cvt.u32.u64 %0, t; }" : "=r"(a) : "l"(p));
    return a;
}
__device__ __forceinline__ void ldx4(uint32_t* r, uint32_t addr){
    asm volatile("ldmatrix.sync.aligned.m8n8.x4.shared.b16 {%0,%1,%2,%3}, [%4];"
        : "=r"(r[0]), "=r"(r[1]), "=r"(r[2]), "=r"(r[3]) : "r"(addr));
}
__device__ __forceinline__ void ldx4t(uint32_t* r, uint32_t addr){
    asm volatile("ldmatrix.sync.aligned.m8n8.x4.trans.shared.b16 {%0,%1,%2,%3}, [%4];"
        : "=r"(r[0]), "=r"(r[1]), "=r"(r[2]), "=r"(r[3]) : "r"(addr));
}
__device__ __forceinline__ void mma_bf16(float* d, const uint32_t* a, const uint32_t* b){
    asm volatile(
        "mma.sync.aligned.m16n8k16.row.col.f32.bf16.bf16.f32 "
        "{%0,%1,%2,%3}, {%4,%5,%6,%7}, {%8,%9}, {%0,%1,%2,%3};"
        : "+f"(d[0]), "+f"(d[1]), "+f"(d[2]), "+f"(d[3])
        : "r"(a[0]), "r"(a[1]), "r"(a[2]), "r"(a[3]), "r"(b[0]), "r"(b[1]));
}
__device__ __forceinline__ void cpa16(uint32_t s, const void* g){
    asm volatile("cp.async.ca.shared.global [%0], [%1], 16;" :: "r"(s), "l"(g));
}
#define CP_COMMIT() asm volatile("cp.async.commit_group;" ::: "memory")
#define CP_WAIT(n)  asm volatile("cp.async.wait_group %0;" :: "n"(n) : "memory")

__device__ __forceinline__ void split4(float4 f, uint2& H, uint2& L){
    __nv_bfloat16 hx = __float2bfloat16(f.x);
    __nv_bfloat16 hy = __float2bfloat16(f.y);
    __nv_bfloat16 hz = __float2bfloat16(f.z);
    __nv_bfloat16 hw = __float2bfloat16(f.w);
    float lx = f.x - __bfloat162float(hx);
    float ly = f.y - __bfloat162float(hy);
    float lz = f.z - __bfloat162float(hz);
    float lw = f.w - __bfloat162float(hw);
    union { __nv_bfloat162 h2[2]; uint2 u; } A, B;
    A.h2[0] = __halves2bfloat162(hx, hy);
    A.h2[1] = __halves2bfloat162(hz, hw);
    B.h2[0] = __floats2bfloat162_rn(lx, ly);
    B.h2[1] = __floats2bfloat162_rn(lz, lw);
    H = A.u; L = B.u;
}
__device__ __forceinline__ void splitp(float a, float b, uint32_t& H, uint32_t& L){
    __nv_bfloat16 ha = __float2bfloat16(a);
    __nv_bfloat16 hb = __float2bfloat16(b);
    float la = a - __bfloat162float(ha);
    float lb = b - __bfloat162float(hb);
    union { __nv_bfloat162 h; uint32_t u; } X, Y;
    X.h = __halves2bfloat162(ha, hb);
    Y.h = __floats2bfloat162_rn(la, lb);
    H = X.u; L = Y.u;
}

// ============================================================================
// zero-pad q/k/v rows t in [TT, TP)
// ============================================================================
__global__ void zero_pad_qkv()
{
    int idx = blockIdx.x * blockDim.x + threadIdx.x;
    const int tot = NB*NH*(TP-TT)*DH;
    if (idx >= tot) return;
    int d = idx & 63;
    int r = idx >> 6;
    int t = TT + (r % (TP-TT));
    int head = r / (TP-TT);
    size_t off = ((size_t)head * TP + t) * DH + d;
    __nv_bfloat16 z = __float2bfloat16(0.f);
    g_qh[off]=z; g_ql[off]=z; g_kh[off]=z; g_kl[off]=z; g_vh[off]=z; g_vl[off]=z;
}

// ============================================================================
// GEMM main loop (R8-proven + B via ldx4): acc(128x128) += A @ B^T
// fp32 in, bf16 split in-loop, double-buffered smem. 256 threads, 8 warps.
// ============================================================================
__device__ __forceinline__ void mm_loop(
    const float* __restrict__ Ab, const float* __restrict__ Bb, int row0,
    char* sm, uint32_t smb, float acc[4][4][4])
{
    const int tid  = threadIdx.x;
    const int lane = tid & 31;
    const int wid  = tid >> 5;
    const int warp_m = wid >> 2;
    const int warp_n = wid & 3;

    const int srow  = tid >> 1;
    const int shalf = (tid & 1) * 8;
    const bool aval = (row0 + srow) < MR;
    const float* ap = Ab + (size_t)(row0 + srow) * EE + shalf;
    const float* bp = Bb + (size_t)srow * EE + shalf;

    const uint32_t a_rd = smb + (uint32_t)(warp_m*64 + (lane & 15)) * RS + (lane >> 4) * 16;
    // B read via ldx4 (R7-validated): rows (lane&15), 16B chunk by lane>>4
    const uint32_t b_rd4 = smb + 2*TILE_SZ + (uint32_t)(warp_n*32 + (lane & 15)) * RS + (lane >> 4) * 16;
    const uint32_t st0 = (uint32_t)srow * RS + shalf * 2;

    float4 a0, a1, b0, b1;
    a0 = aval ? *(const float4*)(ap)     : make_float4(0.f,0.f,0.f,0.f);
    a1 = aval ? *(const float4*)(ap + 4) : make_float4(0.f,0.f,0.f,0.f);
    b0 = *(const float4*)(bp);
    b1 = *(const float4*)(bp + 4);

    #pragma unroll 1
    for (int i = 0; i < NCH; i++) {
        char* stg = sm + (i & 1) * STAGE_SZ;
        uint2 H, L;
        split4(a0, H, L);
        *(uint2*)(stg + st0)               = H;
        *(uint2*)(stg + TILE_SZ + st0)     = L;
        split4(a1, H, L);
        *(uint2*)(stg + st0 + 8)           = H;
        *(uint2*)(stg + TILE_SZ + st0 + 8) = L;
        split4(b0, H, L);
        *(uint2*)(stg + 2*TILE_SZ + st0)       = H;
        *(uint2*)(stg + 3*TILE_SZ + st0)       = L;
        split4(b1, H, L);
        *(uint2*)(stg + 2*TILE_SZ + st0 + 8)   = H;
        *(uint2*)(stg + 3*TILE_SZ + st0 + 8)   = L;

        if (i + 1 < NCH) {
            const float* apn = ap + (i+1)*BK;
            const float* bpn = bp + (i+1)*BK;
            a0 = aval ? *(const float4*)(apn)     : make_float4(0.f,0.f,0.f,0.f);
            a1 = aval ? *(const float4*)(apn + 4) : make_float4(0.f,0.f,0.f,0.f);
            b0 = *(const float4*)(bpn);
            b1 = *(const float4*)(bpn + 4);
        }
        __syncthreads();

        const uint32_t soff = (uint32_t)(i & 1) * STAGE_SZ;
        uint32_t bh[4][2], bl[4][2];
        #pragma unroll
        for (int p = 0; p < 2; p++) {
            uint32_t r4[4];
            ldx4(r4, b_rd4 + soff + p*16*RS);
            bh[2*p][0]=r4[0]; bh[2*p][1]=r4[2]; bh[2*p+1][0]=r4[1]; bh[2*p+1][1]=r4[3];
            ldx4(r4, b_rd4 + soff + p*16*RS + TILE_SZ);
            bl[2*p][0]=r4[0]; bl[2*p][1]=r4[2]; bl[2*p+1][0]=r4[1]; bl[2*p+1][1]=r4[3];
        }
        #pragma unroll
        for (int mt = 0; mt < 4; mt++) {
            uint32_t ah[4], al[4];
            ldx4(ah, a_rd + soff + mt*16*RS);
            ldx4(al, a_rd + soff + mt*16*RS + TILE_SZ);
            #pragma unroll
            for (int nt = 0; nt < 4; nt++) {
                mma_bf16(acc[mt][nt], ah, bh[nt]);
                mma_bf16(acc[mt][nt], ah, bl[nt]);
                mma_bf16(acc[mt][nt], al, bh[nt]);
            }
        }
        __syncthreads();
    }
}

// ============================================================================
// QKV GEMM: grid (30, 47). Epilogue writes pre-split bf16 hi/lo q/k/v.
// ============================================================================
__global__ __launch_bounds__(256, 2) void qkv_mm(
    const float* __restrict__ X,
    const float* __restrict__ Wq, const float* __restrict__ bq,
    const float* __restrict__ Wk,
    const float* __restrict__ Wv, const float* __restrict__ bv)
{
    extern __shared__ char sm[];
    uint32_t smb = smem_u32(sm);
    const int tid = threadIdx.x;
    const int lane = tid & 31;
    const int wid = tid >> 5;
    const int warp_m = wid >> 2, warp_n = wid & 3;

    const int which = blockIdx.x / 10;
    const int wcol0 = (blockIdx.x - which*10) * 128;
    const int row0  = blockIdx.y * 128;
    const float* W = (which == 0) ? Wq : (which == 1 ? Wk : Wv);
    const float* bias = (which == 0) ? bq : (which == 2 ? bv : nullptr);
    const float scl = (which == 0) ? QKSCALE : 1.0f;
    __nv_bfloat16* dh = (which == 0) ? g_qh : (which == 1 ? g_kh : g_vh);
    __nv_bfloat16* dl = (which == 0) ? g_ql : (which == 1 ? g_kl : g_vl);

    float acc[4][4][4];
    #pragma unroll
    for (int mt = 0; mt < 4; mt++)
        #pragma unroll
        for (int nt = 0; nt < 4; nt++)
            #pragma unroll
            for (int j = 0; j < 4; j++) acc[mt][nt][j] = 0.f;

    mm_loop(X, W + (size_t)wcol0 * EE, row0, sm, smb, acc);

    const int g = lane >> 2, t4 = lane & 3;
    #pragma unroll
    for (int mt = 0; mt < 4; mt++) {
        #pragma unroll
        for (int nt = 0; nt < 4; nt++) {
            int col = wcol0 + warp_n*32 + nt*8 + 2*t4;
            float2 bb = bias ? *(const float2*)(bias + col) : make_float2(0.f, 0.f);
            int h = col >> 6, d = col & 63;
            int r0w = row0 + warp_m*64 + mt*16 + g;
            if (r0w < MR) {
                int b_ = r0w / TT, t_ = r0w - b_*TT;
                size_t base = ((size_t)(b_*NH + h) * TP + t_) * DH + d;
                uint32_t H, L;
                splitp((acc[mt][nt][0] + bb.x)*scl, (acc[mt][nt][1] + bb.y)*scl, H, L);
                *(uint32_t*)(dh + base) = H;
                *(uint32_t*)(dl + base) = L;
            }
            int r1w = r0w + 8;
            if (r1w < MR) {
                int b_ = r1w / TT, t_ = r1w - b_*TT;
                size_t base = ((size_t)(b_*NH + h) * TP + t_) * DH + d;
                uint32_t H, L;
                splitp((acc[mt][nt][2] + bb.x)*scl, (acc[mt][nt][3] + bb.y)*scl, H, L);
                *(uint32_t*)(dh + base) = H;
                *(uint32_t*)(dl + base) = L;
            }
        }
    }
}

// ============================================================================
// Output projection: out = ctx @ Wo^T + bo. grid (10, 47).
// ============================================================================
__global__ __launch_bounds__(256, 2) void out_mm(
    const float* __restrict__ Wo, const float* __restrict__ bo,
    float* __restrict__ out)
{
    extern __shared__ char sm[];
    uint32_t smb = smem_u32(sm);
    const int tid = threadIdx.x;
    const int lane = tid & 31;
    const int wid = tid >> 5;
    const int warp_m = wid >> 2, warp_n = wid & 3;
    const int col0 = blockIdx.x * 128;
    const int row0 = blockIdx.y * 128;

    float acc[4][4][4];
    #pragma unroll
    for (int mt = 0; mt < 4; mt++)
        #pragma unroll
        for (int nt = 0; nt < 4; nt++)
            #pragma unroll
            for (int j = 0; j < 4; j++) acc[mt][nt][j] = 0.f;

    mm_loop(g_ctx, Wo + (size_t)col0 * EE, row0, sm, smb, acc);

    const int g = lane >> 2, t4 = lane & 3;
    #pragma unroll
    for (int mt = 0; mt < 4; mt++) {
        #pragma unroll
        for (int nt = 0; nt < 4; nt++) {
            int col = col0 + warp_n*32 + nt*8 + 2*t4;
            float2 bb = *(const float2*)(bo + col);
            int r0w = row0 + warp_m*64 + mt*16 + g;
            if (r0w < MR) {
                float2 v = make_float2(acc[mt][nt][0] + bb.x, acc[mt][nt][1] + bb.y);
                *(float2*)(out + (size_t)r0w*EE + col) = v;
            }
            int r1w = r0w + 8;
            if (r1w < MR) {
                float2 v = make_float2(acc[mt][nt][2] + bb.x, acc[mt][nt][3] + bb.y);
                *(float2*)(out + (size_t)r1w*EE + col) = v;
            }
        }
    }
}

// ============================================================================
// Flash attention: pre-split bf16 q/k/v, double-buffered K/V, x4 ldmatrix.
// Grid (24, 80), 128 threads (4 warps, 16 q-rows each). fp32 ctx out.
// ============================================================================
__global__ __launch_bounds__(128) void attn_kernel()
{
    extern __shared__ char sm[];
    uint32_t smb = smem_u32(sm);

    const int tid = threadIdx.x;
    const int lane = tid & 31;
    const int wid = tid >> 5;
    const int g  = lane >> 2;
    const int t4 = lane & 3;

    const int bhidx = blockIdx.y;
    const int b_ = bhidx / NH;
    const int h_ = bhidx - b_ * NH;
    const size_t hb = (size_t)bhidx * TP * DH;
    const int q0 = blockIdx.x * 64;

    // ---- Q staging into stage-0 area (KH/KL tiles), then fragments ----
    #pragma unroll
    for (int j = 0; j < 4; j++) {
        int seg = tid + 128*j;
        int row = seg >> 3;
        int o8  = (seg & 7) * 8;
        size_t go = hb + (size_t)(q0 + row) * DH + o8;
        uint32_t so = (uint32_t)row * ATS + o8*2;
        cpa16(smb + AKH + so, g_qh + go);
        cpa16(smb + AKL + so, g_ql + go);
    }
    CP_COMMIT(); CP_WAIT(0);
    __syncthreads();

    uint32_t qh[4][4], ql[4][4];
    {
        uint32_t qa = smb + (uint32_t)(wid*16 + (lane & 15)) * ATS + (lane >> 4) * 16;
        #pragma unroll
        for (int kc = 0; kc < 4; kc++) {
            ldx4(qh[kc], qa + AKH + kc*32);
            ldx4(ql[kc], qa + AKL + kc*32);
        }
    }
    __syncthreads();   // all warps done reading Q staging before overwrite

    float m0 = -1e30f, m1 = -1e30f, l0 = 0.f, l1 = 0.f;
    float o[8][4];
    #pragma unroll
    for (int nt = 0; nt < 8; nt++)
        #pragma unroll
        for (int j = 0; j < 4; j++) o[nt][j] = 0.f;

    // per-thread cp.async source/dest mapping (16 ops per tile)
    const int crow = tid >> 3;            // 0..15? no: tid(0..127)>>3 = 0..15 — handled with j loop below

    // issue K/V tile 0 into stage 0
    #pragma unroll
    for (int j = 0; j < 4; j++) {
        int seg = tid + 128*j;
        int row = seg >> 3;
        int o8  = (seg & 7) * 8;
        size_t go = hb + (size_t)(0 + row) * DH + o8;
        uint32_t so = (uint32_t)row * ATS + o8*2;
        cpa16(smb + AKH + so, g_kh + go);
        cpa16(smb + AKL + so, g_kl + go);
        cpa16(smb + AVH + so, g_vh + go);
        cpa16(smb + AVL + so, g_vl + go);
    }
    CP_COMMIT();
    (void)crow;

    #pragma unroll 1
    for (int kt = 0; kt < 24; kt++) {
        CP_WAIT(0);
        __syncthreads();   // stage data visible; prior reads of the other stage finished

        // prefetch next tile into the other stage (overlaps compute below)
        if (kt + 1 < 24) {
            const int k1 = (kt + 1) * 64;
            const uint32_t stN = smb + ((kt + 1) & 1) * AST;
            #pragma unroll
            for (int j = 0; j < 4; j++) {
                int seg = tid + 128*j;
                int row = seg >> 3;
                int o8  = (seg & 7) * 8;
                size_t go = hb + (size_t)(k1 + row) * DH + o8;
                uint32_t so = (uint32_t)row * ATS + o8*2;
                cpa16(stN + AKH + so, g_kh + go);
                cpa16(stN + AKL + so, g_kl + go);
                cpa16(stN + AVH + so, g_vh + go);
                cpa16(stN + AVL + so, g_vl + go);
            }
            CP_COMMIT();
        }

        const uint32_t st = smb + (kt & 1) * AST;
        const int k0 = kt * 64;

        // ---- S = Q K^T (3-term split), K via ldx4 ----
        float s[8][4];
        #pragma unroll
        for (int nt = 0; nt < 8; nt++)
            #pragma unroll
            for (int j = 0; j < 4; j++) s[nt][j] = 0.f;

        const uint32_t k_rd4 = st + (uint32_t)(lane & 15) * ATS + (lane >> 4) * 16;
        #pragma unroll
        for (int kc = 0; kc < 4; kc++) {
            #pragma unroll
            for (int nt2 = 0; nt2 < 4; nt2++) {
                uint32_t r4[4], kh2a[2], kh2b[2], kl2a[2], kl2b[2];
                ldx4(r4, k_rd4 + AKH + (uint32_t)nt2*16*ATS + kc*32);
                kh2a[0]=r4[0]; kh2a[1]=r4[2]; kh2b[0]=r4[1]; kh2b[1]=r4[3];
                ldx4(r4, k_rd4 + AKL + (uint32_t)nt2*16*ATS + kc*32);
                kl2a[0]=r4[0]; kl2a[1]=r4[2]; kl2b[0]=r4[1]; kl2b[1]=r4[3];
                mma_bf16(s[2*nt2],   qh[kc], kh2a);
                mma_bf16(s[2*nt2],   qh[kc], kl2a);
                mma_bf16(s[2*nt2],   ql[kc], kh2a);
                mma_bf16(s[2*nt2+1], qh[kc], kh2b);
                mma_bf16(s[2*nt2+1], qh[kc], kl2b);
                mma_bf16(s[2*nt2+1], ql[kc], kh2b);
            }
        }

        // ---- mask invalid key columns (last tile) ----
        if (k0 + 64 > TT) {
            #pragma unroll
            for (int nt = 0; nt < 8; nt++) {
                int col = k0 + nt*8 + 2*t4;
                if (col   >= TT) { s[nt][0] = -1e30f; s[nt][2] = -1e30f; }
                if (col+1 >= TT) { s[nt][1] = -1e30f; s[nt][3] = -1e30f; }
            }
        }

        // ---- online softmax ----
        float mx0 = -1e30f, mx1 = -1e30f;
        #pragma unroll
        for (int nt = 0; nt < 8; nt++) {
            mx0 = fmaxf(mx0, fmaxf(s[nt][0], s[nt][1]));
            mx1 = fmaxf(mx1, fmaxf(s[nt][2], s[nt][3]));
        }
        mx0 = fmaxf(mx0, __shfl_xor_sync(0xffffffffu, mx0, 1));
        mx0 = fmaxf(mx0, __shfl_xor_sync(0xffffffffu, mx0, 2));
        mx1 = fmaxf(mx1, __shfl_xor_sync(0xffffffffu, mx1, 1));
        mx1 = fmaxf(mx1, __shfl_xor_sync(0xffffffffu, mx1, 2));

        float mn0 = fmaxf(m0, mx0), mn1 = fmaxf(m1, mx1);
        float al0 = __expf(m0 - mn0), al1 = __expf(m1 - mn1);
        m0 = mn0; m1 = mn1;

        float sum0 = 0.f, sum1 = 0.f;
        #pragma unroll
        for (int nt = 0; nt < 8; nt++) {
            s[nt][0] = __expf(s[nt][0] - mn0); sum0 += s[nt][0];
            s[nt][1] = __expf(s[nt][1] - mn0); sum0 += s[nt][1];
            s[nt][2] = __expf(s[nt][2] - mn1); sum1 += s[nt][2];
            s[nt][3] = __expf(s[nt][3] - mn1); sum1 += s[nt][3];
        }
        sum0 += __shfl_xor_sync(0xffffffffu, sum0, 1);
        sum0 += __shfl_xor_sync(0xffffffffu, sum0, 2);
        sum1 += __shfl_xor_sync(0xffffffffu, sum1, 1);
        sum1 += __shfl_xor_sync(0xffffffffu, sum1, 2);
        l0 = l0 * al0 + sum0;
        l1 = l1 * al1 + sum1;

        #pragma unroll
        for (int nt = 0; nt < 8; nt++) {
            o[nt][0] *= al0; o[nt][1] *= al0;
            o[nt][2] *= al1; o[nt][3] *= al1;
        }

        // ---- O += P V (P split in registers; V via ldx4 trans) ----
        const uint32_t v_rd4 = st + (uint32_t)(lane & 15) * ATS + (lane >> 4) * 16;
        #pragma unroll
        for (int kc = 0; kc < 4; kc++) {
            uint32_t ah[4], al_[4];
            splitp(s[2*kc][0],   s[2*kc][1],   ah[0], al_[0]);
            splitp(s[2*kc][2],   s[2*kc][3],   ah[1], al_[1]);
            splitp(s[2*kc+1][0], s[2*kc+1][1], ah[2], al_[2]);
            splitp(s[2*kc+1][2], s[2*kc+1][3], ah[3], al_[3]);
            uint32_t vrow = (uint32_t)kc*16*ATS;
            #pragma unroll
            for (int nt2 = 0; nt2 < 4; nt2++) {
                uint32_t r4[4], vh2a[2], vh2b[2], vl2a[2], vl2b[2];
                ldx4t(r4, v_rd4 + AVH + vrow + nt2*32);
                vh2a[0]=r4[0]; vh2a[1]=r4[1]; vh2b[0]=r4[2]; vh2b[1]=r4[3];
                ldx4t(r4, v_rd4 + AVL + vrow + nt2*32);
                vl2a[0]=r4[0]; vl2a[1]=r4[1]; vl2b[0]=r4[2]; vl2b[1]=r4[3];
                mma_bf16(o[2*nt2],   ah,  vh2a);
                mma_bf16(o[2*nt2],   ah,  vl2a);
                mma_bf16(o[2*nt2],   al_, vh2a);
                mma_bf16(o[2*nt2+1], ah,  vh2b);
                mma_bf16(o[2*nt2+1], ah,  vl2b);
                mma_bf16(o[2*nt2+1], al_, vh2b);
            }
        }
    }

    // ---- epilogue: normalize, write fp32 ctx [b*T+t, h*64+d] ----
    float inv0 = 1.0f / l0, inv1 = 1.0f / l1;
    int r0w = q0 + wid*16 + g;
    int r1w = r0w + 8;
    #pragma unroll
    for (int nt = 0; nt < 8; nt++) {
        int d = nt*8 + 2*t4;
        if (r0w < TT) {
            float* dst = g_ctx + ((size_t)(b_ * TT + r0w)) * EE + h_ * DH + d;
            *(float2*)dst = make_float2(o[nt][0]*inv0, o[nt][1]*inv0);
        }
        if (r1w < TT) {
            float* dst = g_ctx + ((size_t)(b_ * TT + r1w)) * EE + h_ * DH + d;
            *(float2*)dst = make_float2(o[nt][2]*inv1, o[nt][3]*inv1);
        }
    }
}

extern "C" void kernel_launch(void* const* d_in, const int* in_sizes, int n_in,
                              void* d_out, int out_size)
{
    const float* X  = (const float*)d_in[0];
    const float* Wq = (const float*)d_in[1];
    const float* bq = (const float*)d_in[2];
    const float* Wk = (const float*)d_in[3];
    const float* Wv = (const float*)d_in[4];
    const float* bv = (const float*)d_in[5];
    const float* Wo = (const float*)d_in[6];
    const float* bo = (const float*)d_in[7];
    float* out = (float*)d_out;

    cudaFuncSetAttribute(qkv_mm, cudaFuncAttributeMaxDynamicSharedMemorySize, GSM);
    cudaFuncSetAttribute(out_mm, cudaFuncAttributeMaxDynamicSharedMemorySize, GSM);
    cudaFuncSetAttribute(attn_kernel, cudaFuncAttributeMaxDynamicSharedMemorySize, ASMEM);

    zero_pad_qkv<<<(NB*NH*(TP-TT)*DH + 255)/256, 256>>>();

    dim3 g1(30, 47);
    qkv_mm<<<g1, 256, GSM>>>(X, Wq, bq, Wk, Wv, bv);

    dim3 g2(24, NB * NH);
    attn_kernel<<<g2, 128, ASMEM>>>();

    dim3 g3(10, 47);
    out_mm<<<g3, 256, GSM>>>(Wo, bo, out);
}

// round 12
// speedup vs baseline: 1.5801x; 1.5801x over previous
#include <cuda_runtime.h>
#include <cuda_bf16.h>
#include <cstdint>

// Problem constants
#define NB 4
#define TT 1500
#define TP 1536            // padded seq len (24 tiles of 64)
#define EE 1280
#define NH 20
#define DH 64
#define MR (NB*TT)         // 6000
#define QKSCALE 0.125f

// GEMM tiling (R5-proven): block 128x128, k-chunk 16, 8 warps (2x4), warp tile 64x32
#define BK 16
#define NCH (EE/BK)         // 80
#define ROWSTRIDE 48
#define TILE_SZ (128*ROWSTRIDE)      // 6144
#define STAGE_SZ (4*TILE_SZ)         // 24576
#define SMEM_TOTAL (2*STAGE_SZ)      // 49152

// Attention smem: 6 tiles of 64x64 bf16, 144B row stride
#define ATS 144
#define ATILE (64*ATS)
#define AQH 0
#define AQL ATILE
#define AKH (2*ATILE)
#define AKL (3*ATILE)
#define AVH (4*ATILE)
#define AVL (5*ATILE)
#define ASMEM (6*ATILE)    // 55296

// Scratch: q/k/v pre-split bf16 (padded T); ctx fp32
static __device__ __align__(16) __nv_bfloat16 g_qh[(size_t)NB*NH*TP*DH], g_ql[(size_t)NB*NH*TP*DH];
static __device__ __align__(16) __nv_bfloat16 g_kh[(size_t)NB*NH*TP*DH], g_kl[(size_t)NB*NH*TP*DH];
static __device__ __align__(16) __nv_bfloat16 g_vh[(size_t)NB*NH*TP*DH], g_vl[(size_t)NB*NH*TP*DH];
static __device__ float g_ctx[(size_t)MR*EE];

// ---------------- helpers ----------------
__device__ __forceinline__ uint32_t smem_u32(const void* p){
    uint32_t a;
    asm("{ .reg .u64 t; cvta.to.shared.u64 t, %1; cvt.u32.u64 %0, t; }" : "=r"(a) : "l"(p));
    return a;
}
__device__ __forceinline__ void ldx4(uint32_t* r, uint32_t addr){
    asm volatile("ldmatrix.sync.aligned.m8n8.x4.shared.b16 {%0,%1,%2,%3}, [%4];"
        : "=r"(r[0]), "=r"(r[1]), "=r"(r[2]), "=r"(r[3]) : "r"(addr));
}
__device__ __forceinline__ void ldx2(uint32_t* r, uint32_t addr){
    asm volatile("ldmatrix.sync.aligned.m8n8.x2.shared.b16 {%0,%1}, [%2];"
        : "=r"(r[0]), "=r"(r[1]) : "r"(addr));
}
__device__ __forceinline__ void ldx2t(uint32_t* r, uint32_t addr){
    asm volatile("ldmatrix.sync.aligned.m8n8.x2.trans.shared.b16 {%0,%1}, [%2];"
        : "=r"(r[0]), "=r"(r[1]) : "r"(addr));
}
__device__ __forceinline__ void mma_bf16(float* d, const uint32_t* a, const uint32_t* b){
    asm volatile(
        "mma.sync.aligned.m16n8k16.row.col.f32.bf16.bf16.f32 "
        "{%0,%1,%2,%3}, {%4,%5,%6,%7}, {%8,%9}, {%0,%1,%2,%3};"
        : "+f"(d[0]), "+f"(d[1]), "+f"(d[2]), "+f"(d[3])
        : "r"(a[0]), "r"(a[1]), "r"(a[2]), "r"(a[3]), "r"(b[0]), "r"(b[1]));
}
__device__ __forceinline__ void cpa16(uint32_t s, const void* g){
    asm volatile("cp.async.ca.shared.global [%0], [%1], 16;" :: "r"(s), "l"(g));
}
#define CP_COMMIT() asm volatile("cp.async.commit_group;" ::: "memory")
#define CP_WAIT(n)  asm volatile("cp.async.wait_group %0;" :: "n"(n) : "memory")

__device__ __forceinline__ void split4(float4 f, uint2& H, uint2& L){
    __nv_bfloat16 hx = __float2bfloat16(f.x);
    __nv_bfloat16 hy = __float2bfloat16(f.y);
    __nv_bfloat16 hz = __float2bfloat16(f.z);
    __nv_bfloat16 hw = __float2bfloat16(f.w);
    float lx = f.x - __bfloat162float(hx);
    float ly = f.y - __bfloat162float(hy);
    float lz = f.z - __bfloat162float(hz);
    float lw = f.w - __bfloat162float(hw);
    union { __nv_bfloat162 h2[2]; uint2 u; } A, B;
    A.h2[0] = __halves2bfloat162(hx, hy);
    A.h2[1] = __halves2bfloat162(hz, hw);
    B.h2[0] = __floats2bfloat162_rn(lx, ly);
    B.h2[1] = __floats2bfloat162_rn(lz, lw);
    H = A.u; L = B.u;
}
__device__ __forceinline__ void splitp(float a, float b, uint32_t& H, uint32_t& L){
    __nv_bfloat16 ha = __float2bfloat16(a);
    __nv_bfloat16 hb = __float2bfloat16(b);
    float la = a - __bfloat162float(ha);
    float lb = b - __bfloat162float(hb);
    union { __nv_bfloat162 h; uint32_t u; } X, Y;
    X.h = __halves2bfloat162(ha, hb);
    Y.h = __floats2bfloat162_rn(la, lb);
    H = X.u; L = Y.u;
}

// ============================================================================
// zero-pad q/k/v rows t in [TT, TP)
// ============================================================================
__global__ void zero_pad_qkv()
{
    int idx = blockIdx.x * blockDim.x + threadIdx.x;
    const int tot = NB*NH*(TP-TT)*DH;
    if (idx >= tot) return;
    int d = idx & 63;
    int r = idx >> 6;
    int t = TT + (r % (TP-TT));
    int head = r / (TP-TT);
    size_t off = ((size_t)head * TP + t) * DH + d;
    __nv_bfloat16 z = __float2bfloat16(0.f);
    g_qh[off]=z; g_ql[off]=z; g_kh[off]=z; g_kl[off]=z; g_vh[off]=z; g_vl[off]=z;
}

// ============================================================================
// R8-proven GEMM main loop, single sync per chunk (double buffer makes the
// trailing barrier redundant): acc(128x128) += A[row0:+128,:] @ B[0:128,:]^T
// fp32 in, bf16 split in-loop. 256 threads, 8 warps (2x4), warp tile 64x32.
// ============================================================================
__device__ __forceinline__ void mm_loop(
    const float* __restrict__ Ab, const float* __restrict__ Bb, int row0,
    char* sm, uint32_t smb, float acc[4][4][4])
{
    const int tid  = threadIdx.x;
    const int lane = tid & 31;
    const int wid  = tid >> 5;
    const int warp_m = wid >> 2;
    const int warp_n = wid & 3;

    const int srow  = tid >> 1;
    const int shalf = (tid & 1) * 8;
    const bool aval = (row0 + srow) < MR;
    const float* ap = Ab + (size_t)(row0 + srow) * EE + shalf;
    const float* bp = Bb + (size_t)srow * EE + shalf;

    const uint32_t a_rd = smb + (uint32_t)(warp_m*64 + (lane & 15)) * ROWSTRIDE + (lane >> 4) * 16;
    const uint32_t b_rd = smb + 2*TILE_SZ + (uint32_t)(warp_n*32 + (lane & 7)) * ROWSTRIDE + ((lane >> 3) & 1) * 16;
    const uint32_t st0 = (uint32_t)srow * ROWSTRIDE + shalf * 2;

    float4 a0, a1, b0, b1;
    a0 = aval ? *(const float4*)(ap)     : make_float4(0.f,0.f,0.f,0.f);
    a1 = aval ? *(const float4*)(ap + 4) : make_float4(0.f,0.f,0.f,0.f);
    b0 = *(const float4*)(bp);
    b1 = *(const float4*)(bp + 4);

    #pragma unroll 1
    for (int i = 0; i < NCH; i++) {
        char* stg = sm + (i & 1) * STAGE_SZ;
        uint2 H, L;
        split4(a0, H, L);
        *(uint2*)(stg + st0)               = H;
        *(uint2*)(stg + TILE_SZ + st0)     = L;
        split4(a1, H, L);
        *(uint2*)(stg + st0 + 8)           = H;
        *(uint2*)(stg + TILE_SZ + st0 + 8) = L;
        split4(b0, H, L);
        *(uint2*)(stg + 2*TILE_SZ + st0)       = H;
        *(uint2*)(stg + 3*TILE_SZ + st0)       = L;
        split4(b1, H, L);
        *(uint2*)(stg + 2*TILE_SZ + st0 + 8)   = H;
        *(uint2*)(stg + 3*TILE_SZ + st0 + 8)   = L;

        if (i + 1 < NCH) {
            const float* apn = ap + (i+1)*BK;
            const float* bpn = bp + (i+1)*BK;
            a0 = aval ? *(const float4*)(apn)     : make_float4(0.f,0.f,0.f,0.f);
            a1 = aval ? *(const float4*)(apn + 4) : make_float4(0.f,0.f,0.f,0.f);
            b0 = *(const float4*)(bpn);
            b1 = *(const float4*)(bpn + 4);
        }
        __syncthreads();   // stores of stage (i&1) visible; prior readers of it done

        const uint32_t soff = (uint32_t)(i & 1) * STAGE_SZ;
        uint32_t bh[4][2], bl[4][2];
        #pragma unroll
        for (int nt = 0; nt < 4; nt++) {
            ldx2(bh[nt], b_rd + soff + nt*8*ROWSTRIDE);
            ldx2(bl[nt], b_rd + soff + nt*8*ROWSTRIDE + TILE_SZ);
        }
        #pragma unroll
        for (int mt = 0; mt < 4; mt++) {
            uint32_t ah[4], al[4];
            ldx4(ah, a_rd + soff + mt*16*ROWSTRIDE);
            ldx4(al, a_rd + soff + mt*16*ROWSTRIDE + TILE_SZ);
            #pragma unroll
            for (int nt = 0; nt < 4; nt++) {
                mma_bf16(acc[mt][nt], ah, bh[nt]);
                mma_bf16(acc[mt][nt], ah, bl[nt]);
                mma_bf16(acc[mt][nt], al, bh[nt]);
            }
        }
        // no trailing sync: next iteration writes the OTHER stage, and every
        // thread passes the next top-sync only after all readers of that stage
        // (iteration i-1's compute) have finished.
    }
}

// ============================================================================
// QKV GEMM: grid (30, 47). Epilogue writes pre-split bf16 hi/lo q/k/v.
// ============================================================================
__global__ __launch_bounds__(256, 2) void qkv_mm(
    const float* __restrict__ X,
    const float* __restrict__ Wq, const float* __restrict__ bq,
    const float* __restrict__ Wk,
    const float* __restrict__ Wv, const float* __restrict__ bv)
{
    extern __shared__ char sm[];
    uint32_t smb = smem_u32(sm);
    const int tid = threadIdx.x;
    const int lane = tid & 31;
    const int wid = tid >> 5;
    const int warp_m = wid >> 2, warp_n = wid & 3;

    const int which = blockIdx.x / 10;
    const int wcol0 = (blockIdx.x - which*10) * 128;
    const int row0  = blockIdx.y * 128;
    const float* W = (which == 0) ? Wq : (which == 1 ? Wk : Wv);
    const float* bias = (which == 0) ? bq : (which == 2 ? bv : nullptr);
    const float scl = (which == 0) ? QKSCALE : 1.0f;
    __nv_bfloat16* dh = (which == 0) ? g_qh : (which == 1 ? g_kh : g_vh);
    __nv_bfloat16* dl = (which == 0) ? g_ql : (which == 1 ? g_kl : g_vl);

    float acc[4][4][4];
    #pragma unroll
    for (int mt = 0; mt < 4; mt++)
        #pragma unroll
        for (int nt = 0; nt < 4; nt++)
            #pragma unroll
            for (int j = 0; j < 4; j++) acc[mt][nt][j] = 0.f;

    mm_loop(X, W + (size_t)wcol0 * EE, row0, sm, smb, acc);

    const int g = lane >> 2, t4 = lane & 3;
    #pragma unroll
    for (int mt = 0; mt < 4; mt++) {
        #pragma unroll
        for (int nt = 0; nt < 4; nt++) {
            int col = wcol0 + warp_n*32 + nt*8 + 2*t4;
            float2 bb = bias ? *(const float2*)(bias + col) : make_float2(0.f, 0.f);
            int h = col >> 6, d = col & 63;
            int r0w = row0 + warp_m*64 + mt*16 + g;
            if (r0w < MR) {
                int b_ = r0w / TT, t_ = r0w - b_*TT;
                size_t base = ((size_t)(b_*NH + h) * TP + t_) * DH + d;
                uint32_t H, L;
                splitp((acc[mt][nt][0] + bb.x)*scl, (acc[mt][nt][1] + bb.y)*scl, H, L);
                *(uint32_t*)(dh + base) = H;
                *(uint32_t*)(dl + base) = L;
            }
            int r1w = r0w + 8;
            if (r1w < MR) {
                int b_ = r1w / TT, t_ = r1w - b_*TT;
                size_t base = ((size_t)(b_*NH + h) * TP + t_) * DH + d;
                uint32_t H, L;
                splitp((acc[mt][nt][2] + bb.x)*scl, (acc[mt][nt][3] + bb.y)*scl, H, L);
                *(uint32_t*)(dh + base) = H;
                *(uint32_t*)(dl + base) = L;
            }
        }
    }
}

// ============================================================================
// Output projection: out = ctx @ Wo^T + bo. grid (10, 47).
// ============================================================================
__global__ __launch_bounds__(256, 2) void out_mm(
    const float* __restrict__ Wo, const float* __restrict__ bo,
    float* __restrict__ out)
{
    extern __shared__ char sm[];
    uint32_t smb = smem_u32(sm);
    const int tid = threadIdx.x;
    const int lane = tid & 31;
    const int wid = tid >> 5;
    const int warp_m = wid >> 2, warp_n = wid & 3;
    const int col0 = blockIdx.x * 128;
    const int row0 = blockIdx.y * 128;

    float acc[4][4][4];
    #pragma unroll
    for (int mt = 0; mt < 4; mt++)
        #pragma unroll
        for (int nt = 0; nt < 4; nt++)
            #pragma unroll
            for (int j = 0; j < 4; j++) acc[mt][nt][j] = 0.f;

    mm_loop(g_ctx, Wo + (size_t)col0 * EE, row0, sm, smb, acc);

    const int g = lane >> 2, t4 = lane & 3;
    #pragma unroll
    for (int mt = 0; mt < 4; mt++) {
        #pragma unroll
        for (int nt = 0; nt < 4; nt++) {
            int col = col0 + warp_n*32 + nt*8 + 2*t4;
            float2 bb = *(const float2*)(bo + col);
            int r0w = row0 + warp_m*64 + mt*16 + g;
            if (r0w < MR) {
                float2 v = make_float2(acc[mt][nt][0] + bb.x, acc[mt][nt][1] + bb.y);
                *(float2*)(out + (size_t)r0w*EE + col) = v;
            }
            int r1w = r0w + 8;
            if (r1w < MR) {
                float2 v = make_float2(acc[mt][nt][2] + bb.x, acc[mt][nt][3] + bb.y);
                *(float2*)(out + (size_t)r1w*EE + col) = v;
            }
        }
    }
}

// ============================================================================
// Flash attention (R8-proven, byte-identical): pre-split bf16 q/k/v in,
// fp32 ctx out. Grid (24, 80), 128 threads (4 warps, 16 q-rows each).
// ============================================================================
__global__ __launch_bounds__(128) void attn_kernel()
{
    extern __shared__ char sm[];
    uint32_t smb = smem_u32(sm);

    const int tid = threadIdx.x;
    const int lane = tid & 31;
    const int wid = tid >> 5;
    const int g  = lane >> 2;
    const int t4 = lane & 3;

    const int bhidx = blockIdx.y;
    const int b_ = bhidx / NH;
    const int h_ = bhidx - b_ * NH;
    const size_t hb = (size_t)bhidx * TP * DH;
    const int q0 = blockIdx.x * 64;

    // ---- Q tile load (bf16 hi/lo, cp.async) ----
    #pragma unroll
    for (int j = 0; j < 4; j++) {
        int seg = tid + 128*j;
        int row = seg >> 3;
        int o8  = (seg & 7) * 8;
        size_t go = hb + (size_t)(q0 + row) * DH + o8;
        uint32_t so = (uint32_t)row * ATS + o8*2;
        cpa16(smb + AQH + so, g_qh + go);
        cpa16(smb + AQL + so, g_ql + go);
    }
    CP_COMMIT(); CP_WAIT(0);
    __syncthreads();

    // ---- preload Q fragments ----
    uint32_t qh[4][4], ql[4][4];
    {
        uint32_t qa = smb + (uint32_t)(wid*16 + (lane & 15)) * ATS + (lane >> 4) * 16;
        #pragma unroll
        for (int kc = 0; kc < 4; kc++) {
            ldx4(qh[kc], qa + AQH + kc*32);
            ldx4(ql[kc], qa + AQL + kc*32);
        }
    }

    float m0 = -1e30f, m1 = -1e30f, l0 = 0.f, l1 = 0.f;
    float o[8][4];
    #pragma unroll
    for (int nt = 0; nt < 8; nt++)
        #pragma unroll
        for (int j = 0; j < 4; j++) o[nt][j] = 0.f;

    const uint32_t k_rd = smb + (uint32_t)(lane & 7) * ATS + ((lane >> 3) & 1) * 16;
    const uint32_t v_rd = smb + (uint32_t)(lane & 15) * ATS;

    #pragma unroll 1
    for (int kt = 0; kt < 24; kt++) {
        const int k0 = kt * 64;
        __syncthreads();   // previous tile reads done

        // ---- K/V tile load (4 bf16 buffers, cp.async) ----
        #pragma unroll
        for (int j = 0; j < 4; j++) {
            int seg = tid + 128*j;
            int row = seg >> 3;
            int o8  = (seg & 7) * 8;
            size_t go = hb + (size_t)(k0 + row) * DH + o8;
            uint32_t so = (uint32_t)row * ATS + o8*2;
            cpa16(smb + AKH + so, g_kh + go);
            cpa16(smb + AKL + so, g_kl + go);
            cpa16(smb + AVH + so, g_vh + go);
            cpa16(smb + AVL + so, g_vl + go);
        }
        CP_COMMIT(); CP_WAIT(0);
        __syncthreads();

        // ---- S = Q K^T (3-term split) ----
        float s[8][4];
        #pragma unroll
        for (int nt = 0; nt < 8; nt++)
            #pragma unroll
            for (int j = 0; j < 4; j++) s[nt][j] = 0.f;

        #pragma unroll
        for (int nt = 0; nt < 8; nt++) {
            uint32_t kbase = k_rd + (uint32_t)nt*8*ATS;
            #pragma unroll
            for (int kc = 0; kc < 4; kc++) {
                uint32_t kh2[2], kl2[2];
                ldx2(kh2, kbase + AKH + kc*32);
                ldx2(kl2, kbase + AKL + kc*32);
                mma_bf16(s[nt], qh[kc], kh2);
                mma_bf16(s[nt], qh[kc], kl2);
                mma_bf16(s[nt], ql[kc], kh2);
            }
        }

        // ---- mask invalid key columns (last tile) ----
        if (k0 + 64 > TT) {
            #pragma unroll
            for (int nt = 0; nt < 8; nt++) {
                int col = k0 + nt*8 + 2*t4;
                if (col   >= TT) { s[nt][0] = -1e30f; s[nt][2] = -1e30f; }
                if (col+1 >= TT) { s[nt][1] = -1e30f; s[nt][3] = -1e30f; }
            }
        }

        // ---- online softmax ----
        float mx0 = -1e30f, mx1 = -1e30f;
        #pragma unroll
        for (int nt = 0; nt < 8; nt++) {
            mx0 = fmaxf(mx0, fmaxf(s[nt][0], s[nt][1]));
            mx1 = fmaxf(mx1, fmaxf(s[nt][2], s[nt][3]));
        }
        mx0 = fmaxf(mx0, __shfl_xor_sync(0xffffffffu, mx0, 1));
        mx0 = fmaxf(mx0, __shfl_xor_sync(0xffffffffu, mx0, 2));
        mx1 = fmaxf(mx1, __shfl_xor_sync(0xffffffffu, mx1, 1));
        mx1 = fmaxf(mx1, __shfl_xor_sync(0xffffffffu, mx1, 2));

        float mn0 = fmaxf(m0, mx0), mn1 = fmaxf(m1, mx1);
        float al0 = __expf(m0 - mn0), al1 = __expf(m1 - mn1);
        m0 = mn0; m1 = mn1;

        float sum0 = 0.f, sum1 = 0.f;
        #pragma unroll
        for (int nt = 0; nt < 8; nt++) {
            s[nt][0] = __expf(s[nt][0] - mn0); sum0 += s[nt][0];
            s[nt][1] = __expf(s[nt][1] - mn0); sum0 += s[nt][1];
            s[nt][2] = __expf(s[nt][2] - mn1); sum1 += s[nt][2];
            s[nt][3] = __expf(s[nt][3] - mn1); sum1 += s[nt][3];
        }
        sum0 += __shfl_xor_sync(0xffffffffu, sum0, 1);
        sum0 += __shfl_xor_sync(0xffffffffu, sum0, 2);
        sum1 += __shfl_xor_sync(0xffffffffu, sum1, 1);
        sum1 += __shfl_xor_sync(0xffffffffu, sum1, 2);
        l0 = l0 * al0 + sum0;
        l1 = l1 * al1 + sum1;

        #pragma unroll
        for (int nt = 0; nt < 8; nt++) {
            o[nt][0] *= al0; o[nt][1] *= al0;
            o[nt][2] *= al1; o[nt][3] *= al1;
        }

        // ---- O += P V (P split in registers; V via trans-ldmatrix) ----
        #pragma unroll
        for (int kc = 0; kc < 4; kc++) {
            uint32_t ah[4], al_[4];
            splitp(s[2*kc][0],   s[2*kc][1],   ah[0], al_[0]);
            splitp(s[2*kc][2],   s[2*kc][3],   ah[1], al_[1]);
            splitp(s[2*kc+1][0], s[2*kc+1][1], ah[2], al_[2]);
            splitp(s[2*kc+1][2], s[2*kc+1][3], ah[3], al_[3]);
            uint32_t vbase = v_rd + (uint32_t)kc*16*ATS;
            #pragma unroll
            for (int nt = 0; nt < 8; nt++) {
                uint32_t vh2[2], vl2[2];
                ldx2t(vh2, vbase + AVH + nt*16);
                ldx2t(vl2, vbase + AVL + nt*16);
                mma_bf16(o[nt], ah,  vh2);
                mma_bf16(o[nt], ah,  vl2);
                mma_bf16(o[nt], al_, vh2);
            }
        }
    }

    // ---- epilogue: normalize, write fp32 ctx [b*T+t, h*64+d] ----
    float inv0 = 1.0f / l0, inv1 = 1.0f / l1;
    int r0w = q0 + wid*16 + g;
    int r1w = r0w + 8;
    #pragma unroll
    for (int nt = 0; nt < 8; nt++) {
        int d = nt*8 + 2*t4;
        if (r0w < TT) {
            float* dst = g_ctx + ((size_t)(b_ * TT + r0w)) * EE + h_ * DH + d;
            *(float2*)dst = make_float2(o[nt][0]*inv0, o[nt][1]*inv0);
        }
        if (r1w < TT) {
            float* dst = g_ctx + ((size_t)(b_ * TT + r1w)) * EE + h_ * DH + d;
            *(float2*)dst = make_float2(o[nt][2]*inv1, o[nt][3]*inv1);
        }
    }
}

extern "C" void kernel_launch(void* const* d_in, const int* in_sizes, int n_in,
                              void* d_out, int out_size)
{
    const float* X  = (const float*)d_in[0];
    const float* Wq = (const float*)d_in[1];
    const float* bq = (const float*)d_in[2];
    const float* Wk = (const float*)d_in[3];
    const float* Wv = (const float*)d_in[4];
    const float* bv = (const float*)d_in[5];
    const float* Wo = (const float*)d_in[6];
    const float* bo = (const float*)d_in[7];
    float* out = (float*)d_out;

    cudaFuncSetAttribute(qkv_mm, cudaFuncAttributeMaxDynamicSharedMemorySize, SMEM_TOTAL);
    cudaFuncSetAttribute(out_mm, cudaFuncAttributeMaxDynamicSharedMemorySize, SMEM_TOTAL);
    cudaFuncSetAttribute(attn_kernel, cudaFuncAttributeMaxDynamicSharedMemorySize, ASMEM);

    zero_pad_qkv<<<(NB*NH*(TP-TT)*DH + 255)/256, 256>>>();

    dim3 g1(30, 47);
    qkv_mm<<<g1, 256, SMEM_TOTAL>>>(X, Wq, bq, Wk, Wv, bv);

    dim3 g2(24, NB * NH);
    attn_kernel<<<g2, 128, ASMEM>>>();

    dim3 g3(10, 47);
    out_mm<<<g3, 256, SMEM_TOTAL>>>(Wo, bo, out);
}

// round 13
// speedup vs baseline: 1.6965x; 1.0737x over previous
#include <cuda_runtime.h>
#include <cuda_bf16.h>
#include <cstdint>

// Problem constants
#define NB 4
#define TT 1500
#define TP 1536            // padded seq len (24 tiles of 64)
#define EE 1280
#define NH 20
#define DH 64
#define MR (NB*TT)         // 6000
#define QKSCALE 0.125f

// GEMM tiling (R12-proven): block 128x128, k-chunk 16, 8 warps (2x4), warp tile 64x32
#define BK 16
#define NCH (EE/BK)         // 80
#define ROWSTRIDE 48
#define TILE_SZ (128*ROWSTRIDE)      // 6144
#define STAGE_SZ (4*TILE_SZ)         // 24576
#define SMEM_TOTAL (2*STAGE_SZ)      // 49152

// Attention smem: 2 stages x 4 tiles (KH,KL,VH,VL) of 64x64 bf16, 144B stride
#define ATS 144
#define ATILE (64*ATS)      // 9216
#define SKH 0
#define SKL ATILE
#define SVH (2*ATILE)
#define SVL (3*ATILE)
#define AST (4*ATILE)       // 36864 per stage
#define ASMEM (2*AST)       // 73728

// Scratch: q/k/v pre-split bf16 (padded T); ctx fp32
static __device__ __align__(16) __nv_bfloat16 g_qh[(size_t)NB*NH*TP*DH], g_ql[(size_t)NB*NH*TP*DH];
static __device__ __align__(16) __nv_bfloat16 g_kh[(size_t)NB*NH*TP*DH], g_kl[(size_t)NB*NH*TP*DH];
static __device__ __align__(16) __nv_bfloat16 g_vh[(size_t)NB*NH*TP*DH], g_vl[(size_t)NB*NH*TP*DH];
static __device__ float g_ctx[(size_t)MR*EE];

// ---------------- helpers ----------------
__device__ __forceinline__ uint32_t smem_u32(const void* p){
    uint32_t a;
    asm("{ .reg .u64 t; cvta.to.shared.u64 t, %1; cvt.u32.u64 %0, t; }" : "=r"(a) : "l"(p));
    return a;
}
__device__ __forceinline__ void ldx4(uint32_t* r, uint32_t addr){
    asm volatile("ldmatrix.sync.aligned.m8n8.x4.shared.b16 {%0,%1,%2,%3}, [%4];"
        : "=r"(r[0]), "=r"(r[1]), "=r"(r[2]), "=r"(r[3]) : "r"(addr));
}
__device__ __forceinline__ void ldx2(uint32_t* r, uint32_t addr){
    asm volatile("ldmatrix.sync.aligned.m8n8.x2.shared.b16 {%0,%1}, [%2];"
        : "=r"(r[0]), "=r"(r[1]) : "r"(addr));
}
__device__ __forceinline__ void ldx2t(uint32_t* r, uint32_t addr){
    asm volatile("ldmatrix.sync.aligned.m8n8.x2.trans.shared.b16 {%0,%1}, [%2];"
        : "=r"(r[0]), "=r"(r[1]) : "r"(addr));
}
__device__ __forceinline__ void mma_bf16(float* d, const uint32_t* a, const uint32_t* b){
    asm volatile(
        "mma.sync.aligned.m16n8k16.row.col.f32.bf16.bf16.f32 "
        "{%0,%1,%2,%3}, {%4,%5,%6,%7}, {%8,%9}, {%0,%1,%2,%3};"
        : "+f"(d[0]), "+f"(d[1]), "+f"(d[2]), "+f"(d[3])
        : "r"(a[0]), "r"(a[1]), "r"(a[2]), "r"(a[3]), "r"(b[0]), "r"(b[1]));
}
__device__ __forceinline__ void cpa16(uint32_t s, const void* g){
    asm volatile("cp.async.ca.shared.global [%0], [%1], 16;" :: "r"(s), "l"(g));
}
#define CP_COMMIT() asm volatile("cp.async.commit_group;" ::: "memory")
#define CP_WAIT(n)  asm volatile("cp.async.wait_group %0;" :: "n"(n) : "memory")

__device__ __forceinline__ void split4(float4 f, uint2& H, uint2& L){
    __nv_bfloat16 hx = __float2bfloat16(f.x);
    __nv_bfloat16 hy = __float2bfloat16(f.y);
    __nv_bfloat16 hz = __float2bfloat16(f.z);
    __nv_bfloat16 hw = __float2bfloat16(f.w);
    float lx = f.x - __bfloat162float(hx);
    float ly = f.y - __bfloat162float(hy);
    float lz = f.z - __bfloat162float(hz);
    float lw = f.w - __bfloat162float(hw);
    union { __nv_bfloat162 h2[2]; uint2 u; } A, B;
    A.h2[0] = __halves2bfloat162(hx, hy);
    A.h2[1] = __halves2bfloat162(hz, hw);
    B.h2[0] = __floats2bfloat162_rn(lx, ly);
    B.h2[1] = __floats2bfloat162_rn(lz, lw);
    H = A.u; L = B.u;
}
__device__ __forceinline__ void splitp(float a, float b, uint32_t& H, uint32_t& L){
    __nv_bfloat16 ha = __float2bfloat16(a);
    __nv_bfloat16 hb = __float2bfloat16(b);
    float la = a - __bfloat162float(ha);
    float lb = b - __bfloat162float(hb);
    union { __nv_bfloat162 h; uint32_t u; } X, Y;
    X.h = __halves2bfloat162(ha, hb);
    Y.h = __floats2bfloat162_rn(la, lb);
    H = X.u; L = Y.u;
}

// ============================================================================
// zero-pad q/k/v rows t in [TT, TP)
// ============================================================================
__global__ void zero_pad_qkv()
{
    int idx = blockIdx.x * blockDim.x + threadIdx.x;
    const int tot = NB*NH*(TP-TT)*DH;
    if (idx >= tot) return;
    int d = idx & 63;
    int r = idx >> 6;
    int t = TT + (r % (TP-TT));
    int head = r / (TP-TT);
    size_t off = ((size_t)head * TP + t) * DH + d;
    __nv_bfloat16 z = __float2bfloat16(0.f);
    g_qh[off]=z; g_ql[off]=z; g_kh[off]=z; g_kl[off]=z; g_vh[off]=z; g_vl[off]=z;
}

// ============================================================================
// R12-proven GEMM main loop, single sync per chunk.
// ============================================================================
__device__ __forceinline__ void mm_loop(
    const float* __restrict__ Ab, const float* __restrict__ Bb, int row0,
    char* sm, uint32_t smb, float acc[4][4][4])
{
    const int tid  = threadIdx.x;
    const int lane = tid & 31;
    const int wid  = tid >> 5;
    const int warp_m = wid >> 2;
    const int warp_n = wid & 3;

    const int srow  = tid >> 1;
    const int shalf = (tid & 1) * 8;
    const bool aval = (row0 + srow) < MR;
    const float* ap = Ab + (size_t)(row0 + srow) * EE + shalf;
    const float* bp = Bb + (size_t)srow * EE + shalf;

    const uint32_t a_rd = smb + (uint32_t)(warp_m*64 + (lane & 15)) * ROWSTRIDE + (lane >> 4) * 16;
    const uint32_t b_rd = smb + 2*TILE_SZ + (uint32_t)(warp_n*32 + (lane & 7)) * ROWSTRIDE + ((lane >> 3) & 1) * 16;
    const uint32_t st0 = (uint32_t)srow * ROWSTRIDE + shalf * 2;

    float4 a0, a1, b0, b1;
    a0 = aval ? *(const float4*)(ap)     : make_float4(0.f,0.f,0.f,0.f);
    a1 = aval ? *(const float4*)(ap + 4) : make_float4(0.f,0.f,0.f,0.f);
    b0 = *(const float4*)(bp);
    b1 = *(const float4*)(bp + 4);

    #pragma unroll 1
    for (int i = 0; i < NCH; i++) {
        char* stg = sm + (i & 1) * STAGE_SZ;
        uint2 H, L;
        split4(a0, H, L);
        *(uint2*)(stg + st0)               = H;
        *(uint2*)(stg + TILE_SZ + st0)     = L;
        split4(a1, H, L);
        *(uint2*)(stg + st0 + 8)           = H;
        *(uint2*)(stg + TILE_SZ + st0 + 8) = L;
        split4(b0, H, L);
        *(uint2*)(stg + 2*TILE_SZ + st0)       = H;
        *(uint2*)(stg + 3*TILE_SZ + st0)       = L;
        split4(b1, H, L);
        *(uint2*)(stg + 2*TILE_SZ + st0 + 8)   = H;
        *(uint2*)(stg + 3*TILE_SZ + st0 + 8)   = L;

        if (i + 1 < NCH) {
            const float* apn = ap + (i+1)*BK;
            const float* bpn = bp + (i+1)*BK;
            a0 = aval ? *(const float4*)(apn)     : make_float4(0.f,0.f,0.f,0.f);
            a1 = aval ? *(const float4*)(apn + 4) : make_float4(0.f,0.f,0.f,0.f);
            b0 = *(const float4*)(bpn);
            b1 = *(const float4*)(bpn + 4);
        }
        __syncthreads();

        const uint32_t soff = (uint32_t)(i & 1) * STAGE_SZ;
        uint32_t bh[4][2], bl[4][2];
        #pragma unroll
        for (int nt = 0; nt < 4; nt++) {
            ldx2(bh[nt], b_rd + soff + nt*8*ROWSTRIDE);
            ldx2(bl[nt], b_rd + soff + nt*8*ROWSTRIDE + TILE_SZ);
        }
        #pragma unroll
        for (int mt = 0; mt < 4; mt++) {
            uint32_t ah[4], al[4];
            ldx4(ah, a_rd + soff + mt*16*ROWSTRIDE);
            ldx4(al, a_rd + soff + mt*16*ROWSTRIDE + TILE_SZ);
            #pragma unroll
            for (int nt = 0; nt < 4; nt++) {
                mma_bf16(acc[mt][nt], ah, bh[nt]);
                mma_bf16(acc[mt][nt], ah, bl[nt]);
                mma_bf16(acc[mt][nt], al, bh[nt]);
            }
        }
        // no trailing sync (double buffer; proven in R12)
    }
}

// ============================================================================
// QKV GEMM: grid (30, 47). Epilogue writes pre-split bf16 hi/lo q/k/v.
// ============================================================================
__global__ __launch_bounds__(256, 2) void qkv_mm(
    const float* __restrict__ X,
    const float* __restrict__ Wq, const float* __restrict__ bq,
    const float* __restrict__ Wk,
    const float* __restrict__ Wv, const float* __restrict__ bv)
{
    extern __shared__ char sm[];
    uint32_t smb = smem_u32(sm);
    const int tid = threadIdx.x;
    const int lane = tid & 31;
    const int wid = tid >> 5;
    const int warp_m = wid >> 2, warp_n = wid & 3;

    const int which = blockIdx.x / 10;
    const int wcol0 = (blockIdx.x - which*10) * 128;
    const int row0  = blockIdx.y * 128;
    const float* W = (which == 0) ? Wq : (which == 1 ? Wk : Wv);
    const float* bias = (which == 0) ? bq : (which == 2 ? bv : nullptr);
    const float scl = (which == 0) ? QKSCALE : 1.0f;
    __nv_bfloat16* dh = (which == 0) ? g_qh : (which == 1 ? g_kh : g_vh);
    __nv_bfloat16* dl = (which == 0) ? g_ql : (which == 1 ? g_kl : g_vl);

    float acc[4][4][4];
    #pragma unroll
    for (int mt = 0; mt < 4; mt++)
        #pragma unroll
        for (int nt = 0; nt < 4; nt++)
            #pragma unroll
            for (int j = 0; j < 4; j++) acc[mt][nt][j] = 0.f;

    mm_loop(X, W + (size_t)wcol0 * EE, row0, sm, smb, acc);

    const int g = lane >> 2, t4 = lane & 3;
    #pragma unroll
    for (int mt = 0; mt < 4; mt++) {
        #pragma unroll
        for (int nt = 0; nt < 4; nt++) {
            int col = wcol0 + warp_n*32 + nt*8 + 2*t4;
            float2 bb = bias ? *(const float2*)(bias + col) : make_float2(0.f, 0.f);
            int h = col >> 6, d = col & 63;
            int r0w = row0 + warp_m*64 + mt*16 + g;
            if (r0w < MR) {
                int b_ = r0w / TT, t_ = r0w - b_*TT;
                size_t base = ((size_t)(b_*NH + h) * TP + t_) * DH + d;
                uint32_t H, L;
                splitp((acc[mt][nt][0] + bb.x)*scl, (acc[mt][nt][1] + bb.y)*scl, H, L);
                *(uint32_t*)(dh + base) = H;
                *(uint32_t*)(dl + base) = L;
            }
            int r1w = r0w + 8;
            if (r1w < MR) {
                int b_ = r1w / TT, t_ = r1w - b_*TT;
                size_t base = ((size_t)(b_*NH + h) * TP + t_) * DH + d;
                uint32_t H, L;
                splitp((acc[mt][nt][2] + bb.x)*scl, (acc[mt][nt][3] + bb.y)*scl, H, L);
                *(uint32_t*)(dh + base) = H;
                *(uint32_t*)(dl + base) = L;
            }
        }
    }
}

// ============================================================================
// Output projection: out = ctx @ Wo^T + bo. grid (10, 47).
// ============================================================================
__global__ __launch_bounds__(256, 2) void out_mm(
    const float* __restrict__ Wo, const float* __restrict__ bo,
    float* __restrict__ out)
{
    extern __shared__ char sm[];
    uint32_t smb = smem_u32(sm);
    const int tid = threadIdx.x;
    const int lane = tid & 31;
    const int wid = tid >> 5;
    const int warp_m = wid >> 2, warp_n = wid & 3;
    const int col0 = blockIdx.x * 128;
    const int row0 = blockIdx.y * 128;

    float acc[4][4][4];
    #pragma unroll
    for (int mt = 0; mt < 4; mt++)
        #pragma unroll
        for (int nt = 0; nt < 4; nt++)
            #pragma unroll
            for (int j = 0; j < 4; j++) acc[mt][nt][j] = 0.f;

    mm_loop(g_ctx, Wo + (size_t)col0 * EE, row0, sm, smb, acc);

    const int g = lane >> 2, t4 = lane & 3;
    #pragma unroll
    for (int mt = 0; mt < 4; mt++) {
        #pragma unroll
        for (int nt = 0; nt < 4; nt++) {
            int col = col0 + warp_n*32 + nt*8 + 2*t4;
            float2 bb = *(const float2*)(bo + col);
            int r0w = row0 + warp_m*64 + mt*16 + g;
            if (r0w < MR) {
                float2 v = make_float2(acc[mt][nt][0] + bb.x, acc[mt][nt][1] + bb.y);
                *(float2*)(out + (size_t)r0w*EE + col) = v;
            }
            int r1w = r0w + 8;
            if (r1w < MR) {
                float2 v = make_float2(acc[mt][nt][2] + bb.x, acc[mt][nt][3] + bb.y);
                *(float2*)(out + (size_t)r1w*EE + col) = v;
            }
        }
    }
}

// ============================================================================
// Flash attention: R12 arithmetic + read patterns, K/V double-buffered.
// Grid (24, 80), 128 threads (4 warps, 16 q-rows each). fp32 ctx out.
// ============================================================================
__global__ __launch_bounds__(128) void attn_kernel()
{
    extern __shared__ char sm[];
    uint32_t smb = smem_u32(sm);

    const int tid = threadIdx.x;
    const int lane = tid & 31;
    const int wid = tid >> 5;
    const int g  = lane >> 2;
    const int t4 = lane & 3;

    const int bhidx = blockIdx.y;
    const int b_ = bhidx / NH;
    const int h_ = bhidx - b_ * NH;
    const size_t hb = (size_t)bhidx * TP * DH;
    const int q0 = blockIdx.x * 64;

    // ---- Q staging into stage-0 (SKH/SKL areas), then fragments ----
    #pragma unroll
    for (int j = 0; j < 4; j++) {
        int seg = tid + 128*j;
        int row = seg >> 3;
        int o8  = (seg & 7) * 8;
        size_t go = hb + (size_t)(q0 + row) * DH + o8;
        uint32_t so = (uint32_t)row * ATS + o8*2;
        cpa16(smb + SKH + so, g_qh + go);
        cpa16(smb + SKL + so, g_ql + go);
    }
    CP_COMMIT(); CP_WAIT(0);
    __syncthreads();

    uint32_t qh[4][4], ql[4][4];
    {
        uint32_t qa = smb + (uint32_t)(wid*16 + (lane & 15)) * ATS + (lane >> 4) * 16;
        #pragma unroll
        for (int kc = 0; kc < 4; kc++) {
            ldx4(qh[kc], qa + SKH + kc*32);
            ldx4(ql[kc], qa + SKL + kc*32);
        }
    }
    __syncthreads();   // everyone done reading Q staging before tile-0 overwrite

    float m0 = -1e30f, m1 = -1e30f, l0 = 0.f, l1 = 0.f;
    float o[8][4];
    #pragma unroll
    for (int nt = 0; nt < 8; nt++)
        #pragma unroll
        for (int j = 0; j < 4; j++) o[nt][j] = 0.f;

    // ---- issue K/V tile 0 into stage 0 ----
    #pragma unroll
    for (int j = 0; j < 4; j++) {
        int seg = tid + 128*j;
        int row = seg >> 3;
        int o8  = (seg & 7) * 8;
        size_t go = hb + (size_t)row * DH + o8;
        uint32_t so = (uint32_t)row * ATS + o8*2;
        cpa16(smb + SKH + so, g_kh + go);
        cpa16(smb + SKL + so, g_kl + go);
        cpa16(smb + SVH + so, g_vh + go);
        cpa16(smb + SVL + so, g_vl + go);
    }
    CP_COMMIT();

    #pragma unroll 1
    for (int kt = 0; kt < 24; kt++) {
        const int k0 = kt * 64;
        CP_WAIT(0);        // this tile's cp.asyncs (ours) complete
        __syncthreads();   // publish all threads' copies; prior readers of next-stage done

        // prefetch next tile into the other stage (overlaps compute below)
        if (kt + 1 < 24) {
            const int k1 = (kt + 1) * 64;
            const uint32_t stN = smb + ((kt + 1) & 1) * AST;
            #pragma unroll
            for (int j = 0; j < 4; j++) {
                int seg = tid + 128*j;
                int row = seg >> 3;
                int o8  = (seg & 7) * 8;
                size_t go = hb + (size_t)(k1 + row) * DH + o8;
                uint32_t so = (uint32_t)row * ATS + o8*2;
                cpa16(stN + SKH + so, g_kh + go);
                cpa16(stN + SKL + so, g_kl + go);
                cpa16(stN + SVH + so, g_vh + go);
                cpa16(stN + SVL + so, g_vl + go);
            }
            CP_COMMIT();
        }

        const uint32_t st = smb + (kt & 1) * AST;
        const uint32_t k_rd = st + (uint32_t)(lane & 7) * ATS + ((lane >> 3) & 1) * 16;
        const uint32_t v_rd = st + (uint32_t)(lane & 15) * ATS;

        // ---- S = Q K^T (3-term split), ldx2 pattern identical to R12 ----
        float s[8][4];
        #pragma unroll
        for (int nt = 0; nt < 8; nt++)
            #pragma unroll
            for (int j = 0; j < 4; j++) s[nt][j] = 0.f;

        #pragma unroll
        for (int nt = 0; nt < 8; nt++) {
            uint32_t kbase = k_rd + (uint32_t)nt*8*ATS;
            #pragma unroll
            for (int kc = 0; kc < 4; kc++) {
                uint32_t kh2[2], kl2[2];
                ldx2(kh2, kbase + SKH + kc*32);
                ldx2(kl2, kbase + SKL + kc*32);
                mma_bf16(s[nt], qh[kc], kh2);
                mma_bf16(s[nt], qh[kc], kl2);
                mma_bf16(s[nt], ql[kc], kh2);
            }
        }

        // ---- mask invalid key columns (last tile) ----
        if (k0 + 64 > TT) {
            #pragma unroll
            for (int nt = 0; nt < 8; nt++) {
                int col = k0 + nt*8 + 2*t4;
                if (col   >= TT) { s[nt][0] = -1e30f; s[nt][2] = -1e30f; }
                if (col+1 >= TT) { s[nt][1] = -1e30f; s[nt][3] = -1e30f; }
            }
        }

        // ---- online softmax ----
        float mx0 = -1e30f, mx1 = -1e30f;
        #pragma unroll
        for (int nt = 0; nt < 8; nt++) {
            mx0 = fmaxf(mx0, fmaxf(s[nt][0], s[nt][1]));
            mx1 = fmaxf(mx1, fmaxf(s[nt][2], s[nt][3]));
        }
        mx0 = fmaxf(mx0, __shfl_xor_sync(0xffffffffu, mx0, 1));
        mx0 = fmaxf(mx0, __shfl_xor_sync(0xffffffffu, mx0, 2));
        mx1 = fmaxf(mx1, __shfl_xor_sync(0xffffffffu, mx1, 1));
        mx1 = fmaxf(mx1, __shfl_xor_sync(0xffffffffu, mx1, 2));

        float mn0 = fmaxf(m0, mx0), mn1 = fmaxf(m1, mx1);
        float al0 = __expf(m0 - mn0), al1 = __expf(m1 - mn1);
        m0 = mn0; m1 = mn1;

        float sum0 = 0.f, sum1 = 0.f;
        #pragma unroll
        for (int nt = 0; nt < 8; nt++) {
            s[nt][0] = __expf(s[nt][0] - mn0); sum0 += s[nt][0];
            s[nt][1] = __expf(s[nt][1] - mn0); sum0 += s[nt][1];
            s[nt][2] = __expf(s[nt][2] - mn1); sum1 += s[nt][2];
            s[nt][3] = __expf(s[nt][3] - mn1); sum1 += s[nt][3];
        }
        sum0 += __shfl_xor_sync(0xffffffffu, sum0, 1);
        sum0 += __shfl_xor_sync(0xffffffffu, sum0, 2);
        sum1 += __shfl_xor_sync(0xffffffffu, sum1, 1);
        sum1 += __shfl_xor_sync(0xffffffffu, sum1, 2);
        l0 = l0 * al0 + sum0;
        l1 = l1 * al1 + sum1;

        #pragma unroll
        for (int nt = 0; nt < 8; nt++) {
            o[nt][0] *= al0; o[nt][1] *= al0;
            o[nt][2] *= al1; o[nt][3] *= al1;
        }

        // ---- O += P V (P split in registers; V via trans-ldmatrix) ----
        #pragma unroll
        for (int kc = 0; kc < 4; kc++) {
            uint32_t ah[4], al_[4];
            splitp(s[2*kc][0],   s[2*kc][1],   ah[0], al_[0]);
            splitp(s[2*kc][2],   s[2*kc][3],   ah[1], al_[1]);
            splitp(s[2*kc+1][0], s[2*kc+1][1], ah[2], al_[2]);
            splitp(s[2*kc+1][2], s[2*kc+1][3], ah[3], al_[3]);
            uint32_t vbase = v_rd + (uint32_t)kc*16*ATS;
            #pragma unroll
            for (int nt = 0; nt < 8; nt++) {
                uint32_t vh2[2], vl2[2];
                ldx2t(vh2, vbase + SVH + nt*16);
                ldx2t(vl2, vbase + SVL + nt*16);
                mma_bf16(o[nt], ah,  vh2);
                mma_bf16(o[nt], ah,  vl2);
                mma_bf16(o[nt], al_, vh2);
            }
        }
    }

    // ---- epilogue: normalize, write fp32 ctx [b*T+t, h*64+d] ----
    float inv0 = 1.0f / l0, inv1 = 1.0f / l1;
    int r0w = q0 + wid*16 + g;
    int r1w = r0w + 8;
    #pragma unroll
    for (int nt = 0; nt < 8; nt++) {
        int d = nt*8 + 2*t4;
        if (r0w < TT) {
            float* dst = g_ctx + ((size_t)(b_ * TT + r0w)) * EE + h_ * DH + d;
            *(float2*)dst = make_float2(o[nt][0]*inv0, o[nt][1]*inv0);
        }
        if (r1w < TT) {
            float* dst = g_ctx + ((size_t)(b_ * TT + r1w)) * EE + h_ * DH + d;
            *(float2*)dst = make_float2(o[nt][2]*inv1, o[nt][3]*inv1);
        }
    }
}

extern "C" void kernel_launch(void* const* d_in, const int* in_sizes, int n_in,
                              void* d_out, int out_size)
{
    const float* X  = (const float*)d_in[0];
    const float* Wq = (const float*)d_in[1];
    const float* bq = (const float*)d_in[2];
    const float* Wk = (const float*)d_in[3];
    const float* Wv = (const float*)d_in[4];
    const float* bv = (const float*)d_in[5];
    const float* Wo = (const float*)d_in[6];
    const float* bo = (const float*)d_in[7];
    float* out = (float*)d_out;

    cudaFuncSetAttribute(qkv_mm, cudaFuncAttributeMaxDynamicSharedMemorySize, SMEM_TOTAL);
    cudaFuncSetAttribute(out_mm, cudaFuncAttributeMaxDynamicSharedMemorySize, SMEM_TOTAL);
    cudaFuncSetAttribute(attn_kernel, cudaFuncAttributeMaxDynamicSharedMemorySize, ASMEM);

    zero_pad_qkv<<<(NB*NH*(TP-TT)*DH + 255)/256, 256>>>();

    dim3 g1(30, 47);
    qkv_mm<<<g1, 256, SMEM_TOTAL>>>(X, Wq, bq, Wk, Wv, bv);

    dim3 g2(24, NB * NH);
    attn_kernel<<<g2, 128, ASMEM>>>();

    dim3 g3(10, 47);
    out_mm<<<g3, 256, SMEM_TOTAL>>>(Wo, bo, out);
}

// round 14
// speedup vs baseline: 1.7299x; 1.0197x over previous
#include <cuda_runtime.h>
#include <cuda_bf16.h>
#include <cstdint>

// Problem constants
#define NB 4
#define TT 1500
#define TP 1536            // padded seq len (24 tiles of 64)
#define EE 1280
#define NH 20
#define DH 64
#define MR (NB*TT)         // 6000
#define MRP 6016           // padded rows (47 * 128)
#define QKSCALE 0.125f

// GEMM tiling: CTA 128x128, 8 warps (2x4), warp tile 64x32, k-chunk 32, cp.async feed
#define BK 32
#define NCH (EE/BK)         // 40
#define RS 80               // smem row stride bytes (32 bf16 = 64B + 16 pad) - LDSM conflict-free
#define TSZ (128*RS)        // 10240
#define STG (4*TSZ)         // Ah,Al,Bh,Bl = 40960
#define GSM (2*STG)         // 81920

// Attention smem: 2 stages x 4 tiles (KH,KL,VH,VL) of 64x64 bf16, 144B stride
#define ATS 144
#define ATILE (64*ATS)      // 9216
#define SKH 0
#define SKL ATILE
#define SVH (2*ATILE)
#define SVL (3*ATILE)
#define AST (4*ATILE)       // 36864 per stage
#define ASMEM (2*AST)       // 73728

// ---- pre-split bf16 global buffers ----
static __device__ __align__(16) __nv_bfloat16 g_Xh[(size_t)MRP*EE], g_Xl[(size_t)MRP*EE];
static __device__ __align__(16) __nv_bfloat16 g_Wqh[(size_t)EE*EE], g_Wql[(size_t)EE*EE];
static __device__ __align__(16) __nv_bfloat16 g_Wkh[(size_t)EE*EE], g_Wkl[(size_t)EE*EE];
static __device__ __align__(16) __nv_bfloat16 g_Wvh[(size_t)EE*EE], g_Wvl[(size_t)EE*EE];
static __device__ __align__(16) __nv_bfloat16 g_Woh[(size_t)EE*EE], g_Wol[(size_t)EE*EE];
static __device__ __align__(16) __nv_bfloat16 g_qh[(size_t)NB*NH*TP*DH], g_ql[(size_t)NB*NH*TP*DH];
static __device__ __align__(16) __nv_bfloat16 g_kh[(size_t)NB*NH*TP*DH], g_kl[(size_t)NB*NH*TP*DH];
static __device__ __align__(16) __nv_bfloat16 g_vh[(size_t)NB*NH*TP*DH], g_vl[(size_t)NB*NH*TP*DH];
static __device__ __align__(16) __nv_bfloat16 g_cth[(size_t)MRP*EE], g_ctl[(size_t)MRP*EE];

// ---------------- helpers ----------------
__device__ __forceinline__ uint32_t smem_u32(const void* p){
    uint32_t a;
    asm("{ .reg .u64 t; cvta.to.shared.u64 t, %1; cvt.u32.u64 %0, t; }" : "=r"(a) : "l"(p));
    return a;
}
__device__ __forceinline__ void ldx4(uint32_t* r, uint32_t addr){
    asm volatile("ldmatrix.sync.aligned.m8n8.x4.shared.b16 {%0,%1,%2,%3}, [%4];"
        : "=r"(r[0]), "=r"(r[1]), "=r"(r[2]), "=r"(r[3]) : "r"(addr));
}
__device__ __forceinline__ void ldx2(uint32_t* r, uint32_t addr){
    asm volatile("ldmatrix.sync.aligned.m8n8.x2.shared.b16 {%0,%1}, [%2];"
        : "=r"(r[0]), "=r"(r[1]) : "r"(addr));
}
__device__ __forceinline__ void ldx2t(uint32_t* r, uint32_t addr){
    asm volatile("ldmatrix.sync.aligned.m8n8.x2.trans.shared.b16 {%0,%1}, [%2];"
        : "=r"(r[0]), "=r"(r[1]) : "r"(addr));
}
__device__ __forceinline__ void mma_bf16(float* d, const uint32_t* a, const uint32_t* b){
    asm volatile(
        "mma.sync.aligned.m16n8k16.row.col.f32.bf16.bf16.f32 "
        "{%0,%1,%2,%3}, {%4,%5,%6,%7}, {%8,%9}, {%0,%1,%2,%3};"
        : "+f"(d[0]), "+f"(d[1]), "+f"(d[2]), "+f"(d[3])
        : "r"(a[0]), "r"(a[1]), "r"(a[2]), "r"(a[3]), "r"(b[0]), "r"(b[1]));
}
__device__ __forceinline__ void cpa16(uint32_t s, const void* g){
    asm volatile("cp.async.ca.shared.global [%0], [%1], 16;" :: "r"(s), "l"(g));
}
#define CP_COMMIT() asm volatile("cp.async.commit_group;" ::: "memory")
#define CP_WAIT(n)  asm volatile("cp.async.wait_group %0;" :: "n"(n) : "memory")

__device__ __forceinline__ void split4(float4 f, uint2& H, uint2& L){
    __nv_bfloat16 hx = __float2bfloat16(f.x);
    __nv_bfloat16 hy = __float2bfloat16(f.y);
    __nv_bfloat16 hz = __float2bfloat16(f.z);
    __nv_bfloat16 hw = __float2bfloat16(f.w);
    float lx = f.x - __bfloat162float(hx);
    float ly = f.y - __bfloat162float(hy);
    float lz = f.z - __bfloat162float(hz);
    float lw = f.w - __bfloat162float(hw);
    union { __nv_bfloat162 h2[2]; uint2 u; } A, B;
    A.h2[0] = __halves2bfloat162(hx, hy);
    A.h2[1] = __halves2bfloat162(hz, hw);
    B.h2[0] = __floats2bfloat162_rn(lx, ly);
    B.h2[1] = __floats2bfloat162_rn(lz, lw);
    H = A.u; L = B.u;
}
__device__ __forceinline__ void splitp(float a, float b, uint32_t& H, uint32_t& L){
    __nv_bfloat16 ha = __float2bfloat16(a);
    __nv_bfloat16 hb = __float2bfloat16(b);
    float la = a - __bfloat162float(ha);
    float lb = b - __bfloat162float(hb);
    union { __nv_bfloat162 h; uint32_t u; } X, Y;
    X.h = __halves2bfloat162(ha, hb);
    Y.h = __floats2bfloat162_rn(la, lb);
    H = X.u; L = Y.u;
}

// ============================================================================
// Prep kernels
// ============================================================================
__global__ void split_sel(const float* __restrict__ src, int sel, int valid_rows, int total_rows)
{
    __nv_bfloat16 *h, *l;
    switch (sel) {
        case 0: h = g_Xh;  l = g_Xl;  break;
        case 1: h = g_Wqh; l = g_Wql; break;
        case 2: h = g_Wkh; l = g_Wkl; break;
        case 3: h = g_Wvh; l = g_Wvl; break;
        default: h = g_Woh; l = g_Wol; break;
    }
    size_t i4 = (size_t)blockIdx.x * blockDim.x + threadIdx.x;
    size_t tot = (size_t)total_rows * EE / 4;
    if (i4 >= tot) return;
    int row = (int)(i4 * 4 / EE);
    float4 f = (row < valid_rows) ? *(const float4*)(src + i4*4) : make_float4(0.f,0.f,0.f,0.f);
    uint2 H, L;
    split4(f, H, L);
    *(uint2*)(h + i4*4) = H;
    *(uint2*)(l + i4*4) = L;
}

__global__ void zero_pad_qkv()
{
    int idx = blockIdx.x * blockDim.x + threadIdx.x;
    const int tot = NB*NH*(TP-TT)*DH;
    if (idx >= tot) return;
    int d = idx & 63;
    int r = idx >> 6;
    int t = TT + (r % (TP-TT));
    int head = r / (TP-TT);
    size_t off = ((size_t)head * TP + t) * DH + d;
    __nv_bfloat16 z = __float2bfloat16(0.f);
    g_qh[off]=z; g_ql[off]=z; g_kh[off]=z; g_kl[off]=z; g_vh[off]=z; g_vl[off]=z;
}

__global__ void zero_pad_ctx()
{
    int idx = blockIdx.x * blockDim.x + threadIdx.x;
    const int tot = (MRP-MR)*EE;
    if (idx >= tot) return;
    size_t off = (size_t)MR*EE + idx;
    __nv_bfloat16 z = __float2bfloat16(0.f);
    g_cth[off] = z; g_ctl[off] = z;
}

// ============================================================================
// GEMM main loop: pre-split bf16 operands, cp.async 2-stage pipeline with
// prefetch-after-sync (R13-attention-proven ordering), BK=32 (40 chunks).
// acc(128x128) += A[arow0:+128,:] @ B[brow0:+128,:]^T. 256 thr, warp 64x32.
// ============================================================================
__device__ __forceinline__ void mm_loop_bf(
    const __nv_bfloat16* __restrict__ Ah_, const __nv_bfloat16* __restrict__ Al_,
    const __nv_bfloat16* __restrict__ Bh_, const __nv_bfloat16* __restrict__ Bl_,
    int arow0, int brow0, uint32_t smb, float acc[4][4][4])
{
    const int tid  = threadIdx.x;
    const int lane = tid & 31;
    const int wid  = tid >> 5;
    const int warp_m = wid >> 2;   // 0..1
    const int warp_n = wid & 3;    // 0..3

    // cp.async mapping: per tile each thread copies rows r0 and r0+64, 16B at col c0
    const int r0 = tid >> 2;             // 0..63
    const int c0 = (tid & 3) * 8;        // element offset (8 bf16 = 16B)
    const __nv_bfloat16* gAh0 = Ah_ + (size_t)(arow0 + r0)      * EE + c0;
    const __nv_bfloat16* gAh1 = Ah_ + (size_t)(arow0 + r0 + 64) * EE + c0;
    const __nv_bfloat16* gAl0 = Al_ + (size_t)(arow0 + r0)      * EE + c0;
    const __nv_bfloat16* gAl1 = Al_ + (size_t)(arow0 + r0 + 64) * EE + c0;
    const __nv_bfloat16* gBh0 = Bh_ + (size_t)(brow0 + r0)      * EE + c0;
    const __nv_bfloat16* gBh1 = Bh_ + (size_t)(brow0 + r0 + 64) * EE + c0;
    const __nv_bfloat16* gBl0 = Bl_ + (size_t)(brow0 + r0)      * EE + c0;
    const __nv_bfloat16* gBl1 = Bl_ + (size_t)(brow0 + r0 + 64) * EE + c0;
    const uint32_t sd0 = smb + (uint32_t)r0 * RS + c0 * 2;          // row r0
    const uint32_t sd1 = smb + (uint32_t)(r0 + 64) * RS + c0 * 2;   // row r0+64

    const uint32_t a_rd = smb + (uint32_t)(warp_m*64 + (lane & 15)) * RS + (lane >> 4) * 16;
    const uint32_t b_rd = smb + 2*TSZ + (uint32_t)(warp_n*32 + (lane & 7)) * RS + ((lane >> 3) & 1) * 16;

    // issue chunk 0 into stage 0
    {
        cpa16(sd0,           gAh0); cpa16(sd1,           gAh1);
        cpa16(sd0 + TSZ,     gAl0); cpa16(sd1 + TSZ,     gAl1);
        cpa16(sd0 + 2*TSZ,   gBh0); cpa16(sd1 + 2*TSZ,   gBh1);
        cpa16(sd0 + 3*TSZ,   gBl0); cpa16(sd1 + 3*TSZ,   gBl1);
        CP_COMMIT();
    }

    #pragma unroll 1
    for (int i = 0; i < NCH; i++) {
        CP_WAIT(0);        // chunk i (our copies) landed
        __syncthreads();   // all threads' copies visible; compute i-1 done by all

        // prefetch chunk i+1 into the other stage (overlaps compute below)
        if (i + 1 < NCH) {
            const int ko = (i + 1) * BK;
            const uint32_t so = ((i + 1) & 1) * STG;
            cpa16(sd0 + so,           gAh0 + ko); cpa16(sd1 + so,           gAh1 + ko);
            cpa16(sd0 + so + TSZ,     gAl0 + ko); cpa16(sd1 + so + TSZ,     gAl1 + ko);
            cpa16(sd0 + so + 2*TSZ,   gBh0 + ko); cpa16(sd1 + so + 2*TSZ,   gBh1 + ko);
            cpa16(sd0 + so + 3*TSZ,   gBl0 + ko); cpa16(sd1 + so + 3*TSZ,   gBl1 + ko);
            CP_COMMIT();
        }

        const uint32_t soff = (uint32_t)(i & 1) * STG;
        #pragma unroll
        for (int kk = 0; kk < 2; kk++) {
            const uint32_t koff = soff + kk*32;
            uint32_t bh[4][2], bl[4][2];
            #pragma unroll
            for (int nt = 0; nt < 4; nt++) {
                ldx2(bh[nt], b_rd + koff + nt*8*RS);
                ldx2(bl[nt], b_rd + koff + nt*8*RS + TSZ);
            }
            #pragma unroll
            for (int mt = 0; mt < 4; mt++) {
                uint32_t ah[4], al[4];
                ldx4(ah, a_rd + koff + mt*16*RS);
                ldx4(al, a_rd + koff + mt*16*RS + TSZ);
                #pragma unroll
                for (int nt = 0; nt < 4; nt++) {
                    mma_bf16(acc[mt][nt], ah, bh[nt]);
                    mma_bf16(acc[mt][nt], ah, bl[nt]);
                    mma_bf16(acc[mt][nt], al, bh[nt]);
                }
            }
        }
        // no trailing sync: next iteration's sync separates compute i from the
        // prefetch that overwrites stage (i&1) at iteration i+1.
    }
}

// ============================================================================
// QKV GEMM: grid (30, 47), 256 threads. Epilogue writes pre-split bf16 q/k/v.
// ============================================================================
__global__ __launch_bounds__(256, 2) void qkv_mm(
    const float* __restrict__ bq, const float* __restrict__ bv)
{
    extern __shared__ char sm[];
    uint32_t smb = smem_u32(sm);
    const int tid = threadIdx.x;
    const int lane = tid & 31;
    const int wid = tid >> 5;
    const int warp_m = wid >> 2, warp_n = wid & 3;

    const int which = blockIdx.x / 10;
    const int wcol0 = (blockIdx.x - which*10) * 128;
    const int row0  = blockIdx.y * 128;

    const __nv_bfloat16 *Bh, *Bl;
    __nv_bfloat16 *dh, *dl;
    const float* bias;
    float scl;
    if (which == 0)      { Bh=g_Wqh; Bl=g_Wql; dh=g_qh; dl=g_ql; bias=bq;      scl=QKSCALE; }
    else if (which == 1) { Bh=g_Wkh; Bl=g_Wkl; dh=g_kh; dl=g_kl; bias=nullptr; scl=1.0f; }
    else                 { Bh=g_Wvh; Bl=g_Wvl; dh=g_vh; dl=g_vl; bias=bv;      scl=1.0f; }

    float acc[4][4][4];
    #pragma unroll
    for (int mt = 0; mt < 4; mt++)
        #pragma unroll
        for (int nt = 0; nt < 4; nt++)
            #pragma unroll
            for (int j = 0; j < 4; j++) acc[mt][nt][j] = 0.f;

    mm_loop_bf(g_Xh, g_Xl, Bh, Bl, row0, wcol0, smb, acc);

    const int g = lane >> 2, t4 = lane & 3;
    #pragma unroll
    for (int mt = 0; mt < 4; mt++) {
        #pragma unroll
        for (int nt = 0; nt < 4; nt++) {
            int col = wcol0 + warp_n*32 + nt*8 + 2*t4;
            float2 bb = bias ? *(const float2*)(bias + col) : make_float2(0.f, 0.f);
            int h = col >> 6, d = col & 63;
            int r0w = row0 + warp_m*64 + mt*16 + g;
            if (r0w < MR) {
                int b_ = r0w / TT, t_ = r0w - b_*TT;
                size_t base = ((size_t)(b_*NH + h) * TP + t_) * DH + d;
                uint32_t H, L;
                splitp((acc[mt][nt][0] + bb.x)*scl, (acc[mt][nt][1] + bb.y)*scl, H, L);
                *(uint32_t*)(dh + base) = H;
                *(uint32_t*)(dl + base) = L;
            }
            int r1w = r0w + 8;
            if (r1w < MR) {
                int b_ = r1w / TT, t_ = r1w - b_*TT;
                size_t base = ((size_t)(b_*NH + h) * TP + t_) * DH + d;
                uint32_t H, L;
                splitp((acc[mt][nt][2] + bb.x)*scl, (acc[mt][nt][3] + bb.y)*scl, H, L);
                *(uint32_t*)(dh + base) = H;
                *(uint32_t*)(dl + base) = L;
            }
        }
    }
}

// ============================================================================
// Output projection: out = ctx @ Wo^T + bo. grid (10, 47), 256 threads.
// ============================================================================
__global__ __launch_bounds__(256, 2) void out_mm(
    const float* __restrict__ bo, float* __restrict__ out)
{
    extern __shared__ char sm[];
    uint32_t smb = smem_u32(sm);
    const int tid = threadIdx.x;
    const int lane = tid & 31;
    const int wid = tid >> 5;
    const int warp_m = wid >> 2, warp_n = wid & 3;
    const int col0 = blockIdx.x * 128;
    const int row0 = blockIdx.y * 128;

    float acc[4][4][4];
    #pragma unroll
    for (int mt = 0; mt < 4; mt++)
        #pragma unroll
        for (int nt = 0; nt < 4; nt++)
            #pragma unroll
            for (int j = 0; j < 4; j++) acc[mt][nt][j] = 0.f;

    mm_loop_bf(g_cth, g_ctl, g_Woh, g_Wol, row0, col0, smb, acc);

    const int g = lane >> 2, t4 = lane & 3;
    #pragma unroll
    for (int mt = 0; mt < 4; mt++) {
        #pragma unroll
        for (int nt = 0; nt < 4; nt++) {
            int col = col0 + warp_n*32 + nt*8 + 2*t4;
            float2 bb = *(const float2*)(bo + col);
            int r0w = row0 + warp_m*64 + mt*16 + g;
            if (r0w < MR) {
                float2 v = make_float2(acc[mt][nt][0] + bb.x, acc[mt][nt][1] + bb.y);
                *(float2*)(out + (size_t)r0w*EE + col) = v;
            }
            int r1w = r0w + 8;
            if (r1w < MR) {
                float2 v = make_float2(acc[mt][nt][2] + bb.x, acc[mt][nt][3] + bb.y);
                *(float2*)(out + (size_t)r1w*EE + col) = v;
            }
        }
    }
}

// ============================================================================
// Flash attention (R13-proven loop): pre-split bf16 q/k/v, double-buffered K/V.
// Epilogue writes pre-split bf16 ctx for out_mm.
// Grid (24, 80), 128 threads (4 warps, 16 q-rows each).
// ============================================================================
__global__ __launch_bounds__(128) void attn_kernel()
{
    extern __shared__ char sm[];
    uint32_t smb = smem_u32(sm);

    const int tid = threadIdx.x;
    const int lane = tid & 31;
    const int wid = tid >> 5;
    const int g  = lane >> 2;
    const int t4 = lane & 3;

    const int bhidx = blockIdx.y;
    const int b_ = bhidx / NH;
    const int h_ = bhidx - b_ * NH;
    const size_t hb = (size_t)bhidx * TP * DH;
    const int q0 = blockIdx.x * 64;

    // ---- Q staging into stage-0 (SKH/SKL areas), then fragments ----
    #pragma unroll
    for (int j = 0; j < 4; j++) {
        int seg = tid + 128*j;
        int row = seg >> 3;
        int o8  = (seg & 7) * 8;
        size_t go = hb + (size_t)(q0 + row) * DH + o8;
        uint32_t so = (uint32_t)row * ATS + o8*2;
        cpa16(smb + SKH + so, g_qh + go);
        cpa16(smb + SKL + so, g_ql + go);
    }
    CP_COMMIT(); CP_WAIT(0);
    __syncthreads();

    uint32_t qh[4][4], ql[4][4];
    {
        uint32_t qa = smb + (uint32_t)(wid*16 + (lane & 15)) * ATS + (lane >> 4) * 16;
        #pragma unroll
        for (int kc = 0; kc < 4; kc++) {
            ldx4(qh[kc], qa + SKH + kc*32);
            ldx4(ql[kc], qa + SKL + kc*32);
        }
    }
    __syncthreads();   // everyone done reading Q staging before tile-0 overwrite

    float m0 = -1e30f, m1 = -1e30f, l0 = 0.f, l1 = 0.f;
    float o[8][4];
    #pragma unroll
    for (int nt = 0; nt < 8; nt++)
        #pragma unroll
        for (int j = 0; j < 4; j++) o[nt][j] = 0.f;

    // ---- issue K/V tile 0 into stage 0 ----
    #pragma unroll
    for (int j = 0; j < 4; j++) {
        int seg = tid + 128*j;
        int row = seg >> 3;
        int o8  = (seg & 7) * 8;
        size_t go = hb + (size_t)row * DH + o8;
        uint32_t so = (uint32_t)row * ATS + o8*2;
        cpa16(smb + SKH + so, g_kh + go);
        cpa16(smb + SKL + so, g_kl + go);
        cpa16(smb + SVH + so, g_vh + go);
        cpa16(smb + SVL + so, g_vl + go);
    }
    CP_COMMIT();

    #pragma unroll 1
    for (int kt = 0; kt < 24; kt++) {
        const int k0 = kt * 64;
        CP_WAIT(0);
        __syncthreads();

        // prefetch next tile into the other stage
        if (kt + 1 < 24) {
            const int k1 = (kt + 1) * 64;
            const uint32_t stN = smb + ((kt + 1) & 1) * AST;
            #pragma unroll
            for (int j = 0; j < 4; j++) {
                int seg = tid + 128*j;
                int row = seg >> 3;
                int o8  = (seg & 7) * 8;
                size_t go = hb + (size_t)(k1 + row) * DH + o8;
                uint32_t so = (uint32_t)row * ATS + o8*2;
                cpa16(stN + SKH + so, g_kh + go);
                cpa16(stN + SKL + so, g_kl + go);
                cpa16(stN + SVH + so, g_vh + go);
                cpa16(stN + SVL + so, g_vl + go);
            }
            CP_COMMIT();
        }

        const uint32_t st = smb + (kt & 1) * AST;
        const uint32_t k_rd = st + (uint32_t)(lane & 7) * ATS + ((lane >> 3) & 1) * 16;
        const uint32_t v_rd = st + (uint32_t)(lane & 15) * ATS;

        // ---- S = Q K^T (3-term split) ----
        float s[8][4];
        #pragma unroll
        for (int nt = 0; nt < 8; nt++)
            #pragma unroll
            for (int j = 0; j < 4; j++) s[nt][j] = 0.f;

        #pragma unroll
        for (int nt = 0; nt < 8; nt++) {
            uint32_t kbase = k_rd + (uint32_t)nt*8*ATS;
            #pragma unroll
            for (int kc = 0; kc < 4; kc++) {
                uint32_t kh2[2], kl2[2];
                ldx2(kh2, kbase + SKH + kc*32);
                ldx2(kl2, kbase + SKL + kc*32);
                mma_bf16(s[nt], qh[kc], kh2);
                mma_bf16(s[nt], qh[kc], kl2);
                mma_bf16(s[nt], ql[kc], kh2);
            }
        }

        if (k0 + 64 > TT) {
            #pragma unroll
            for (int nt = 0; nt < 8; nt++) {
                int col = k0 + nt*8 + 2*t4;
                if (col   >= TT) { s[nt][0] = -1e30f; s[nt][2] = -1e30f; }
                if (col+1 >= TT) { s[nt][1] = -1e30f; s[nt][3] = -1e30f; }
            }
        }

        // ---- online softmax ----
        float mx0 = -1e30f, mx1 = -1e30f;
        #pragma unroll
        for (int nt = 0; nt < 8; nt++) {
            mx0 = fmaxf(mx0, fmaxf(s[nt][0], s[nt][1]));
            mx1 = fmaxf(mx1, fmaxf(s[nt][2], s[nt][3]));
        }
        mx0 = fmaxf(mx0, __shfl_xor_sync(0xffffffffu, mx0, 1));
        mx0 = fmaxf(mx0, __shfl_xor_sync(0xffffffffu, mx0, 2));
        mx1 = fmaxf(mx1, __shfl_xor_sync(0xffffffffu, mx1, 1));
        mx1 = fmaxf(mx1, __shfl_xor_sync(0xffffffffu, mx1, 2));

        float mn0 = fmaxf(m0, mx0), mn1 = fmaxf(m1, mx1);
        float al0 = __expf(m0 - mn0), al1 = __expf(m1 - mn1);
        m0 = mn0; m1 = mn1;

        float sum0 = 0.f, sum1 = 0.f;
        #pragma unroll
        for (int nt = 0; nt < 8; nt++) {
            s[nt][0] = __expf(s[nt][0] - mn0); sum0 += s[nt][0];
            s[nt][1] = __expf(s[nt][1] - mn0); sum0 += s[nt][1];
            s[nt][2] = __expf(s[nt][2] - mn1); sum1 += s[nt][2];
            s[nt][3] = __expf(s[nt][3] - mn1); sum1 += s[nt][3];
        }
        sum0 += __shfl_xor_sync(0xffffffffu, sum0, 1);
        sum0 += __shfl_xor_sync(0xffffffffu, sum0, 2);
        sum1 += __shfl_xor_sync(0xffffffffu, sum1, 1);
        sum1 += __shfl_xor_sync(0xffffffffu, sum1, 2);
        l0 = l0 * al0 + sum0;
        l1 = l1 * al1 + sum1;

        #pragma unroll
        for (int nt = 0; nt < 8; nt++) {
            o[nt][0] *= al0; o[nt][1] *= al0;
            o[nt][2] *= al1; o[nt][3] *= al1;
        }

        // ---- O += P V ----
        #pragma unroll
        for (int kc = 0; kc < 4; kc++) {
            uint32_t ah[4], al_[4];
            splitp(s[2*kc][0],   s[2*kc][1],   ah[0], al_[0]);
            splitp(s[2*kc][2],   s[2*kc][3],   ah[1], al_[1]);
            splitp(s[2*kc+1][0], s[2*kc+1][1], ah[2], al_[2]);
            splitp(s[2*kc+1][2], s[2*kc+1][3], ah[3], al_[3]);
            uint32_t vbase = v_rd + (uint32_t)kc*16*ATS;
            #pragma unroll
            for (int nt = 0; nt < 8; nt++) {
                uint32_t vh2[2], vl2[2];
                ldx2t(vh2, vbase + SVH + nt*16);
                ldx2t(vl2, vbase + SVL + nt*16);
                mma_bf16(o[nt], ah,  vh2);
                mma_bf16(o[nt], ah,  vl2);
                mma_bf16(o[nt], al_, vh2);
            }
        }
    }

    // ---- epilogue: normalize, split, write pre-split bf16 ctx ----
    float inv0 = 1.0f / l0, inv1 = 1.0f / l1;
    int r0w = q0 + wid*16 + g;
    int r1w = r0w + 8;
    #pragma unroll
    for (int nt = 0; nt < 8; nt++) {
        int d = nt*8 + 2*t4;
        if (r0w < TT) {
            size_t base = (size_t)(b_ * TT + r0w) * EE + h_ * DH + d;
            uint32_t H, L;
            splitp(o[nt][0]*inv0, o[nt][1]*inv0, H, L);
            *(uint32_t*)(g_cth + base) = H;
            *(uint32_t*)(g_ctl + base) = L;
        }
        if (r1w < TT) {
            size_t base = (size_t)(b_ * TT + r1w) * EE + h_ * DH + d;
            uint32_t H, L;
            splitp(o[nt][2]*inv1, o[nt][3]*inv1, H, L);
            *(uint32_t*)(g_cth + base) = H;
            *(uint32_t*)(g_ctl + base) = L;
        }
    }
}

extern "C" void kernel_launch(void* const* d_in, const int* in_sizes, int n_in,
                              void* d_out, int out_size)
{
    const float* X  = (const float*)d_in[0];
    const float* Wq = (const float*)d_in[1];
    const float* bq = (const float*)d_in[2];
    const float* Wk = (const float*)d_in[3];
    const float* Wv = (const float*)d_in[4];
    const float* bv = (const float*)d_in[5];
    const float* Wo = (const float*)d_in[6];
    const float* bo = (const float*)d_in[7];
    float* out = (float*)d_out;

    cudaFuncSetAttribute(qkv_mm, cudaFuncAttributeMaxDynamicSharedMemorySize, GSM);
    cudaFuncSetAttribute(out_mm, cudaFuncAttributeMaxDynamicSharedMemorySize, GSM);
    cudaFuncSetAttribute(attn_kernel, cudaFuncAttributeMaxDynamicSharedMemorySize, ASMEM);

    // prep: pre-split inputs + zero pads
    split_sel<<<(MRP*EE/4 + 255)/256, 256>>>(X, 0, MR, MRP);
    split_sel<<<(EE*EE/4 + 255)/256, 256>>>(Wq, 1, EE, EE);
    split_sel<<<(EE*EE/4 + 255)/256, 256>>>(Wk, 2, EE, EE);
    split_sel<<<(EE*EE/4 + 255)/256, 256>>>(Wv, 3, EE, EE);
    split_sel<<<(EE*EE/4 + 255)/256, 256>>>(Wo, 4, EE, EE);
    zero_pad_qkv<<<(NB*NH*(TP-TT)*DH + 255)/256, 256>>>();
    zero_pad_ctx<<<((MRP-MR)*EE + 255)/256, 256>>>();

    dim3 g1(30, 47);
    qkv_mm<<<g1, 256, GSM>>>(bq, bv);

    dim3 g2(24, NB * NH);
    attn_kernel<<<g2, 128, ASMEM>>>();

    dim3 g3(10, 47);
    out_mm<<<g3, 256, GSM>>>(bo, out);
}

// round 15
// speedup vs baseline: 1.7807x; 1.0293x over previous
#include <cuda_runtime.h>
#include <cuda_bf16.h>
#include <cstdint>

// Problem constants
#define NB 4
#define TT 1500
#define TP 1536
#define EE 1280
#define NH 20
#define DH 64
#define MR (NB*TT)         // 6000
#define MRP 6016
#define QKSCALE 0.125f
#define LOG2E 1.44269504088896f

// GEMM tiling: CTA 128x128, 8 warps (2x4), warp tile 64x32, k-chunk 32, cp.async feed
#define BK 32
#define NCH (EE/BK)         // 40
#define RS 80
#define TSZ (128*RS)        // 10240
#define STG (4*TSZ)         // 40960
#define GSM (2*STG)         // 81920

// Attention smem: 2 stages x 4 tiles (KH,KL,VH,VL) of 64x64 bf16, 144B stride
#define ATS 144
#define ATILE (64*ATS)
#define SKH 0
#define SKL ATILE
#define SVH (2*ATILE)
#define SVL (3*ATILE)
#define AST (4*ATILE)
#define ASMEM (2*AST)       // 73728

// ---- pre-split bf16 global buffers ----
static __device__ __align__(16) __nv_bfloat16 g_Xh[(size_t)MRP*EE], g_Xl[(size_t)MRP*EE];
static __device__ __align__(16) __nv_bfloat16 g_Wqh[(size_t)EE*EE], g_Wql[(size_t)EE*EE];
static __device__ __align__(16) __nv_bfloat16 g_Wkh[(size_t)EE*EE], g_Wkl[(size_t)EE*EE];
static __device__ __align__(16) __nv_bfloat16 g_Wvh[(size_t)EE*EE], g_Wvl[(size_t)EE*EE];
static __device__ __align__(16) __nv_bfloat16 g_Woh[(size_t)EE*EE], g_Wol[(size_t)EE*EE];
static __device__ __align__(16) __nv_bfloat16 g_qh[(size_t)NB*NH*TP*DH], g_ql[(size_t)NB*NH*TP*DH];
static __device__ __align__(16) __nv_bfloat16 g_kh[(size_t)NB*NH*TP*DH], g_kl[(size_t)NB*NH*TP*DH];
static __device__ __align__(16) __nv_bfloat16 g_vh[(size_t)NB*NH*TP*DH], g_vl[(size_t)NB*NH*TP*DH];
static __device__ __align__(16) __nv_bfloat16 g_cth[(size_t)MRP*EE], g_ctl[(size_t)MRP*EE];

// ---------------- helpers ----------------
__device__ __forceinline__ uint32_t smem_u32(const void* p){
    uint32_t a;
    asm("{ .reg .u64 t; cvta.to.shared.u64 t, %1; cvt.u32.u64 %0, t; }" : "=r"(a) : "l"(p));
    return a;
}
__device__ __forceinline__ void ldx4(uint32_t* r, uint32_t addr){
    asm volatile("ldmatrix.sync.aligned.m8n8.x4.shared.b16 {%0,%1,%2,%3}, [%4];"
        : "=r"(r[0]), "=r"(r[1]), "=r"(r[2]), "=r"(r[3]) : "r"(addr));
}
__device__ __forceinline__ void ldx2(uint32_t* r, uint32_t addr){
    asm volatile("ldmatrix.sync.aligned.m8n8.x2.shared.b16 {%0,%1}, [%2];"
        : "=r"(r[0]), "=r"(r[1]) : "r"(addr));
}
__device__ __forceinline__ void ldx2t(uint32_t* r, uint32_t addr){
    asm volatile("ldmatrix.sync.aligned.m8n8.x2.trans.shared.b16 {%0,%1}, [%2];"
        : "=r"(r[0]), "=r"(r[1]) : "r"(addr));
}
__device__ __forceinline__ void mma_bf16(float* d, const uint32_t* a, const uint32_t* b){
    asm volatile(
        "mma.sync.aligned.m16n8k16.row.col.f32.bf16.bf16.f32 "
        "{%0,%1,%2,%3}, {%4,%5,%6,%7}, {%8,%9}, {%0,%1,%2,%3};"
        : "+f"(d[0]), "+f"(d[1]), "+f"(d[2]), "+f"(d[3])
        : "r"(a[0]), "r"(a[1]), "r"(a[2]), "r"(a[3]), "r"(b[0]), "r"(b[1]));
}
__device__ __forceinline__ void cpa16(uint32_t s, const void* g){
    asm volatile("cp.async.ca.shared.global [%0], [%1], 16;" :: "r"(s), "l"(g));
}
#define CP_COMMIT() asm volatile("cp.async.commit_group;" ::: "memory")
#define CP_WAIT(n)  asm volatile("cp.async.wait_group %0;" :: "n"(n) : "memory")

__device__ __forceinline__ void split4(float4 f, uint2& H, uint2& L){
    __nv_bfloat16 hx = __float2bfloat16(f.x);
    __nv_bfloat16 hy = __float2bfloat16(f.y);
    __nv_bfloat16 hz = __float2bfloat16(f.z);
    __nv_bfloat16 hw = __float2bfloat16(f.w);
    float lx = f.x - __bfloat162float(hx);
    float ly = f.y - __bfloat162float(hy);
    float lz = f.z - __bfloat162float(hz);
    float lw = f.w - __bfloat162float(hw);
    union { __nv_bfloat162 h2[2]; uint2 u; } A, B;
    A.h2[0] = __halves2bfloat162(hx, hy);
    A.h2[1] = __halves2bfloat162(hz, hw);
    B.h2[0] = __floats2bfloat162_rn(lx, ly);
    B.h2[1] = __floats2bfloat162_rn(lz, lw);
    H = A.u; L = B.u;
}
__device__ __forceinline__ void splitp(float a, float b, uint32_t& H, uint32_t& L){
    __nv_bfloat16 ha = __float2bfloat16(a);
    __nv_bfloat16 hb = __float2bfloat16(b);
    float la = a - __bfloat162float(ha);
    float lb = b - __bfloat162float(hb);
    union { __nv_bfloat162 h; uint32_t u; } X, Y;
    X.h = __halves2bfloat162(ha, hb);
    Y.h = __floats2bfloat162_rn(la, lb);
    H = X.u; L = Y.u;
}

// ============================================================================
// Fused prep: split X + 4 weights into bf16 hi/lo in one launch.
// ============================================================================
__global__ void prep_all(const float* __restrict__ X,
                         const float* __restrict__ Wq, const float* __restrict__ Wk,
                         const float* __restrict__ Wv, const float* __restrict__ Wo)
{
    const size_t NX = (size_t)MRP*EE/4;
    const size_t NW = (size_t)EE*EE/4;
    size_t i = (size_t)blockIdx.x * blockDim.x + threadIdx.x;
    const float* src;
    __nv_bfloat16 *h, *l;
    size_t j;
    bool pad = false;
    if (i < NX) {
        j = i; src = X; h = g_Xh; l = g_Xl;
        int row = (int)(j * 4 / EE);
        pad = (row >= MR);
    } else {
        i -= NX;
        int w = (int)(i / NW);
        j = i - (size_t)w * NW;
        if (i >= 4*NW) return;
        switch (w) {
            case 0: src = Wq; h = g_Wqh; l = g_Wql; break;
            case 1: src = Wk; h = g_Wkh; l = g_Wkl; break;
            case 2: src = Wv; h = g_Wvh; l = g_Wvl; break;
            default: src = Wo; h = g_Woh; l = g_Wol; break;
        }
    }
    float4 f = pad ? make_float4(0.f,0.f,0.f,0.f) : *(const float4*)(src + j*4);
    uint2 H, L;
    split4(f, H, L);
    *(uint2*)(h + j*4) = H;
    *(uint2*)(l + j*4) = L;
}

__global__ void zero_pad_qkv()
{
    int idx = blockIdx.x * blockDim.x + threadIdx.x;
    const int tot = NB*NH*(TP-TT)*DH;
    if (idx >= tot) return;
    int d = idx & 63;
    int r = idx >> 6;
    int t = TT + (r % (TP-TT));
    int head = r / (TP-TT);
    size_t off = ((size_t)head * TP + t) * DH + d;
    __nv_bfloat16 z = __float2bfloat16(0.f);
    g_qh[off]=z; g_ql[off]=z; g_kh[off]=z; g_kl[off]=z; g_vh[off]=z; g_vl[off]=z;
}

__global__ void zero_pad_ctx()
{
    int idx = blockIdx.x * blockDim.x + threadIdx.x;
    const int tot = (MRP-MR)*EE;
    if (idx >= tot) return;
    size_t off = (size_t)MR*EE + idx;
    __nv_bfloat16 z = __float2bfloat16(0.f);
    g_cth[off] = z; g_ctl[off] = z;
}

// ============================================================================
// GEMM main loop (R14 pipeline + term-major MMA reorder; per-accumulator
// addition order unchanged → bitwise identical results).
// ============================================================================
__device__ __forceinline__ void mm_loop_bf(
    const __nv_bfloat16* __restrict__ Ah_, const __nv_bfloat16* __restrict__ Al_,
    const __nv_bfloat16* __restrict__ Bh_, const __nv_bfloat16* __restrict__ Bl_,
    int arow0, int brow0, uint32_t smb, float acc[4][4][4])
{
    const int tid  = threadIdx.x;
    const int lane = tid & 31;
    const int wid  = tid >> 5;
    const int warp_m = wid >> 2;
    const int warp_n = wid & 3;

    const int r0 = tid >> 2;
    const int c0 = (tid & 3) * 8;
    const __nv_bfloat16* gAh0 = Ah_ + (size_t)(arow0 + r0)      * EE + c0;
    const __nv_bfloat16* gAh1 = Ah_ + (size_t)(arow0 + r0 + 64) * EE + c0;
    const __nv_bfloat16* gAl0 = Al_ + (size_t)(arow0 + r0)      * EE + c0;
    const __nv_bfloat16* gAl1 = Al_ + (size_t)(arow0 + r0 + 64) * EE + c0;
    const __nv_bfloat16* gBh0 = Bh_ + (size_t)(brow0 + r0)      * EE + c0;
    const __nv_bfloat16* gBh1 = Bh_ + (size_t)(brow0 + r0 + 64) * EE + c0;
    const __nv_bfloat16* gBl0 = Bl_ + (size_t)(brow0 + r0)      * EE + c0;
    const __nv_bfloat16* gBl1 = Bl_ + (size_t)(brow0 + r0 + 64) * EE + c0;
    const uint32_t sd0 = smb + (uint32_t)r0 * RS + c0 * 2;
    const uint32_t sd1 = smb + (uint32_t)(r0 + 64) * RS + c0 * 2;

    const uint32_t a_rd = smb + (uint32_t)(warp_m*64 + (lane & 15)) * RS + (lane >> 4) * 16;
    const uint32_t b_rd = smb + 2*TSZ + (uint32_t)(warp_n*32 + (lane & 7)) * RS + ((lane >> 3) & 1) * 16;

    // issue chunk 0 into stage 0
    cpa16(sd0,           gAh0); cpa16(sd1,           gAh1);
    cpa16(sd0 + TSZ,     gAl0); cpa16(sd1 + TSZ,     gAl1);
    cpa16(sd0 + 2*TSZ,   gBh0); cpa16(sd1 + 2*TSZ,   gBh1);
    cpa16(sd0 + 3*TSZ,   gBl0); cpa16(sd1 + 3*TSZ,   gBl1);
    CP_COMMIT();

    #pragma unroll 1
    for (int i = 0; i < NCH; i++) {
        CP_WAIT(0);
        __syncthreads();

        if (i + 1 < NCH) {
            const int ko = (i + 1) * BK;
            const uint32_t so = ((i + 1) & 1) * STG;
            cpa16(sd0 + so,           gAh0 + ko); cpa16(sd1 + so,           gAh1 + ko);
            cpa16(sd0 + so + TSZ,     gAl0 + ko); cpa16(sd1 + so + TSZ,     gAl1 + ko);
            cpa16(sd0 + so + 2*TSZ,   gBh0 + ko); cpa16(sd1 + so + 2*TSZ,   gBh1 + ko);
            cpa16(sd0 + so + 3*TSZ,   gBl0 + ko); cpa16(sd1 + so + 3*TSZ,   gBl1 + ko);
            CP_COMMIT();
        }

        const uint32_t soff = (uint32_t)(i & 1) * STG;
        #pragma unroll
        for (int kk = 0; kk < 2; kk++) {
            const uint32_t koff = soff + kk*32;
            uint32_t bh[4][2], bl[4][2];
            #pragma unroll
            for (int nt = 0; nt < 4; nt++) {
                ldx2(bh[nt], b_rd + koff + nt*8*RS);
                ldx2(bl[nt], b_rd + koff + nt*8*RS + TSZ);
            }
            #pragma unroll
            for (int mt = 0; mt < 4; mt++) {
                uint32_t ah[4], al[4];
                ldx4(ah, a_rd + koff + mt*16*RS);
                ldx4(al, a_rd + koff + mt*16*RS + TSZ);
                // term-major: independent accumulators between reuses
                #pragma unroll
                for (int nt = 0; nt < 4; nt++) mma_bf16(acc[mt][nt], ah, bh[nt]);
                #pragma unroll
                for (int nt = 0; nt < 4; nt++) mma_bf16(acc[mt][nt], ah, bl[nt]);
                #pragma unroll
                for (int nt = 0; nt < 4; nt++) mma_bf16(acc[mt][nt], al, bh[nt]);
            }
        }
    }
}

// ============================================================================
// QKV GEMM: grid (30, 47), 256 threads. q pre-scaled by QKSCALE*log2(e).
// ============================================================================
__global__ __launch_bounds__(256, 2) void qkv_mm(
    const float* __restrict__ bq, const float* __restrict__ bv)
{
    extern __shared__ char sm[];
    uint32_t smb = smem_u32(sm);
    const int tid = threadIdx.x;
    const int lane = tid & 31;
    const int wid = tid >> 5;
    const int warp_m = wid >> 2, warp_n = wid & 3;

    const int which = blockIdx.x / 10;
    const int wcol0 = (blockIdx.x - which*10) * 128;
    const int row0  = blockIdx.y * 128;

    const __nv_bfloat16 *Bh, *Bl;
    __nv_bfloat16 *dh, *dl;
    const float* bias;
    float scl;
    if (which == 0)      { Bh=g_Wqh; Bl=g_Wql; dh=g_qh; dl=g_ql; bias=bq;      scl=QKSCALE*LOG2E; }
    else if (which == 1) { Bh=g_Wkh; Bl=g_Wkl; dh=g_kh; dl=g_kl; bias=nullptr; scl=1.0f; }
    else                 { Bh=g_Wvh; Bl=g_Wvl; dh=g_vh; dl=g_vl; bias=bv;      scl=1.0f; }

    float acc[4][4][4];
    #pragma unroll
    for (int mt = 0; mt < 4; mt++)
        #pragma unroll
        for (int nt = 0; nt < 4; nt++)
            #pragma unroll
            for (int j = 0; j < 4; j++) acc[mt][nt][j] = 0.f;

    mm_loop_bf(g_Xh, g_Xl, Bh, Bl, row0, wcol0, smb, acc);

    const int g = lane >> 2, t4 = lane & 3;
    #pragma unroll
    for (int mt = 0; mt < 4; mt++) {
        #pragma unroll
        for (int nt = 0; nt < 4; nt++) {
            int col = wcol0 + warp_n*32 + nt*8 + 2*t4;
            float2 bb = bias ? *(const float2*)(bias + col) : make_float2(0.f, 0.f);
            int h = col >> 6, d = col & 63;
            int r0w = row0 + warp_m*64 + mt*16 + g;
            if (r0w < MR) {
                int b_ = r0w / TT, t_ = r0w - b_*TT;
                size_t base = ((size_t)(b_*NH + h) * TP + t_) * DH + d;
                uint32_t H, L;
                splitp((acc[mt][nt][0] + bb.x)*scl, (acc[mt][nt][1] + bb.y)*scl, H, L);
                *(uint32_t*)(dh + base) = H;
                *(uint32_t*)(dl + base) = L;
            }
            int r1w = r0w + 8;
            if (r1w < MR) {
                int b_ = r1w / TT, t_ = r1w - b_*TT;
                size_t base = ((size_t)(b_*NH + h) * TP + t_) * DH + d;
                uint32_t H, L;
                splitp((acc[mt][nt][2] + bb.x)*scl, (acc[mt][nt][3] + bb.y)*scl, H, L);
                *(uint32_t*)(dh + base) = H;
                *(uint32_t*)(dl + base) = L;
            }
        }
    }
}

// ============================================================================
// Output projection: out = ctx @ Wo^T + bo. grid (10, 47), 256 threads.
// ============================================================================
__global__ __launch_bounds__(256, 2) void out_mm(
    const float* __restrict__ bo, float* __restrict__ out)
{
    extern __shared__ char sm[];
    uint32_t smb = smem_u32(sm);
    const int tid = threadIdx.x;
    const int lane = tid & 31;
    const int wid = tid >> 5;
    const int warp_m = wid >> 2, warp_n = wid & 3;
    const int col0 = blockIdx.x * 128;
    const int row0 = blockIdx.y * 128;

    float acc[4][4][4];
    #pragma unroll
    for (int mt = 0; mt < 4; mt++)
        #pragma unroll
        for (int nt = 0; nt < 4; nt++)
            #pragma unroll
            for (int j = 0; j < 4; j++) acc[mt][nt][j] = 0.f;

    mm_loop_bf(g_cth, g_ctl, g_Woh, g_Wol, row0, col0, smb, acc);

    const int g = lane >> 2, t4 = lane & 3;
    #pragma unroll
    for (int mt = 0; mt < 4; mt++) {
        #pragma unroll
        for (int nt = 0; nt < 4; nt++) {
            int col = col0 + warp_n*32 + nt*8 + 2*t4;
            float2 bb = *(const float2*)(bo + col);
            int r0w = row0 + warp_m*64 + mt*16 + g;
            if (r0w < MR) {
                float2 v = make_float2(acc[mt][nt][0] + bb.x, acc[mt][nt][1] + bb.y);
                *(float2*)(out + (size_t)r0w*EE + col) = v;
            }
            int r1w = r0w + 8;
            if (r1w < MR) {
                float2 v = make_float2(acc[mt][nt][2] + bb.x, acc[mt][nt][3] + bb.y);
                *(float2*)(out + (size_t)r1w*EE + col) = v;
            }
        }
    }
}

// ============================================================================
// Flash attention: R14 pipeline, term-major MMA quads, exp2 softmax.
// Grid (24, 80), 128 threads. Writes pre-split bf16 ctx.
// ============================================================================
__global__ __launch_bounds__(128) void attn_kernel()
{
    extern __shared__ char sm[];
    uint32_t smb = smem_u32(sm);

    const int tid = threadIdx.x;
    const int lane = tid & 31;
    const int wid = tid >> 5;
    const int g  = lane >> 2;
    const int t4 = lane & 3;

    const int bhidx = blockIdx.y;
    const int b_ = bhidx / NH;
    const int h_ = bhidx - b_ * NH;
    const size_t hb = (size_t)bhidx * TP * DH;
    const int q0 = blockIdx.x * 64;

    // ---- Q staging into stage-0, then fragments ----
    #pragma unroll
    for (int j = 0; j < 4; j++) {
        int seg = tid + 128*j;
        int row = seg >> 3;
        int o8  = (seg & 7) * 8;
        size_t go = hb + (size_t)(q0 + row) * DH + o8;
        uint32_t so = (uint32_t)row * ATS + o8*2;
        cpa16(smb + SKH + so, g_qh + go);
        cpa16(smb + SKL + so, g_ql + go);
    }
    CP_COMMIT(); CP_WAIT(0);
    __syncthreads();

    uint32_t qh[4][4], ql[4][4];
    {
        uint32_t qa = smb + (uint32_t)(wid*16 + (lane & 15)) * ATS + (lane >> 4) * 16;
        #pragma unroll
        for (int kc = 0; kc < 4; kc++) {
            ldx4(qh[kc], qa + SKH + kc*32);
            ldx4(ql[kc], qa + SKL + kc*32);
        }
    }
    __syncthreads();

    float m0 = -1e30f, m1 = -1e30f, l0 = 0.f, l1 = 0.f;
    float o[8][4];
    #pragma unroll
    for (int nt = 0; nt < 8; nt++)
        #pragma unroll
        for (int j = 0; j < 4; j++) o[nt][j] = 0.f;

    // ---- issue K/V tile 0 into stage 0 ----
    #pragma unroll
    for (int j = 0; j < 4; j++) {
        int seg = tid + 128*j;
        int row = seg >> 3;
        int o8  = (seg & 7) * 8;
        size_t go = hb + (size_t)row * DH + o8;
        uint32_t so = (uint32_t)row * ATS + o8*2;
        cpa16(smb + SKH + so, g_kh + go);
        cpa16(smb + SKL + so, g_kl + go);
        cpa16(smb + SVH + so, g_vh + go);
        cpa16(smb + SVL + so, g_vl + go);
    }
    CP_COMMIT();

    #pragma unroll 1
    for (int kt = 0; kt < 24; kt++) {
        const int k0 = kt * 64;
        CP_WAIT(0);
        __syncthreads();

        if (kt + 1 < 24) {
            const int k1 = (kt + 1) * 64;
            const uint32_t stN = smb + ((kt + 1) & 1) * AST;
            #pragma unroll
            for (int j = 0; j < 4; j++) {
                int seg = tid + 128*j;
                int row = seg >> 3;
                int o8  = (seg & 7) * 8;
                size_t go = hb + (size_t)(k1 + row) * DH + o8;
                uint32_t so = (uint32_t)row * ATS + o8*2;
                cpa16(stN + SKH + so, g_kh + go);
                cpa16(stN + SKL + so, g_kl + go);
                cpa16(stN + SVH + so, g_vh + go);
                cpa16(stN + SVL + so, g_vl + go);
            }
            CP_COMMIT();
        }

        const uint32_t st = smb + (kt & 1) * AST;
        const uint32_t k_rd = st + (uint32_t)(lane & 7) * ATS + ((lane >> 3) & 1) * 16;
        const uint32_t v_rd = st + (uint32_t)(lane & 15) * ATS;

        // ---- S = Q K^T, term-major in nt-quads ----
        float s[8][4];
        #pragma unroll
        for (int nt = 0; nt < 8; nt++)
            #pragma unroll
            for (int j = 0; j < 4; j++) s[nt][j] = 0.f;

        #pragma unroll
        for (int kc = 0; kc < 4; kc++) {
            #pragma unroll
            for (int half = 0; half < 2; half++) {
                uint32_t kh2[4][2], kl2[4][2];
                #pragma unroll
                for (int q = 0; q < 4; q++) {
                    uint32_t kbase = k_rd + (uint32_t)(half*4 + q)*8*ATS + kc*32;
                    ldx2(kh2[q], kbase + SKH);
                    ldx2(kl2[q], kbase + SKL);
                }
                #pragma unroll
                for (int q = 0; q < 4; q++) mma_bf16(s[half*4+q], qh[kc], kh2[q]);
                #pragma unroll
                for (int q = 0; q < 4; q++) mma_bf16(s[half*4+q], qh[kc], kl2[q]);
                #pragma unroll
                for (int q = 0; q < 4; q++) mma_bf16(s[half*4+q], ql[kc], kh2[q]);
            }
        }

        if (k0 + 64 > TT) {
            #pragma unroll
            for (int nt = 0; nt < 8; nt++) {
                int col = k0 + nt*8 + 2*t4;
                if (col   >= TT) { s[nt][0] = -1e30f; s[nt][2] = -1e30f; }
                if (col+1 >= TT) { s[nt][1] = -1e30f; s[nt][3] = -1e30f; }
            }
        }

        // ---- online softmax (base-2: scores pre-scaled by log2 e) ----
        float mx0 = -1e30f, mx1 = -1e30f;
        #pragma unroll
        for (int nt = 0; nt < 8; nt++) {
            mx0 = fmaxf(mx0, fmaxf(s[nt][0], s[nt][1]));
            mx1 = fmaxf(mx1, fmaxf(s[nt][2], s[nt][3]));
        }
        mx0 = fmaxf(mx0, __shfl_xor_sync(0xffffffffu, mx0, 1));
        mx0 = fmaxf(mx0, __shfl_xor_sync(0xffffffffu, mx0, 2));
        mx1 = fmaxf(mx1, __shfl_xor_sync(0xffffffffu, mx1, 1));
        mx1 = fmaxf(mx1, __shfl_xor_sync(0xffffffffu, mx1, 2));

        float mn0 = fmaxf(m0, mx0), mn1 = fmaxf(m1, mx1);
        float al0 = exp2f(m0 - mn0), al1 = exp2f(m1 - mn1);
        m0 = mn0; m1 = mn1;

        float sum0 = 0.f, sum1 = 0.f;
        #pragma unroll
        for (int nt = 0; nt < 8; nt++) {
            s[nt][0] = exp2f(s[nt][0] - mn0); sum0 += s[nt][0];
            s[nt][1] = exp2f(s[nt][1] - mn0); sum0 += s[nt][1];
            s[nt][2] = exp2f(s[nt][2] - mn1); sum1 += s[nt][2];
            s[nt][3] = exp2f(s[nt][3] - mn1); sum1 += s[nt][3];
        }
        sum0 += __shfl_xor_sync(0xffffffffu, sum0, 1);
        sum0 += __shfl_xor_sync(0xffffffffu, sum0, 2);
        sum1 += __shfl_xor_sync(0xffffffffu, sum1, 1);
        sum1 += __shfl_xor_sync(0xffffffffu, sum1, 2);
        l0 = l0 * al0 + sum0;
        l1 = l1 * al1 + sum1;

        #pragma unroll
        for (int nt = 0; nt < 8; nt++) {
            o[nt][0] *= al0; o[nt][1] *= al0;
            o[nt][2] *= al1; o[nt][3] *= al1;
        }

        // ---- O += P V, term-major in nt-quads ----
        #pragma unroll
        for (int kc = 0; kc < 4; kc++) {
            uint32_t ah[4], al_[4];
            splitp(s[2*kc][0],   s[2*kc][1],   ah[0], al_[0]);
            splitp(s[2*kc][2],   s[2*kc][3],   ah[1], al_[1]);
            splitp(s[2*kc+1][0], s[2*kc+1][1], ah[2], al_[2]);
            splitp(s[2*kc+1][2], s[2*kc+1][3], ah[3], al_[3]);
            uint32_t vbase = v_rd + (uint32_t)kc*16*ATS;
            #pragma unroll
            for (int half = 0; half < 2; half++) {
                uint32_t vh2[4][2], vl2[4][2];
                #pragma unroll
                for (int q = 0; q < 4; q++) {
                    ldx2t(vh2[q], vbase + SVH + (half*4 + q)*16);
                    ldx2t(vl2[q], vbase + SVL + (half*4 + q)*16);
                }
                #pragma unroll
                for (int q = 0; q < 4; q++) mma_bf16(o[half*4+q], ah,  vh2[q]);
                #pragma unroll
                for (int q = 0; q < 4; q++) mma_bf16(o[half*4+q], ah,  vl2[q]);
                #pragma unroll
                for (int q = 0; q < 4; q++) mma_bf16(o[half*4+q], al_, vh2[q]);
            }
        }
    }

    // ---- epilogue: normalize, split, write pre-split bf16 ctx ----
    float inv0 = 1.0f / l0, inv1 = 1.0f / l1;
    int r0w = q0 + wid*16 + g;
    int r1w = r0w + 8;
    #pragma unroll
    for (int nt = 0; nt < 8; nt++) {
        int d = nt*8 + 2*t4;
        if (r0w < TT) {
            size_t base = (size_t)(b_ * TT + r0w) * EE + h_ * DH + d;
            uint32_t H, L;
            splitp(o[nt][0]*inv0, o[nt][1]*inv0, H, L);
            *(uint32_t*)(g_cth + base) = H;
            *(uint32_t*)(g_ctl + base) = L;
        }
        if (r1w < TT) {
            size_t base = (size_t)(b_ * TT + r1w) * EE + h_ * DH + d;
            uint32_t H, L;
            splitp(o[nt][2]*inv1, o[nt][3]*inv1, H, L);
            *(uint32_t*)(g_cth + base) = H;
            *(uint32_t*)(g_ctl + base) = L;
        }
    }
}

extern "C" void kernel_launch(void* const* d_in, const int* in_sizes, int n_in,
                              void* d_out, int out_size)
{
    const float* X  = (const float*)d_in[0];
    const float* Wq = (const float*)d_in[1];
    const float* bq = (const float*)d_in[2];
    const float* Wk = (const float*)d_in[3];
    const float* Wv = (const float*)d_in[4];
    const float* bv = (const float*)d_in[5];
    const float* Wo = (const float*)d_in[6];
    const float* bo = (const float*)d_in[7];
    float* out = (float*)d_out;

    cudaFuncSetAttribute(qkv_mm, cudaFuncAttributeMaxDynamicSharedMemorySize, GSM);
    cudaFuncSetAttribute(out_mm, cudaFuncAttributeMaxDynamicSharedMemorySize, GSM);
    cudaFuncSetAttribute(attn_kernel, cudaFuncAttributeMaxDynamicSharedMemorySize, ASMEM);

    // fused prep
    {
        size_t tot = (size_t)MRP*EE/4 + 4*(size_t)EE*EE/4;
        prep_all<<<(unsigned)((tot + 255)/256), 256>>>(X, Wq, Wk, Wv, Wo);
    }
    zero_pad_qkv<<<(NB*NH*(TP-TT)*DH + 255)/256, 256>>>();
    zero_pad_ctx<<<((MRP-MR)*EE + 255)/256, 256>>>();

    dim3 g1(30, 47);
    qkv_mm<<<g1, 256, GSM>>>(bq, bv);

    dim3 g2(24, NB * NH);
    attn_kernel<<<g2, 128, ASMEM>>>();

    dim3 g3(10, 47);
    out_mm<<<g3, 256, GSM>>>(bo, out);
}

// round 16
// speedup vs baseline: 1.9468x; 1.0933x over previous
#include <cuda_runtime.h>
#include <cuda_bf16.h>
#include <cuda_fp16.h>
#include <cstdint>

// Problem constants
#define NB 4
#define TT 1500
#define TP 1536
#define EE 1280
#define NH 20
#define DH 64
#define MR (NB*TT)         // 6000
#define MRP 6016
#define QKSCALE 0.125f
#define LOG2E 1.44269504088896f

// GEMM tiling: CTA 128x128, 8 warps (2x4), warp tile 64x32, k-chunk 32
#define BK 32
#define NCH (EE/BK)         // 40
#define RS 80
#define TSZ (128*RS)        // 10240
#define STG (4*TSZ)         // qkv: Ah,Al,Bh,Bl = 40960
#define GSM (2*STG)         // 81920
#define STG3 (3*TSZ)        // out: A,Bh,Bl = 30720
#define GSM3 (2*STG3)       // 61440

// Attention smem: 2 stages x 4 tiles (KH,KL,VH,VL) of 64x64 16-bit, 144B stride
#define ATS 144
#define ATILE (64*ATS)
#define SKH 0
#define SKL ATILE
#define SVH (2*ATILE)
#define SVL (3*ATILE)
#define AST (4*ATILE)
#define ASMEM (2*AST)       // 73728

// ---- pre-split global buffers ----
// bf16 (3-term paths): X, Wq, Wk, Wv, q, k
static __device__ __align__(16) __nv_bfloat16 g_Xh[(size_t)MRP*EE], g_Xl[(size_t)MRP*EE];
static __device__ __align__(16) __nv_bfloat16 g_Wqh[(size_t)EE*EE], g_Wql[(size_t)EE*EE];
static __device__ __align__(16) __nv_bfloat16 g_Wkh[(size_t)EE*EE], g_Wkl[(size_t)EE*EE];
static __device__ __align__(16) __nv_bfloat16 g_Wvh[(size_t)EE*EE], g_Wvl[(size_t)EE*EE];
static __device__ __align__(16) __nv_bfloat16 g_qh[(size_t)NB*NH*TP*DH], g_ql[(size_t)NB*NH*TP*DH];
static __device__ __align__(16) __nv_bfloat16 g_kh[(size_t)NB*NH*TP*DH], g_kl[(size_t)NB*NH*TP*DH];
// fp16 (2-term paths): V hi/lo, Wo hi/lo, ctx single
static __device__ __align__(16) __half g_vh[(size_t)NB*NH*TP*DH], g_vl[(size_t)NB*NH*TP*DH];
static __device__ __align__(16) __half g_Woh[(size_t)EE*EE], g_Wol[(size_t)EE*EE];
static __device__ __align__(16) __half g_ct[(size_t)MRP*EE];

// ---------------- helpers ----------------
__device__ __forceinline__ uint32_t smem_u32(const void* p){
    uint32_t a;
    asm("{ .reg .u64 t; cvta.to.shared.u64 t, %1; cvt.u32.u64 %0, t; }" : "=r"(a) : "l"(p));
    return a;
}
__device__ __forceinline__ void ldx4(uint32_t* r, uint32_t addr){
    asm volatile("ldmatrix.sync.aligned.m8n8.x4.shared.b16 {%0,%1,%2,%3}, [%4];"
        : "=r"(r[0]), "=r"(r[1]), "=r"(r[2]), "=r"(r[3]) : "r"(addr));
}
__device__ __forceinline__ void ldx2(uint32_t* r, uint32_t addr){
    asm volatile("ldmatrix.sync.aligned.m8n8.x2.shared.b16 {%0,%1}, [%2];"
        : "=r"(r[0]), "=r"(r[1]) : "r"(addr));
}
__device__ __forceinline__ void ldx2t(uint32_t* r, uint32_t addr){
    asm volatile("ldmatrix.sync.aligned.m8n8.x2.trans.shared.b16 {%0,%1}, [%2];"
        : "=r"(r[0]), "=r"(r[1]) : "r"(addr));
}
__device__ __forceinline__ void mma_bf16(float* d, const uint32_t* a, const uint32_t* b){
    asm volatile(
        "mma.sync.aligned.m16n8k16.row.col.f32.bf16.bf16.f32 "
        "{%0,%1,%2,%3}, {%4,%5,%6,%7}, {%8,%9}, {%0,%1,%2,%3};"
        : "+f"(d[0]), "+f"(d[1]), "+f"(d[2]), "+f"(d[3])
        : "r"(a[0]), "r"(a[1]), "r"(a[2]), "r"(a[3]), "r"(b[0]), "r"(b[1]));
}
__device__ __forceinline__ void mma_f16(float* d, const uint32_t* a, const uint32_t* b){
    asm volatile(
        "mma.sync.aligned.m16n8k16.row.col.f32.f16.f16.f32 "
        "{%0,%1,%2,%3}, {%4,%5,%6,%7}, {%8,%9}, {%0,%1,%2,%3};"
        : "+f"(d[0]), "+f"(d[1]), "+f"(d[2]), "+f"(d[3])
        : "r"(a[0]), "r"(a[1]), "r"(a[2]), "r"(a[3]), "r"(b[0]), "r"(b[1]));
}
__device__ __forceinline__ void cpa16(uint32_t s, const void* g){
    asm volatile("cp.async.ca.shared.global [%0], [%1], 16;" :: "r"(s), "l"(g));
}
#define CP_COMMIT() asm volatile("cp.async.commit_group;" ::: "memory")
#define CP_WAIT(n)  asm volatile("cp.async.wait_group %0;" :: "n"(n) : "memory")

__device__ __forceinline__ void split4(float4 f, uint2& H, uint2& L){
    __nv_bfloat16 hx = __float2bfloat16(f.x);
    __nv_bfloat16 hy = __float2bfloat16(f.y);
    __nv_bfloat16 hz = __float2bfloat16(f.z);
    __nv_bfloat16 hw = __float2bfloat16(f.w);
    float lx = f.x - __bfloat162float(hx);
    float ly = f.y - __bfloat162float(hy);
    float lz = f.z - __bfloat162float(hz);
    float lw = f.w - __bfloat162float(hw);
    union { __nv_bfloat162 h2[2]; uint2 u; } A, B;
    A.h2[0] = __halves2bfloat162(hx, hy);
    A.h2[1] = __halves2bfloat162(hz, hw);
    B.h2[0] = __floats2bfloat162_rn(lx, ly);
    B.h2[1] = __floats2bfloat162_rn(lz, lw);
    H = A.u; L = B.u;
}
__device__ __forceinline__ void splitp(float a, float b, uint32_t& H, uint32_t& L){
    __nv_bfloat16 ha = __float2bfloat16(a);
    __nv_bfloat16 hb = __float2bfloat16(b);
    float la = a - __bfloat162float(ha);
    float lb = b - __bfloat162float(hb);
    union { __nv_bfloat162 h; uint32_t u; } X, Y;
    X.h = __halves2bfloat162(ha, hb);
    Y.h = __floats2bfloat162_rn(la, lb);
    H = X.u; L = Y.u;
}
// fp16 split pair
__device__ __forceinline__ void splitph(float a, float b, uint32_t& H, uint32_t& L){
    __half ha = __float2half_rn(a);
    __half hb = __float2half_rn(b);
    float la = a - __half2float(ha);
    float lb = b - __half2float(hb);
    union { __half2 h; uint32_t u; } X, Y;
    X.h = __halves2half2(ha, hb);
    Y.h = __floats2half2_rn(la, lb);
    H = X.u; L = Y.u;
}
__device__ __forceinline__ uint32_t f2h2(float a, float b){
    union { __half2 h; uint32_t u; } X;
    X.h = __floats2half2_rn(a, b);
    return X.u;
}

// ============================================================================
// Prep kernels
// ============================================================================
__global__ void prep_all(const float* __restrict__ X,
                         const float* __restrict__ Wq, const float* __restrict__ Wk,
                         const float* __restrict__ Wv)
{
    const size_t NX = (size_t)MRP*EE/4;
    const size_t NW = (size_t)EE*EE/4;
    size_t i = (size_t)blockIdx.x * blockDim.x + threadIdx.x;
    const float* src;
    __nv_bfloat16 *h, *l;
    size_t j;
    bool pad = false;
    if (i < NX) {
        j = i; src = X; h = g_Xh; l = g_Xl;
        int row = (int)(j * 4 / EE);
        pad = (row >= MR);
    } else {
        i -= NX;
        if (i >= 3*NW) return;
        int w = (int)(i / NW);
        j = i - (size_t)w * NW;
        switch (w) {
            case 0: src = Wq; h = g_Wqh; l = g_Wql; break;
            case 1: src = Wk; h = g_Wkh; l = g_Wkl; break;
            default: src = Wv; h = g_Wvh; l = g_Wvl; break;
        }
    }
    float4 f = pad ? make_float4(0.f,0.f,0.f,0.f) : *(const float4*)(src + j*4);
    uint2 H, L;
    split4(f, H, L);
    *(uint2*)(h + j*4) = H;
    *(uint2*)(l + j*4) = L;
}

__global__ void prep_wo(const float* __restrict__ Wo)
{
    size_t j = (size_t)blockIdx.x * blockDim.x + threadIdx.x;
    if (j >= (size_t)EE*EE/2) return;
    float2 f = *(const float2*)(Wo + j*2);
    uint32_t H, L;
    splitph(f.x, f.y, H, L);
    *(uint32_t*)(g_Woh + j*2) = H;
    *(uint32_t*)(g_Wol + j*2) = L;
}

__global__ void zero_pad_qkv()
{
    int idx = blockIdx.x * blockDim.x + threadIdx.x;
    const int tot = NB*NH*(TP-TT)*DH;
    if (idx >= tot) return;
    int d = idx & 63;
    int r = idx >> 6;
    int t = TT + (r % (TP-TT));
    int head = r / (TP-TT);
    size_t off = ((size_t)head * TP + t) * DH + d;
    __nv_bfloat16 z = __float2bfloat16(0.f);
    __half zh = __float2half(0.f);
    g_qh[off]=z; g_ql[off]=z; g_kh[off]=z; g_kl[off]=z; g_vh[off]=zh; g_vl[off]=zh;
}

__global__ void zero_pad_ctx()
{
    int idx = blockIdx.x * blockDim.x + threadIdx.x;
    const int tot = (MRP-MR)*EE;
    if (idx >= tot) return;
    g_ct[(size_t)MR*EE + idx] = __float2half(0.f);
}

// ============================================================================
// QKV GEMM mainloop: bf16 3-term, cp.async 2-stage prefetch-after-sync.
// ============================================================================
__device__ __forceinline__ void mm_loop_bf(
    const __nv_bfloat16* __restrict__ Ah_, const __nv_bfloat16* __restrict__ Al_,
    const __nv_bfloat16* __restrict__ Bh_, const __nv_bfloat16* __restrict__ Bl_,
    int arow0, int brow0, uint32_t smb, float acc[4][4][4])
{
    const int tid  = threadIdx.x;
    const int lane = tid & 31;
    const int wid  = tid >> 5;
    const int warp_m = wid >> 2;
    const int warp_n = wid & 3;

    const int r0 = tid >> 2;
    const int c0 = (tid & 3) * 8;
    const __nv_bfloat16* gAh0 = Ah_ + (size_t)(arow0 + r0)      * EE + c0;
    const __nv_bfloat16* gAh1 = Ah_ + (size_t)(arow0 + r0 + 64) * EE + c0;
    const __nv_bfloat16* gAl0 = Al_ + (size_t)(arow0 + r0)      * EE + c0;
    const __nv_bfloat16* gAl1 = Al_ + (size_t)(arow0 + r0 + 64) * EE + c0;
    const __nv_bfloat16* gBh0 = Bh_ + (size_t)(brow0 + r0)      * EE + c0;
    const __nv_bfloat16* gBh1 = Bh_ + (size_t)(brow0 + r0 + 64) * EE + c0;
    const __nv_bfloat16* gBl0 = Bl_ + (size_t)(brow0 + r0)      * EE + c0;
    const __nv_bfloat16* gBl1 = Bl_ + (size_t)(brow0 + r0 + 64) * EE + c0;
    const uint32_t sd0 = smb + (uint32_t)r0 * RS + c0 * 2;
    const uint32_t sd1 = smb + (uint32_t)(r0 + 64) * RS + c0 * 2;

    const uint32_t a_rd = smb + (uint32_t)(warp_m*64 + (lane & 15)) * RS + (lane >> 4) * 16;
    const uint32_t b_rd = smb + 2*TSZ + (uint32_t)(warp_n*32 + (lane & 7)) * RS + ((lane >> 3) & 1) * 16;

    cpa16(sd0,           gAh0); cpa16(sd1,           gAh1);
    cpa16(sd0 + TSZ,     gAl0); cpa16(sd1 + TSZ,     gAl1);
    cpa16(sd0 + 2*TSZ,   gBh0); cpa16(sd1 + 2*TSZ,   gBh1);
    cpa16(sd0 + 3*TSZ,   gBl0); cpa16(sd1 + 3*TSZ,   gBl1);
    CP_COMMIT();

    #pragma unroll 1
    for (int i = 0; i < NCH; i++) {
        CP_WAIT(0);
        __syncthreads();

        if (i + 1 < NCH) {
            const int ko = (i + 1) * BK;
            const uint32_t so = ((i + 1) & 1) * STG;
            cpa16(sd0 + so,           gAh0 + ko); cpa16(sd1 + so,           gAh1 + ko);
            cpa16(sd0 + so + TSZ,     gAl0 + ko); cpa16(sd1 + so + TSZ,     gAl1 + ko);
            cpa16(sd0 + so + 2*TSZ,   gBh0 + ko); cpa16(sd1 + so + 2*TSZ,   gBh1 + ko);
            cpa16(sd0 + so + 3*TSZ,   gBl0 + ko); cpa16(sd1 + so + 3*TSZ,   gBl1 + ko);
            CP_COMMIT();
        }

        const uint32_t soff = (uint32_t)(i & 1) * STG;
        #pragma unroll
        for (int kk = 0; kk < 2; kk++) {
            const uint32_t koff = soff + kk*32;
            uint32_t bh[4][2], bl[4][2];
            #pragma unroll
            for (int nt = 0; nt < 4; nt++) {
                ldx2(bh[nt], b_rd + koff + nt*8*RS);
                ldx2(bl[nt], b_rd + koff + nt*8*RS + TSZ);
            }
            #pragma unroll
            for (int mt = 0; mt < 4; mt++) {
                uint32_t ah[4], al[4];
                ldx4(ah, a_rd + koff + mt*16*RS);
                ldx4(al, a_rd + koff + mt*16*RS + TSZ);
                #pragma unroll
                for (int nt = 0; nt < 4; nt++) mma_bf16(acc[mt][nt], ah, bh[nt]);
                #pragma unroll
                for (int nt = 0; nt < 4; nt++) mma_bf16(acc[mt][nt], ah, bl[nt]);
                #pragma unroll
                for (int nt = 0; nt < 4; nt++) mma_bf16(acc[mt][nt], al, bh[nt]);
            }
        }
    }
}

// ============================================================================
// out_mm mainloop: fp16 2-term (A single, B hi/lo). 3 tiles/stage.
// ============================================================================
__device__ __forceinline__ void mm_loop_h(
    const __half* __restrict__ A_,
    const __half* __restrict__ Bh_, const __half* __restrict__ Bl_,
    int arow0, int brow0, uint32_t smb, float acc[4][4][4])
{
    const int tid  = threadIdx.x;
    const int lane = tid & 31;
    const int wid  = tid >> 5;
    const int warp_m = wid >> 2;
    const int warp_n = wid & 3;

    const int r0 = tid >> 2;
    const int c0 = (tid & 3) * 8;
    const __half* gA0 = A_ + (size_t)(arow0 + r0)      * EE + c0;
    const __half* gA1 = A_ + (size_t)(arow0 + r0 + 64) * EE + c0;
    const __half* gBh0 = Bh_ + (size_t)(brow0 + r0)      * EE + c0;
    const __half* gBh1 = Bh_ + (size_t)(brow0 + r0 + 64) * EE + c0;
    const __half* gBl0 = Bl_ + (size_t)(brow0 + r0)      * EE + c0;
    const __half* gBl1 = Bl_ + (size_t)(brow0 + r0 + 64) * EE + c0;
    const uint32_t sd0 = smb + (uint32_t)r0 * RS + c0 * 2;
    const uint32_t sd1 = smb + (uint32_t)(r0 + 64) * RS + c0 * 2;

    const uint32_t a_rd = smb + (uint32_t)(warp_m*64 + (lane & 15)) * RS + (lane >> 4) * 16;
    const uint32_t b_rd = smb + TSZ + (uint32_t)(warp_n*32 + (lane & 7)) * RS + ((lane >> 3) & 1) * 16;

    cpa16(sd0,           gA0);  cpa16(sd1,           gA1);
    cpa16(sd0 + TSZ,     gBh0); cpa16(sd1 + TSZ,     gBh1);
    cpa16(sd0 + 2*TSZ,   gBl0); cpa16(sd1 + 2*TSZ,   gBl1);
    CP_COMMIT();

    #pragma unroll 1
    for (int i = 0; i < NCH; i++) {
        CP_WAIT(0);
        __syncthreads();

        if (i + 1 < NCH) {
            const int ko = (i + 1) * BK;
            const uint32_t so = ((i + 1) & 1) * STG3;
            cpa16(sd0 + so,           gA0 + ko);  cpa16(sd1 + so,           gA1 + ko);
            cpa16(sd0 + so + TSZ,     gBh0 + ko); cpa16(sd1 + so + TSZ,     gBh1 + ko);
            cpa16(sd0 + so + 2*TSZ,   gBl0 + ko); cpa16(sd1 + so + 2*TSZ,   gBl1 + ko);
            CP_COMMIT();
        }

        const uint32_t soff = (uint32_t)(i & 1) * STG3;
        #pragma unroll
        for (int kk = 0; kk < 2; kk++) {
            const uint32_t koff = soff + kk*32;
            uint32_t bh[4][2], bl[4][2];
            #pragma unroll
            for (int nt = 0; nt < 4; nt++) {
                ldx2(bh[nt], b_rd + koff + nt*8*RS);
                ldx2(bl[nt], b_rd + koff + nt*8*RS + TSZ);
            }
            #pragma unroll
            for (int mt = 0; mt < 4; mt++) {
                uint32_t ah[4];
                ldx4(ah, a_rd + koff + mt*16*RS);
                #pragma unroll
                for (int nt = 0; nt < 4; nt++) mma_f16(acc[mt][nt], ah, bh[nt]);
                #pragma unroll
                for (int nt = 0; nt < 4; nt++) mma_f16(acc[mt][nt], ah, bl[nt]);
            }
        }
    }
}

// ============================================================================
// QKV GEMM: grid (30, 47). q,k -> bf16 hi/lo; v -> fp16 hi/lo.
// ============================================================================
__global__ __launch_bounds__(256, 2) void qkv_mm(
    const float* __restrict__ bq, const float* __restrict__ bv)
{
    extern __shared__ char sm[];
    uint32_t smb = smem_u32(sm);
    const int tid = threadIdx.x;
    const int lane = tid & 31;
    const int wid = tid >> 5;
    const int warp_m = wid >> 2, warp_n = wid & 3;

    const int which = blockIdx.x / 10;
    const int wcol0 = (blockIdx.x - which*10) * 128;
    const int row0  = blockIdx.y * 128;

    const __nv_bfloat16 *Bh, *Bl;
    void *dh, *dl;
    const float* bias;
    float scl;
    if (which == 0)      { Bh=g_Wqh; Bl=g_Wql; dh=g_qh; dl=g_ql; bias=bq;      scl=QKSCALE*LOG2E; }
    else if (which == 1) { Bh=g_Wkh; Bl=g_Wkl; dh=g_kh; dl=g_kl; bias=nullptr; scl=1.0f; }
    else                 { Bh=g_Wvh; Bl=g_Wvl; dh=g_vh; dl=g_vl; bias=bv;      scl=1.0f; }

    float acc[4][4][4];
    #pragma unroll
    for (int mt = 0; mt < 4; mt++)
        #pragma unroll
        for (int nt = 0; nt < 4; nt++)
            #pragma unroll
            for (int j = 0; j < 4; j++) acc[mt][nt][j] = 0.f;

    mm_loop_bf(g_Xh, g_Xl, Bh, Bl, row0, wcol0, smb, acc);

    const int g = lane >> 2, t4 = lane & 3;
    #pragma unroll
    for (int mt = 0; mt < 4; mt++) {
        int r0w = row0 + warp_m*64 + mt*16 + g;
        int r1w = r0w + 8;
        int b0 = r0w / TT, t0 = r0w - b0*TT;
        int b1 = r1w / TT, t1 = r1w - b1*TT;
        bool v0 = r0w < MR, v1 = r1w < MR;
        #pragma unroll
        for (int nt = 0; nt < 4; nt++) {
            int col = wcol0 + warp_n*32 + nt*8 + 2*t4;
            float2 bb = bias ? *(const float2*)(bias + col) : make_float2(0.f, 0.f);
            int h = col >> 6, d = col & 63;
            if (v0) {
                size_t base = ((size_t)(b0*NH + h) * TP + t0) * DH + d;
                uint32_t H, L;
                float x = (acc[mt][nt][0] + bb.x)*scl, y = (acc[mt][nt][1] + bb.y)*scl;
                if (which == 2) splitph(x, y, H, L); else splitp(x, y, H, L);
                *(uint32_t*)((__half*)dh + base) = H;
                *(uint32_t*)((__half*)dl + base) = L;
            }
            if (v1) {
                size_t base = ((size_t)(b1*NH + h) * TP + t1) * DH + d;
                uint32_t H, L;
                float x = (acc[mt][nt][2] + bb.x)*scl, y = (acc[mt][nt][3] + bb.y)*scl;
                if (which == 2) splitph(x, y, H, L); else splitp(x, y, H, L);
                *(uint32_t*)((__half*)dh + base) = H;
                *(uint32_t*)((__half*)dl + base) = L;
            }
        }
    }
}

// ============================================================================
// Output projection: out = ctx @ Wo^T + bo (fp16 2-term). grid (10, 47).
// ============================================================================
__global__ __launch_bounds__(256, 2) void out_mm(
    const float* __restrict__ bo, float* __restrict__ out)
{
    extern __shared__ char sm[];
    uint32_t smb = smem_u32(sm);
    const int tid = threadIdx.x;
    const int lane = tid & 31;
    const int wid = tid >> 5;
    const int warp_m = wid >> 2, warp_n = wid & 3;
    const int col0 = blockIdx.x * 128;
    const int row0 = blockIdx.y * 128;

    float acc[4][4][4];
    #pragma unroll
    for (int mt = 0; mt < 4; mt++)
        #pragma unroll
        for (int nt = 0; nt < 4; nt++)
            #pragma unroll
            for (int j = 0; j < 4; j++) acc[mt][nt][j] = 0.f;

    mm_loop_h(g_ct, g_Woh, g_Wol, row0, col0, smb, acc);

    const int g = lane >> 2, t4 = lane & 3;
    #pragma unroll
    for (int mt = 0; mt < 4; mt++) {
        int r0w = row0 + warp_m*64 + mt*16 + g;
        int r1w = r0w + 8;
        #pragma unroll
        for (int nt = 0; nt < 4; nt++) {
            int col = col0 + warp_n*32 + nt*8 + 2*t4;
            float2 bb = *(const float2*)(bo + col);
            if (r0w < MR) {
                float2 v = make_float2(acc[mt][nt][0] + bb.x, acc[mt][nt][1] + bb.y);
                *(float2*)(out + (size_t)r0w*EE + col) = v;
            }
            if (r1w < MR) {
                float2 v = make_float2(acc[mt][nt][2] + bb.x, acc[mt][nt][3] + bb.y);
                *(float2*)(out + (size_t)r1w*EE + col) = v;
            }
        }
    }
}

// ============================================================================
// Flash attention: S = bf16 3-term; PV = fp16 P-single x V hi/lo (2-term).
// Double-buffered K/V, exp2 softmax. Writes ctx as single fp16.
// Grid (24, 80), 128 threads.
// ============================================================================
__global__ __launch_bounds__(128) void attn_kernel()
{
    extern __shared__ char sm[];
    uint32_t smb = smem_u32(sm);

    const int tid = threadIdx.x;
    const int lane = tid & 31;
    const int wid = tid >> 5;
    const int g  = lane >> 2;
    const int t4 = lane & 3;

    const int bhidx = blockIdx.y;
    const int b_ = bhidx / NH;
    const int h_ = bhidx - b_ * NH;
    const size_t hb = (size_t)bhidx * TP * DH;
    const int q0 = blockIdx.x * 64;

    // ---- Q staging into stage-0, then fragments ----
    #pragma unroll
    for (int j = 0; j < 4; j++) {
        int seg = tid + 128*j;
        int row = seg >> 3;
        int o8  = (seg & 7) * 8;
        size_t go = hb + (size_t)(q0 + row) * DH + o8;
        uint32_t so = (uint32_t)row * ATS + o8*2;
        cpa16(smb + SKH + so, g_qh + go);
        cpa16(smb + SKL + so, g_ql + go);
    }
    CP_COMMIT(); CP_WAIT(0);
    __syncthreads();

    uint32_t qh[4][4], ql[4][4];
    {
        uint32_t qa = smb + (uint32_t)(wid*16 + (lane & 15)) * ATS + (lane >> 4) * 16;
        #pragma unroll
        for (int kc = 0; kc < 4; kc++) {
            ldx4(qh[kc], qa + SKH + kc*32);
            ldx4(ql[kc], qa + SKL + kc*32);
        }
    }
    __syncthreads();

    float m0 = -1e30f, m1 = -1e30f, l0 = 0.f, l1 = 0.f;
    float o[8][4];
    #pragma unroll
    for (int nt = 0; nt < 8; nt++)
        #pragma unroll
        for (int j = 0; j < 4; j++) o[nt][j] = 0.f;

    // ---- issue K/V tile 0 into stage 0 ----
    #pragma unroll
    for (int j = 0; j < 4; j++) {
        int seg = tid + 128*j;
        int row = seg >> 3;
        int o8  = (seg & 7) * 8;
        size_t go = hb + (size_t)row * DH + o8;
        uint32_t so = (uint32_t)row * ATS + o8*2;
        cpa16(smb + SKH + so, g_kh + go);
        cpa16(smb + SKL + so, g_kl + go);
        cpa16(smb + SVH + so, g_vh + go);
        cpa16(smb + SVL + so, g_vl + go);
    }
    CP_COMMIT();

    #pragma unroll 1
    for (int kt = 0; kt < 24; kt++) {
        const int k0 = kt * 64;
        CP_WAIT(0);
        __syncthreads();

        if (kt + 1 < 24) {
            const int k1 = (kt + 1) * 64;
            const uint32_t stN = smb + ((kt + 1) & 1) * AST;
            #pragma unroll
            for (int j = 0; j < 4; j++) {
                int seg = tid + 128*j;
                int row = seg >> 3;
                int o8  = (seg & 7) * 8;
                size_t go = hb + (size_t)(k1 + row) * DH + o8;
                uint32_t so = (uint32_t)row * ATS + o8*2;
                cpa16(stN + SKH + so, g_kh + go);
                cpa16(stN + SKL + so, g_kl + go);
                cpa16(stN + SVH + so, g_vh + go);
                cpa16(stN + SVL + so, g_vl + go);
            }
            CP_COMMIT();
        }

        const uint32_t st = smb + (kt & 1) * AST;
        const uint32_t k_rd = st + (uint32_t)(lane & 7) * ATS + ((lane >> 3) & 1) * 16;
        const uint32_t v_rd = st + (uint32_t)(lane & 15) * ATS;

        // ---- S = Q K^T, bf16 3-term, term-major nt-quads ----
        float s[8][4];
        #pragma unroll
        for (int nt = 0; nt < 8; nt++)
            #pragma unroll
            for (int j = 0; j < 4; j++) s[nt][j] = 0.f;

        #pragma unroll
        for (int kc = 0; kc < 4; kc++) {
            #pragma unroll
            for (int half = 0; half < 2; half++) {
                uint32_t kh2[4][2], kl2[4][2];
                #pragma unroll
                for (int q = 0; q < 4; q++) {
                    uint32_t kbase = k_rd + (uint32_t)(half*4 + q)*8*ATS + kc*32;
                    ldx2(kh2[q], kbase + SKH);
                    ldx2(kl2[q], kbase + SKL);
                }
                #pragma unroll
                for (int q = 0; q < 4; q++) mma_bf16(s[half*4+q], qh[kc], kh2[q]);
                #pragma unroll
                for (int q = 0; q < 4; q++) mma_bf16(s[half*4+q], qh[kc], kl2[q]);
                #pragma unroll
                for (int q = 0; q < 4; q++) mma_bf16(s[half*4+q], ql[kc], kh2[q]);
            }
        }

        if (k0 + 64 > TT) {
            #pragma unroll
            for (int nt = 0; nt < 8; nt++) {
                int col = k0 + nt*8 + 2*t4;
                if (col   >= TT) { s[nt][0] = -1e30f; s[nt][2] = -1e30f; }
                if (col+1 >= TT) { s[nt][1] = -1e30f; s[nt][3] = -1e30f; }
            }
        }

        // ---- online softmax (base-2) ----
        float mx0 = -1e30f, mx1 = -1e30f;
        #pragma unroll
        for (int nt = 0; nt < 8; nt++) {
            mx0 = fmaxf(mx0, fmaxf(s[nt][0], s[nt][1]));
            mx1 = fmaxf(mx1, fmaxf(s[nt][2], s[nt][3]));
        }
        mx0 = fmaxf(mx0, __shfl_xor_sync(0xffffffffu, mx0, 1));
        mx0 = fmaxf(mx0, __shfl_xor_sync(0xffffffffu, mx0, 2));
        mx1 = fmaxf(mx1, __shfl_xor_sync(0xffffffffu, mx1, 1));
        mx1 = fmaxf(mx1, __shfl_xor_sync(0xffffffffu, mx1, 2));

        float mn0 = fmaxf(m0, mx0), mn1 = fmaxf(m1, mx1);
        float al0 = exp2f(m0 - mn0), al1 = exp2f(m1 - mn1);
        m0 = mn0; m1 = mn1;

        float sum0 = 0.f, sum1 = 0.f;
        #pragma unroll
        for (int nt = 0; nt < 8; nt++) {
            s[nt][0] = exp2f(s[nt][0] - mn0); sum0 += s[nt][0];
            s[nt][1] = exp2f(s[nt][1] - mn0); sum0 += s[nt][1];
            s[nt][2] = exp2f(s[nt][2] - mn1); sum1 += s[nt][2];
            s[nt][3] = exp2f(s[nt][3] - mn1); sum1 += s[nt][3];
        }
        sum0 += __shfl_xor_sync(0xffffffffu, sum0, 1);
        sum0 += __shfl_xor_sync(0xffffffffu, sum0, 2);
        sum1 += __shfl_xor_sync(0xffffffffu, sum1, 1);
        sum1 += __shfl_xor_sync(0xffffffffu, sum1, 2);
        l0 = l0 * al0 + sum0;
        l1 = l1 * al1 + sum1;

        #pragma unroll
        for (int nt = 0; nt < 8; nt++) {
            o[nt][0] *= al0; o[nt][1] *= al0;
            o[nt][2] *= al1; o[nt][3] *= al1;
        }

        // ---- O += P V: P single fp16, V fp16 hi/lo (2 terms) ----
        #pragma unroll
        for (int kc = 0; kc < 4; kc++) {
            uint32_t p[4];
            p[0] = f2h2(s[2*kc][0],   s[2*kc][1]);
            p[1] = f2h2(s[2*kc][2],   s[2*kc][3]);
            p[2] = f2h2(s[2*kc+1][0], s[2*kc+1][1]);
            p[3] = f2h2(s[2*kc+1][2], s[2*kc+1][3]);
            uint32_t vbase = v_rd + (uint32_t)kc*16*ATS;
            #pragma unroll
            for (int half = 0; half < 2; half++) {
                uint32_t vh2[4][2], vl2[4][2];
                #pragma unroll
                for (int q = 0; q < 4; q++) {
                    ldx2t(vh2[q], vbase + SVH + (half*4 + q)*16);
                    ldx2t(vl2[q], vbase + SVL + (half*4 + q)*16);
                }
                #pragma unroll
                for (int q = 0; q < 4; q++) mma_f16(o[half*4+q], p, vh2[q]);
                #pragma unroll
                for (int q = 0; q < 4; q++) mma_f16(o[half*4+q], p, vl2[q]);
            }
        }
    }

    // ---- epilogue: normalize, write single-fp16 ctx ----
    float inv0 = 1.0f / l0, inv1 = 1.0f / l1;
    int r0w = q0 + wid*16 + g;
    int r1w = r0w + 8;
    #pragma unroll
    for (int nt = 0; nt < 8; nt++) {
        int d = nt*8 + 2*t4;
        if (r0w < TT) {
            size_t base = (size_t)(b_ * TT + r0w) * EE + h_ * DH + d;
            *(uint32_t*)(g_ct + base) = f2h2(o[nt][0]*inv0, o[nt][1]*inv0);
        }
        if (r1w < TT) {
            size_t base = (size_t)(b_ * TT + r1w) * EE + h_ * DH + d;
            *(uint32_t*)(g_ct + base) = f2h2(o[nt][2]*inv1, o[nt][3]*inv1);
        }
    }
}

extern "C" void kernel_launch(void* const* d_in, const int* in_sizes, int n_in,
                              void* d_out, int out_size)
{
    const float* X  = (const float*)d_in[0];
    const float* Wq = (const float*)d_in[1];
    const float* bq = (const float*)d_in[2];
    const float* Wk = (const float*)d_in[3];
    const float* Wv = (const float*)d_in[4];
    const float* bv = (const float*)d_in[5];
    const float* Wo = (const float*)d_in[6];
    const float* bo = (const float*)d_in[7];
    float* out = (float*)d_out;

    cudaFuncSetAttribute(qkv_mm, cudaFuncAttributeMaxDynamicSharedMemorySize, GSM);
    cudaFuncSetAttribute(out_mm, cudaFuncAttributeMaxDynamicSharedMemorySize, GSM3);
    cudaFuncSetAttribute(attn_kernel, cudaFuncAttributeMaxDynamicSharedMemorySize, ASMEM);

    {
        size_t tot = (size_t)MRP*EE/4 + 3*(size_t)EE*EE/4;
        prep_all<<<(unsigned)((tot + 255)/256), 256>>>(X, Wq, Wk, Wv);
    }
    prep_wo<<<(EE*EE/2 + 255)/256, 256>>>(Wo);
    zero_pad_qkv<<<(NB*NH*(TP-TT)*DH + 255)/256, 256>>>();
    zero_pad_ctx<<<((MRP-MR)*EE + 255)/256, 256>>>();

    dim3 g1(30, 47);
    qkv_mm<<<g1, 256, GSM>>>(bq, bv);

    dim3 g2(24, NB * NH);
    attn_kernel<<<g2, 128, ASMEM>>>();

    dim3 g3(10, 47);
    out_mm<<<g3, 256, GSM3>>>(bo, out);
}

// round 17
// speedup vs baseline: 1.9753x; 1.0146x over previous
#include <cuda_runtime.h>
#include <cuda_bf16.h>
#include <cuda_fp16.h>
#include <cstdint>

// Problem constants
#define NB 4
#define TT 1500
#define TP 1536
#define EE 1280
#define NH 20
#define DH 64
#define MR (NB*TT)         // 6000
#define MRP 6016
#define QKSCALE 0.125f
#define LOG2E 1.44269504088896f

// GEMM tiling: CTA 128x128, 8 warps (2x4), warp tile 64x32, k-chunk 32
#define BK 32
#define NCH (EE/BK)         // 40
#define RS 80
#define TSZ (128*RS)        // 10240
#define STG (4*TSZ)         // bf16 3-term: Ah,Al,Bh,Bl
#define GSM (2*STG)         // 81920
#define STG3 (3*TSZ)        // fp16 2-term: A,Bh,Bl
#define GSM3 (2*STG3)       // 61440

// Attention smem: 2 stages x 4 tiles (KH,KL,VH,VL), 144B stride
#define ATS 144
#define ATILE (64*ATS)
#define SKH 0
#define SKL ATILE
#define SVH (2*ATILE)
#define SVL (3*ATILE)
#define AST (4*ATILE)
#define ASMEM (2*AST)       // 73728

// ---- pre-split global buffers ----
// bf16 3-term paths: X, Wq, Wk
static __device__ __align__(16) __nv_bfloat16 g_Xh[(size_t)MRP*EE], g_Xl[(size_t)MRP*EE];
static __device__ __align__(16) __nv_bfloat16 g_Wqh[(size_t)EE*EE], g_Wql[(size_t)EE*EE];
static __device__ __align__(16) __nv_bfloat16 g_Wkh[(size_t)EE*EE], g_Wkl[(size_t)EE*EE];
// fp16 paths
static __device__ __align__(16) __half g_Xf[(size_t)MRP*EE];                      // X single (V-proj A)
static __device__ __align__(16) __half g_Wvh[(size_t)EE*EE], g_Wvl[(size_t)EE*EE];
static __device__ __align__(16) __half g_q[(size_t)NB*NH*TP*DH];                  // q single
static __device__ __align__(16) __half g_kh[(size_t)NB*NH*TP*DH], g_kl[(size_t)NB*NH*TP*DH];
static __device__ __align__(16) __half g_vh[(size_t)NB*NH*TP*DH], g_vl[(size_t)NB*NH*TP*DH];
static __device__ __align__(16) __half g_Woh[(size_t)EE*EE], g_Wol[(size_t)EE*EE];
static __device__ __align__(16) __half g_ct[(size_t)MRP*EE];

// ---------------- helpers ----------------
__device__ __forceinline__ uint32_t smem_u32(const void* p){
    uint32_t a;
    asm("{ .reg .u64 t; cvta.to.shared.u64 t, %1; cvt.u32.u64 %0, t; }" : "=r"(a) : "l"(p));
    return a;
}
__device__ __forceinline__ void ldx4(uint32_t* r, uint32_t addr){
    asm volatile("ldmatrix.sync.aligned.m8n8.x4.shared.b16 {%0,%1,%2,%3}, [%4];"
        : "=r"(r[0]), "=r"(r[1]), "=r"(r[2]), "=r"(r[3]) : "r"(addr));
}
__device__ __forceinline__ void ldx2(uint32_t* r, uint32_t addr){
    asm volatile("ldmatrix.sync.aligned.m8n8.x2.shared.b16 {%0,%1}, [%2];"
        : "=r"(r[0]), "=r"(r[1]) : "r"(addr));
}
__device__ __forceinline__ void ldx2t(uint32_t* r, uint32_t addr){
    asm volatile("ldmatrix.sync.aligned.m8n8.x2.trans.shared.b16 {%0,%1}, [%2];"
        : "=r"(r[0]), "=r"(r[1]) : "r"(addr));
}
__device__ __forceinline__ void mma_bf16(float* d, const uint32_t* a, const uint32_t* b){
    asm volatile(
        "mma.sync.aligned.m16n8k16.row.col.f32.bf16.bf16.f32 "
        "{%0,%1,%2,%3}, {%4,%5,%6,%7}, {%8,%9}, {%0,%1,%2,%3};"
        : "+f"(d[0]), "+f"(d[1]), "+f"(d[2]), "+f"(d[3])
        : "r"(a[0]), "r"(a[1]), "r"(a[2]), "r"(a[3]), "r"(b[0]), "r"(b[1]));
}
__device__ __forceinline__ void mma_f16(float* d, const uint32_t* a, const uint32_t* b){
    asm volatile(
        "mma.sync.aligned.m16n8k16.row.col.f32.f16.f16.f32 "
        "{%0,%1,%2,%3}, {%4,%5,%6,%7}, {%8,%9}, {%0,%1,%2,%3};"
        : "+f"(d[0]), "+f"(d[1]), "+f"(d[2]), "+f"(d[3])
        : "r"(a[0]), "r"(a[1]), "r"(a[2]), "r"(a[3]), "r"(b[0]), "r"(b[1]));
}
__device__ __forceinline__ void cpa16(uint32_t s, const void* g){
    asm volatile("cp.async.ca.shared.global [%0], [%1], 16;" :: "r"(s), "l"(g));
}
#define CP_COMMIT() asm volatile("cp.async.commit_group;" ::: "memory")
#define CP_WAIT(n)  asm volatile("cp.async.wait_group %0;" :: "n"(n) : "memory")

__device__ __forceinline__ void split4(float4 f, uint2& H, uint2& L){
    __nv_bfloat16 hx = __float2bfloat16(f.x);
    __nv_bfloat16 hy = __float2bfloat16(f.y);
    __nv_bfloat16 hz = __float2bfloat16(f.z);
    __nv_bfloat16 hw = __float2bfloat16(f.w);
    float lx = f.x - __bfloat162float(hx);
    float ly = f.y - __bfloat162float(hy);
    float lz = f.z - __bfloat162float(hz);
    float lw = f.w - __bfloat162float(hw);
    union { __nv_bfloat162 h2[2]; uint2 u; } A, B;
    A.h2[0] = __halves2bfloat162(hx, hy);
    A.h2[1] = __halves2bfloat162(hz, hw);
    B.h2[0] = __floats2bfloat162_rn(lx, ly);
    B.h2[1] = __floats2bfloat162_rn(lz, lw);
    H = A.u; L = B.u;
}
__device__ __forceinline__ void splitph(float a, float b, uint32_t& H, uint32_t& L){
    __half ha = __float2half_rn(a);
    __half hb = __float2half_rn(b);
    float la = a - __half2float(ha);
    float lb = b - __half2float(hb);
    union { __half2 h; uint32_t u; } X, Y;
    X.h = __halves2half2(ha, hb);
    Y.h = __floats2half2_rn(la, lb);
    H = X.u; L = Y.u;
}
__device__ __forceinline__ uint32_t f2h2(float a, float b){
    union { __half2 h; uint32_t u; } X;
    X.h = __floats2half2_rn(a, b);
    return X.u;
}

// ============================================================================
// Prep: X -> bf16 hi/lo + fp16 single; Wq,Wk -> bf16 hi/lo; Wv,Wo -> fp16 hi/lo.
// ============================================================================
__global__ void prep_all(const float* __restrict__ X,
                         const float* __restrict__ Wq, const float* __restrict__ Wk,
                         const float* __restrict__ Wv, const float* __restrict__ Wo)
{
    const size_t NX = (size_t)MRP*EE/4;
    const size_t NW = (size_t)EE*EE/4;
    size_t i = (size_t)blockIdx.x * blockDim.x + threadIdx.x;
    if (i < NX) {
        size_t j = i;
        int row = (int)(j * 4 / EE);
        float4 f = (row < MR) ? *(const float4*)(X + j*4) : make_float4(0.f,0.f,0.f,0.f);
        uint2 H, L;
        split4(f, H, L);
        *(uint2*)(g_Xh + j*4) = H;
        *(uint2*)(g_Xl + j*4) = L;
        uint2 F;
        F.x = f2h2(f.x, f.y);
        F.y = f2h2(f.z, f.w);
        *(uint2*)(g_Xf + j*4) = F;
        return;
    }
    i -= NX;
    if (i >= 4*NW) return;
    int w = (int)(i / NW);
    size_t j = i - (size_t)w * NW;
    if (w < 2) {
        const float* src = (w == 0) ? Wq : Wk;
        __nv_bfloat16* h = (w == 0) ? g_Wqh : g_Wkh;
        __nv_bfloat16* l = (w == 0) ? g_Wql : g_Wkl;
        float4 f = *(const float4*)(src + j*4);
        uint2 H, L;
        split4(f, H, L);
        *(uint2*)(h + j*4) = H;
        *(uint2*)(l + j*4) = L;
    } else {
        const float* src = (w == 2) ? Wv : Wo;
        __half* h = (w == 2) ? g_Wvh : g_Woh;
        __half* l = (w == 2) ? g_Wvl : g_Wol;
        float4 f = *(const float4*)(src + j*4);
        uint32_t H0, L0, H1, L1;
        splitph(f.x, f.y, H0, L0);
        splitph(f.z, f.w, H1, L1);
        *(uint32_t*)(h + j*4)     = H0;
        *(uint32_t*)(h + j*4 + 2) = H1;
        *(uint32_t*)(l + j*4)     = L0;
        *(uint32_t*)(l + j*4 + 2) = L1;
    }
}

__global__ void zero_pad_qkv()
{
    int idx = blockIdx.x * blockDim.x + threadIdx.x;
    const int tot = NB*NH*(TP-TT)*DH;
    if (idx >= tot) return;
    int d = idx & 63;
    int r = idx >> 6;
    int t = TT + (r % (TP-TT));
    int head = r / (TP-TT);
    size_t off = ((size_t)head * TP + t) * DH + d;
    __half z = __float2half(0.f);
    g_q[off]=z; g_kh[off]=z; g_kl[off]=z; g_vh[off]=z; g_vl[off]=z;
}

__global__ void zero_pad_ctx()
{
    int idx = blockIdx.x * blockDim.x + threadIdx.x;
    const int tot = (MRP-MR)*EE;
    if (idx >= tot) return;
    g_ct[(size_t)MR*EE + idx] = __float2half(0.f);
}

// ============================================================================
// bf16 3-term GEMM mainloop (Q/K projections).
// ============================================================================
__device__ __forceinline__ void mm_loop_bf(
    const __nv_bfloat16* __restrict__ Ah_, const __nv_bfloat16* __restrict__ Al_,
    const __nv_bfloat16* __restrict__ Bh_, const __nv_bfloat16* __restrict__ Bl_,
    int arow0, int brow0, uint32_t smb, float acc[4][4][4])
{
    const int tid  = threadIdx.x;
    const int lane = tid & 31;
    const int wid  = tid >> 5;
    const int warp_m = wid >> 2;
    const int warp_n = wid & 3;

    const int r0 = tid >> 2;
    const int c0 = (tid & 3) * 8;
    const __nv_bfloat16* gAh0 = Ah_ + (size_t)(arow0 + r0)      * EE + c0;
    const __nv_bfloat16* gAh1 = Ah_ + (size_t)(arow0 + r0 + 64) * EE + c0;
    const __nv_bfloat16* gAl0 = Al_ + (size_t)(arow0 + r0)      * EE + c0;
    const __nv_bfloat16* gAl1 = Al_ + (size_t)(arow0 + r0 + 64) * EE + c0;
    const __nv_bfloat16* gBh0 = Bh_ + (size_t)(brow0 + r0)      * EE + c0;
    const __nv_bfloat16* gBh1 = Bh_ + (size_t)(brow0 + r0 + 64) * EE + c0;
    const __nv_bfloat16* gBl0 = Bl_ + (size_t)(brow0 + r0)      * EE + c0;
    const __nv_bfloat16* gBl1 = Bl_ + (size_t)(brow0 + r0 + 64) * EE + c0;
    const uint32_t sd0 = smb + (uint32_t)r0 * RS + c0 * 2;
    const uint32_t sd1 = smb + (uint32_t)(r0 + 64) * RS + c0 * 2;

    const uint32_t a_rd = smb + (uint32_t)(warp_m*64 + (lane & 15)) * RS + (lane >> 4) * 16;
    const uint32_t b_rd = smb + 2*TSZ + (uint32_t)(warp_n*32 + (lane & 7)) * RS + ((lane >> 3) & 1) * 16;

    cpa16(sd0,           gAh0); cpa16(sd1,           gAh1);
    cpa16(sd0 + TSZ,     gAl0); cpa16(sd1 + TSZ,     gAl1);
    cpa16(sd0 + 2*TSZ,   gBh0); cpa16(sd1 + 2*TSZ,   gBh1);
    cpa16(sd0 + 3*TSZ,   gBl0); cpa16(sd1 + 3*TSZ,   gBl1);
    CP_COMMIT();

    #pragma unroll 1
    for (int i = 0; i < NCH; i++) {
        CP_WAIT(0);
        __syncthreads();

        if (i + 1 < NCH) {
            const int ko = (i + 1) * BK;
            const uint32_t so = ((i + 1) & 1) * STG;
            cpa16(sd0 + so,           gAh0 + ko); cpa16(sd1 + so,           gAh1 + ko);
            cpa16(sd0 + so + TSZ,     gAl0 + ko); cpa16(sd1 + so + TSZ,     gAl1 + ko);
            cpa16(sd0 + so + 2*TSZ,   gBh0 + ko); cpa16(sd1 + so + 2*TSZ,   gBh1 + ko);
            cpa16(sd0 + so + 3*TSZ,   gBl0 + ko); cpa16(sd1 + so + 3*TSZ,   gBl1 + ko);
            CP_COMMIT();
        }

        const uint32_t soff = (uint32_t)(i & 1) * STG;
        #pragma unroll
        for (int kk = 0; kk < 2; kk++) {
            const uint32_t koff = soff + kk*32;
            uint32_t bh[4][2], bl[4][2];
            #pragma unroll
            for (int nt = 0; nt < 4; nt++) {
                ldx2(bh[nt], b_rd + koff + nt*8*RS);
                ldx2(bl[nt], b_rd + koff + nt*8*RS + TSZ);
            }
            #pragma unroll
            for (int mt = 0; mt < 4; mt++) {
                uint32_t ah[4], al[4];
                ldx4(ah, a_rd + koff + mt*16*RS);
                ldx4(al, a_rd + koff + mt*16*RS + TSZ);
                #pragma unroll
                for (int nt = 0; nt < 4; nt++) mma_bf16(acc[mt][nt], ah, bh[nt]);
                #pragma unroll
                for (int nt = 0; nt < 4; nt++) mma_bf16(acc[mt][nt], ah, bl[nt]);
                #pragma unroll
                for (int nt = 0; nt < 4; nt++) mma_bf16(acc[mt][nt], al, bh[nt]);
            }
        }
    }
}

// ============================================================================
// fp16 2-term GEMM mainloop (A single, B hi/lo): V-projection + out_mm.
// ============================================================================
__device__ __forceinline__ void mm_loop_h(
    const __half* __restrict__ A_,
    const __half* __restrict__ Bh_, const __half* __restrict__ Bl_,
    int arow0, int brow0, uint32_t smb, float acc[4][4][4])
{
    const int tid  = threadIdx.x;
    const int lane = tid & 31;
    const int wid  = tid >> 5;
    const int warp_m = wid >> 2;
    const int warp_n = wid & 3;

    const int r0 = tid >> 2;
    const int c0 = (tid & 3) * 8;
    const __half* gA0 = A_ + (size_t)(arow0 + r0)      * EE + c0;
    const __half* gA1 = A_ + (size_t)(arow0 + r0 + 64) * EE + c0;
    const __half* gBh0 = Bh_ + (size_t)(brow0 + r0)      * EE + c0;
    const __half* gBh1 = Bh_ + (size_t)(brow0 + r0 + 64) * EE + c0;
    const __half* gBl0 = Bl_ + (size_t)(brow0 + r0)      * EE + c0;
    const __half* gBl1 = Bl_ + (size_t)(brow0 + r0 + 64) * EE + c0;
    const uint32_t sd0 = smb + (uint32_t)r0 * RS + c0 * 2;
    const uint32_t sd1 = smb + (uint32_t)(r0 + 64) * RS + c0 * 2;

    const uint32_t a_rd = smb + (uint32_t)(warp_m*64 + (lane & 15)) * RS + (lane >> 4) * 16;
    const uint32_t b_rd = smb + TSZ + (uint32_t)(warp_n*32 + (lane & 7)) * RS + ((lane >> 3) & 1) * 16;

    cpa16(sd0,           gA0);  cpa16(sd1,           gA1);
    cpa16(sd0 + TSZ,     gBh0); cpa16(sd1 + TSZ,     gBh1);
    cpa16(sd0 + 2*TSZ,   gBl0); cpa16(sd1 + 2*TSZ,   gBl1);
    CP_COMMIT();

    #pragma unroll 1
    for (int i = 0; i < NCH; i++) {
        CP_WAIT(0);
        __syncthreads();

        if (i + 1 < NCH) {
            const int ko = (i + 1) * BK;
            const uint32_t so = ((i + 1) & 1) * STG3;
            cpa16(sd0 + so,           gA0 + ko);  cpa16(sd1 + so,           gA1 + ko);
            cpa16(sd0 + so + TSZ,     gBh0 + ko); cpa16(sd1 + so + TSZ,     gBh1 + ko);
            cpa16(sd0 + so + 2*TSZ,   gBl0 + ko); cpa16(sd1 + so + 2*TSZ,   gBl1 + ko);
            CP_COMMIT();
        }

        const uint32_t soff = (uint32_t)(i & 1) * STG3;
        #pragma unroll
        for (int kk = 0; kk < 2; kk++) {
            const uint32_t koff = soff + kk*32;
            uint32_t bh[4][2], bl[4][2];
            #pragma unroll
            for (int nt = 0; nt < 4; nt++) {
                ldx2(bh[nt], b_rd + koff + nt*8*RS);
                ldx2(bl[nt], b_rd + koff + nt*8*RS + TSZ);
            }
            #pragma unroll
            for (int mt = 0; mt < 4; mt++) {
                uint32_t ah[4];
                ldx4(ah, a_rd + koff + mt*16*RS);
                #pragma unroll
                for (int nt = 0; nt < 4; nt++) mma_f16(acc[mt][nt], ah, bh[nt]);
                #pragma unroll
                for (int nt = 0; nt < 4; nt++) mma_f16(acc[mt][nt], ah, bl[nt]);
            }
        }
    }
}

// ============================================================================
// QKV GEMM: grid (30, 47). Q -> single fp16 (scaled); K,V -> fp16 hi/lo.
// Q/K via bf16 3-term; V via fp16 2-term.
// ============================================================================
__global__ __launch_bounds__(256, 2) void qkv_mm(
    const float* __restrict__ bq, const float* __restrict__ bv)
{
    extern __shared__ char sm[];
    uint32_t smb = smem_u32(sm);
    const int tid = threadIdx.x;
    const int lane = tid & 31;
    const int wid = tid >> 5;
    const int warp_m = wid >> 2, warp_n = wid & 3;

    const int which = blockIdx.x / 10;
    const int wcol0 = (blockIdx.x - which*10) * 128;
    const int row0  = blockIdx.y * 128;

    float acc[4][4][4];
    #pragma unroll
    for (int mt = 0; mt < 4; mt++)
        #pragma unroll
        for (int nt = 0; nt < 4; nt++)
            #pragma unroll
            for (int j = 0; j < 4; j++) acc[mt][nt][j] = 0.f;

    if (which == 0)      mm_loop_bf(g_Xh, g_Xl, g_Wqh, g_Wql, row0, wcol0, smb, acc);
    else if (which == 1) mm_loop_bf(g_Xh, g_Xl, g_Wkh, g_Wkl, row0, wcol0, smb, acc);
    else                 mm_loop_h (g_Xf, g_Wvh, g_Wvl,       row0, wcol0, smb, acc);

    const float* bias = (which == 0) ? bq : (which == 2 ? bv : nullptr);
    const float scl = (which == 0) ? QKSCALE*LOG2E : 1.0f;

    const int g = lane >> 2, t4 = lane & 3;
    #pragma unroll
    for (int mt = 0; mt < 4; mt++) {
        int r0w = row0 + warp_m*64 + mt*16 + g;
        int r1w = r0w + 8;
        int b0 = r0w / TT, t0 = r0w - b0*TT;
        int b1 = r1w / TT, t1 = r1w - b1*TT;
        bool v0 = r0w < MR, v1 = r1w < MR;
        #pragma unroll
        for (int nt = 0; nt < 4; nt++) {
            int col = wcol0 + warp_n*32 + nt*8 + 2*t4;
            float2 bb = bias ? *(const float2*)(bias + col) : make_float2(0.f, 0.f);
            int h = col >> 6, d = col & 63;
            if (v0) {
                size_t base = ((size_t)(b0*NH + h) * TP + t0) * DH + d;
                float x = (acc[mt][nt][0] + bb.x)*scl, y = (acc[mt][nt][1] + bb.y)*scl;
                if (which == 0) {
                    *(uint32_t*)(g_q + base) = f2h2(x, y);
                } else {
                    uint32_t H, L;
                    splitph(x, y, H, L);
                    __half* dh = (which == 1) ? g_kh : g_vh;
                    __half* dl = (which == 1) ? g_kl : g_vl;
                    *(uint32_t*)(dh + base) = H;
                    *(uint32_t*)(dl + base) = L;
                }
            }
            if (v1) {
                size_t base = ((size_t)(b1*NH + h) * TP + t1) * DH + d;
                float x = (acc[mt][nt][2] + bb.x)*scl, y = (acc[mt][nt][3] + bb.y)*scl;
                if (which == 0) {
                    *(uint32_t*)(g_q + base) = f2h2(x, y);
                } else {
                    uint32_t H, L;
                    splitph(x, y, H, L);
                    __half* dh = (which == 1) ? g_kh : g_vh;
                    __half* dl = (which == 1) ? g_kl : g_vl;
                    *(uint32_t*)(dh + base) = H;
                    *(uint32_t*)(dl + base) = L;
                }
            }
        }
    }
}

// ============================================================================
// Output projection: out = ctx @ Wo^T + bo (fp16 2-term). grid (10, 47).
// ============================================================================
__global__ __launch_bounds__(256, 2) void out_mm(
    const float* __restrict__ bo, float* __restrict__ out)
{
    extern __shared__ char sm[];
    uint32_t smb = smem_u32(sm);
    const int tid = threadIdx.x;
    const int lane = tid & 31;
    const int wid = tid >> 5;
    const int warp_m = wid >> 2, warp_n = wid & 3;
    const int col0 = blockIdx.x * 128;
    const int row0 = blockIdx.y * 128;

    float acc[4][4][4];
    #pragma unroll
    for (int mt = 0; mt < 4; mt++)
        #pragma unroll
        for (int nt = 0; nt < 4; nt++)
            #pragma unroll
            for (int j = 0; j < 4; j++) acc[mt][nt][j] = 0.f;

    mm_loop_h(g_ct, g_Woh, g_Wol, row0, col0, smb, acc);

    const int g = lane >> 2, t4 = lane & 3;
    #pragma unroll
    for (int mt = 0; mt < 4; mt++) {
        int r0w = row0 + warp_m*64 + mt*16 + g;
        int r1w = r0w + 8;
        #pragma unroll
        for (int nt = 0; nt < 4; nt++) {
            int col = col0 + warp_n*32 + nt*8 + 2*t4;
            float2 bb = *(const float2*)(bo + col);
            if (r0w < MR) {
                float2 v = make_float2(acc[mt][nt][0] + bb.x, acc[mt][nt][1] + bb.y);
                *(float2*)(out + (size_t)r0w*EE + col) = v;
            }
            if (r1w < MR) {
                float2 v = make_float2(acc[mt][nt][2] + bb.x, acc[mt][nt][3] + bb.y);
                *(float2*)(out + (size_t)r1w*EE + col) = v;
            }
        }
    }
}

// ============================================================================
// Flash attention: S = q(single fp16) x K(fp16 hi/lo) = 2 MMAs;
// PV = P(single fp16) x V(fp16 hi/lo) = 2 MMAs. Double-buffered K/V, exp2.
// Grid (24, 80), 128 threads. Writes ctx single fp16.
// ============================================================================
__global__ __launch_bounds__(128) void attn_kernel()
{
    extern __shared__ char sm[];
    uint32_t smb = smem_u32(sm);

    const int tid = threadIdx.x;
    const int lane = tid & 31;
    const int wid = tid >> 5;
    const int g  = lane >> 2;
    const int t4 = lane & 3;

    const int bhidx = blockIdx.y;
    const int b_ = bhidx / NH;
    const int h_ = bhidx - b_ * NH;
    const size_t hb = (size_t)bhidx * TP * DH;
    const int q0 = blockIdx.x * 64;

    // ---- Q staging (single fp16, 8KB) into stage-0 SKH area ----
    #pragma unroll
    for (int j = 0; j < 4; j++) {
        int seg = tid + 128*j;
        int row = seg >> 3;
        int o8  = (seg & 7) * 8;
        size_t go = hb + (size_t)(q0 + row) * DH + o8;
        uint32_t so = (uint32_t)row * ATS + o8*2;
        cpa16(smb + SKH + so, g_q + go);
    }
    CP_COMMIT(); CP_WAIT(0);
    __syncthreads();

    uint32_t qf[4][4];
    {
        uint32_t qa = smb + (uint32_t)(wid*16 + (lane & 15)) * ATS + (lane >> 4) * 16;
        #pragma unroll
        for (int kc = 0; kc < 4; kc++) ldx4(qf[kc], qa + SKH + kc*32);
    }
    __syncthreads();

    float m0 = -1e30f, m1 = -1e30f, l0 = 0.f, l1 = 0.f;
    float o[8][4];
    #pragma unroll
    for (int nt = 0; nt < 8; nt++)
        #pragma unroll
        for (int j = 0; j < 4; j++) o[nt][j] = 0.f;

    // ---- issue K/V tile 0 into stage 0 ----
    #pragma unroll
    for (int j = 0; j < 4; j++) {
        int seg = tid + 128*j;
        int row = seg >> 3;
        int o8  = (seg & 7) * 8;
        size_t go = hb + (size_t)row * DH + o8;
        uint32_t so = (uint32_t)row * ATS + o8*2;
        cpa16(smb + SKH + so, g_kh + go);
        cpa16(smb + SKL + so, g_kl + go);
        cpa16(smb + SVH + so, g_vh + go);
        cpa16(smb + SVL + so, g_vl + go);
    }
    CP_COMMIT();

    #pragma unroll 1
    for (int kt = 0; kt < 24; kt++) {
        const int k0 = kt * 64;
        CP_WAIT(0);
        __syncthreads();

        if (kt + 1 < 24) {
            const int k1 = (kt + 1) * 64;
            const uint32_t stN = smb + ((kt + 1) & 1) * AST;
            #pragma unroll
            for (int j = 0; j < 4; j++) {
                int seg = tid + 128*j;
                int row = seg >> 3;
                int o8  = (seg & 7) * 8;
                size_t go = hb + (size_t)(k1 + row) * DH + o8;
                uint32_t so = (uint32_t)row * ATS + o8*2;
                cpa16(stN + SKH + so, g_kh + go);
                cpa16(stN + SKL + so, g_kl + go);
                cpa16(stN + SVH + so, g_vh + go);
                cpa16(stN + SVL + so, g_vl + go);
            }
            CP_COMMIT();
        }

        const uint32_t st = smb + (kt & 1) * AST;
        const uint32_t k_rd = st + (uint32_t)(lane & 7) * ATS + ((lane >> 3) & 1) * 16;
        const uint32_t v_rd = st + (uint32_t)(lane & 15) * ATS;

        // ---- S = q K^T (2 terms), term-major nt-quads ----
        float s[8][4];
        #pragma unroll
        for (int nt = 0; nt < 8; nt++)
            #pragma unroll
            for (int j = 0; j < 4; j++) s[nt][j] = 0.f;

        #pragma unroll
        for (int kc = 0; kc < 4; kc++) {
            #pragma unroll
            for (int half = 0; half < 2; half++) {
                uint32_t kh2[4][2], kl2[4][2];
                #pragma unroll
                for (int q = 0; q < 4; q++) {
                    uint32_t kbase = k_rd + (uint32_t)(half*4 + q)*8*ATS + kc*32;
                    ldx2(kh2[q], kbase + SKH);
                    ldx2(kl2[q], kbase + SKL);
                }
                #pragma unroll
                for (int q = 0; q < 4; q++) mma_f16(s[half*4+q], qf[kc], kh2[q]);
                #pragma unroll
                for (int q = 0; q < 4; q++) mma_f16(s[half*4+q], qf[kc], kl2[q]);
            }
        }

        if (k0 + 64 > TT) {
            #pragma unroll
            for (int nt = 0; nt < 8; nt++) {
                int col = k0 + nt*8 + 2*t4;
                if (col   >= TT) { s[nt][0] = -1e30f; s[nt][2] = -1e30f; }
                if (col+1 >= TT) { s[nt][1] = -1e30f; s[nt][3] = -1e30f; }
            }
        }

        // ---- online softmax (base-2) ----
        float mx0 = -1e30f, mx1 = -1e30f;
        #pragma unroll
        for (int nt = 0; nt < 8; nt++) {
            mx0 = fmaxf(mx0, fmaxf(s[nt][0], s[nt][1]));
            mx1 = fmaxf(mx1, fmaxf(s[nt][2], s[nt][3]));
        }
        mx0 = fmaxf(mx0, __shfl_xor_sync(0xffffffffu, mx0, 1));
        mx0 = fmaxf(mx0, __shfl_xor_sync(0xffffffffu, mx0, 2));
        mx1 = fmaxf(mx1, __shfl_xor_sync(0xffffffffu, mx1, 1));
        mx1 = fmaxf(mx1, __shfl_xor_sync(0xffffffffu, mx1, 2));

        float mn0 = fmaxf(m0, mx0), mn1 = fmaxf(m1, mx1);
        float al0 = exp2f(m0 - mn0), al1 = exp2f(m1 - mn1);
        m0 = mn0; m1 = mn1;

        float sum0 = 0.f, sum1 = 0.f;
        #pragma unroll
        for (int nt = 0; nt < 8; nt++) {
            s[nt][0] = exp2f(s[nt][0] - mn0); sum0 += s[nt][0];
            s[nt][1] = exp2f(s[nt][1] - mn0); sum0 += s[nt][1];
            s[nt][2] = exp2f(s[nt][2] - mn1); sum1 += s[nt][2];
            s[nt][3] = exp2f(s[nt][3] - mn1); sum1 += s[nt][3];
        }
        sum0 += __shfl_xor_sync(0xffffffffu, sum0, 1);
        sum0 += __shfl_xor_sync(0xffffffffu, sum0, 2);
        sum1 += __shfl_xor_sync(0xffffffffu, sum1, 1);
        sum1 += __shfl_xor_sync(0xffffffffu, sum1, 2);
        l0 = l0 * al0 + sum0;
        l1 = l1 * al1 + sum1;

        #pragma unroll
        for (int nt = 0; nt < 8; nt++) {
            o[nt][0] *= al0; o[nt][1] *= al0;
            o[nt][2] *= al1; o[nt][3] *= al1;
        }

        // ---- O += P V (P single fp16, V hi/lo) ----
        #pragma unroll
        for (int kc = 0; kc < 4; kc++) {
            uint32_t p[4];
            p[0] = f2h2(s[2*kc][0],   s[2*kc][1]);
            p[1] = f2h2(s[2*kc][2],   s[2*kc][3]);
            p[2] = f2h2(s[2*kc+1][0], s[2*kc+1][1]);
            p[3] = f2h2(s[2*kc+1][2], s[2*kc+1][3]);
            uint32_t vbase = v_rd + (uint32_t)kc*16*ATS;
            #pragma unroll
            for (int half = 0; half < 2; half++) {
                uint32_t vh2[4][2], vl2[4][2];
                #pragma unroll
                for (int q = 0; q < 4; q++) {
                    ldx2t(vh2[q], vbase + SVH + (half*4 + q)*16);
                    ldx2t(vl2[q], vbase + SVL + (half*4 + q)*16);
                }
                #pragma unroll
                for (int q = 0; q < 4; q++) mma_f16(o[half*4+q], p, vh2[q]);
                #pragma unroll
                for (int q = 0; q < 4; q++) mma_f16(o[half*4+q], p, vl2[q]);
            }
        }
    }

    // ---- epilogue: normalize, write single-fp16 ctx ----
    float inv0 = 1.0f / l0, inv1 = 1.0f / l1;
    int r0w = q0 + wid*16 + g;
    int r1w = r0w + 8;
    #pragma unroll
    for (int nt = 0; nt < 8; nt++) {
        int d = nt*8 + 2*t4;
        if (r0w < TT) {
            size_t base = (size_t)(b_ * TT + r0w) * EE + h_ * DH + d;
            *(uint32_t*)(g_ct + base) = f2h2(o[nt][0]*inv0, o[nt][1]*inv0);
        }
        if (r1w < TT) {
            size_t base = (size_t)(b_ * TT + r1w) * EE + h_ * DH + d;
            *(uint32_t*)(g_ct + base) = f2h2(o[nt][2]*inv1, o[nt][3]*inv1);
        }
    }
}

extern "C" void kernel_launch(void* const* d_in, const int* in_sizes, int n_in,
                              void* d_out, int out_size)
{
    const float* X  = (const float*)d_in[0];
    const float* Wq = (const float*)d_in[1];
    const float* bq = (const float*)d_in[2];
    const float* Wk = (const float*)d_in[3];
    const float* Wv = (const float*)d_in[4];
    const float* bv = (const float*)d_in[5];
    const float* Wo = (const float*)d_in[6];
    const float* bo = (const float*)d_in[7];
    float* out = (float*)d_out;

    cudaFuncSetAttribute(qkv_mm, cudaFuncAttributeMaxDynamicSharedMemorySize, GSM);
    cudaFuncSetAttribute(out_mm, cudaFuncAttributeMaxDynamicSharedMemorySize, GSM3);
    cudaFuncSetAttribute(attn_kernel, cudaFuncAttributeMaxDynamicSharedMemorySize, ASMEM);

    {
        size_t tot = (size_t)MRP*EE/4 + 4*(size_t)EE*EE/4;
        prep_all<<<(unsigned)((tot + 255)/256), 256>>>(X, Wq, Wk, Wv, Wo);
    }
    zero_pad_qkv<<<(NB*NH*(TP-TT)*DH + 255)/256, 256>>>();
    zero_pad_ctx<<<((MRP-MR)*EE + 255)/256, 256>>>();

    dim3 g1(30, 47);
    qkv_mm<<<g1, 256, GSM>>>(bq, bv);

    dim3 g2(24, NB * NH);
    attn_kernel<<<g2, 128, ASMEM>>>();

    dim3 g3(10, 47);
    out_mm<<<g3, 256, GSM3>>>(bo, out);
}